// round 1
// baseline (speedup 1.0000x reference)
#include <cuda_runtime.h>
#include <cuda_bf16.h>
#include <cstddef>

// ---------------------------------------------------------------------------
// mulGCN: two-branch GCN forward.
// Per branch:
//   hW  = h @ W                                    (GEMM, MODE 0)
//   agg[dst] += hW[src]   over 800k edges          (scatter kernel, atomics)
//   h1  = relu(agg + b) + relu(h @ Wr + br)        (GEMM, MODE 1, fused epilogue)
//   T[g] = segment_sum over nodes of relu(h1 @ Ri + rbi)   (GEMM, MODE 2, atomic epilogue)
//   gacc += T @ Ro + counts*rbo                    (small readout GEMM)
// Final: out = gacc @ Wp + bp
// Key restructure: segment_sum(t@Ro+rbo) == segment_sum(t)@Ro + count*rbo,
// collapsing the [50000,256]x[256,200] readout GEMM to [512,256]x[256,200].
// ---------------------------------------------------------------------------

#define N_NODES   50000
#define N_EDGES   800000
#define DFEAT     256
#define G_FEAT    200
#define N_GRAPHS  512

// Scratch (static device globals: allocation-free per harness rules)
__device__ float g_hW  [(size_t)N_NODES * DFEAT];
__device__ float g_agg [(size_t)N_NODES * DFEAT];
__device__ float g_h1  [(size_t)N_NODES * DFEAT];
__device__ float g_T   [N_GRAPHS * DFEAT];
__device__ float g_gacc[N_GRAPHS * G_FEAT];
__device__ int   g_counts[N_GRAPHS];

__device__ __forceinline__ float frelu(float x) { return x > 0.f ? x : 0.f; }

// ---------------------------------------------------------------------------
// Tiled fp32 GEMM: C[M,N] = epilogue(A[M,256] @ W[256,N])
// BM=128, BN=64, BK=16; 256 threads; 8x4 outputs per thread.
// MODE 0: C = acc                              (plain)
// MODE 1: C = relu(acc + bias) + relu(agg + bagg)
// MODE 2: v = relu(acc + bias); atomicAdd(T[gid[row]][col], v)  (per-thread
//         run-length merge over its 8 consecutive rows since gid is sorted)
// ---------------------------------------------------------------------------
template<int MODE>
__global__ __launch_bounds__(256)
void gemm_kernel(const float* __restrict__ A,
                 const float* __restrict__ W,
                 const float* __restrict__ bias,
                 const float* __restrict__ agg,
                 const float* __restrict__ bagg,
                 const int*   __restrict__ gid,
                 float* __restrict__ C,
                 int M, int N)
{
    constexpr int BM = 128, BN = 64, BK = 16;
    __shared__ float As[BK][BM + 4];
    __shared__ float Bs[BK][BN];

    const int tid = threadIdx.x;
    const int tx  = tid & 15;          // 0..15 -> 4 cols each
    const int ty  = tid >> 4;          // 0..15 -> 8 rows each
    const int rowBase = blockIdx.x * BM;
    const int colBase = blockIdx.y * BN;

    float acc[8][4];
    #pragma unroll
    for (int i = 0; i < 8; i++)
        #pragma unroll
        for (int j = 0; j < 4; j++) acc[i][j] = 0.f;

    for (int kt = 0; kt < 256; kt += BK) {
        // Load A tile (128x16), transposed into As[k][row]
        #pragma unroll
        for (int i = 0; i < 2; i++) {
            int idx  = tid + i * 256;      // 0..511
            int arow = idx >> 2;
            int ac4  = (idx & 3) * 4;
            float4 v = make_float4(0.f, 0.f, 0.f, 0.f);
            int grow = rowBase + arow;
            if (grow < M)
                v = *reinterpret_cast<const float4*>(A + (size_t)grow * 256 + kt + ac4);
            As[ac4 + 0][arow] = v.x;
            As[ac4 + 1][arow] = v.y;
            As[ac4 + 2][arow] = v.z;
            As[ac4 + 3][arow] = v.w;
        }
        // Load B tile (16x64), natural layout
        {
            int brow = tid >> 4;           // 0..15
            int bc4  = (tid & 15) * 4;     // 0..60
            float4 v = *reinterpret_cast<const float4*>(
                W + (size_t)(kt + brow) * N + colBase + bc4);
            *reinterpret_cast<float4*>(&Bs[brow][bc4]) = v;
        }
        __syncthreads();

        #pragma unroll
        for (int k = 0; k < BK; k++) {
            float a[8], b[4];
            *reinterpret_cast<float4*>(&a[0]) = *reinterpret_cast<float4*>(&As[k][ty * 8]);
            *reinterpret_cast<float4*>(&a[4]) = *reinterpret_cast<float4*>(&As[k][ty * 8 + 4]);
            *reinterpret_cast<float4*>(&b[0]) = *reinterpret_cast<float4*>(&Bs[k][tx * 4]);
            #pragma unroll
            for (int i = 0; i < 8; i++)
                #pragma unroll
                for (int j = 0; j < 4; j++)
                    acc[i][j] += a[i] * b[j];
        }
        __syncthreads();
    }

    const int col0 = colBase + tx * 4;

    if (MODE == 0) {
        #pragma unroll
        for (int i = 0; i < 8; i++) {
            int row = rowBase + ty * 8 + i;
            if (row < M) {
                float4 v = make_float4(acc[i][0], acc[i][1], acc[i][2], acc[i][3]);
                *reinterpret_cast<float4*>(C + (size_t)row * N + col0) = v;
            }
        }
    } else if (MODE == 1) {
        float4 bs  = *reinterpret_cast<const float4*>(bias + col0);
        float4 bas = *reinterpret_cast<const float4*>(bagg + col0);
        #pragma unroll
        for (int i = 0; i < 8; i++) {
            int row = rowBase + ty * 8 + i;
            if (row < M) {
                float4 ag = *reinterpret_cast<const float4*>(agg + (size_t)row * N + col0);
                float4 v;
                v.x = frelu(acc[i][0] + bs.x) + frelu(ag.x + bas.x);
                v.y = frelu(acc[i][1] + bs.y) + frelu(ag.y + bas.y);
                v.z = frelu(acc[i][2] + bs.z) + frelu(ag.z + bas.z);
                v.w = frelu(acc[i][3] + bs.w) + frelu(ag.w + bas.w);
                *reinterpret_cast<float4*>(C + (size_t)row * N + col0) = v;
            }
        }
    } else { // MODE 2: readout segment-sum into T
        float4 bs = *reinterpret_cast<const float4*>(bias + col0);
        int   lastg = -1;
        float r0 = 0.f, r1 = 0.f, r2 = 0.f, r3 = 0.f;
        #pragma unroll
        for (int i = 0; i < 8; i++) {
            int row = rowBase + ty * 8 + i;
            if (row < M) {
                int g = gid[row];
                float v0 = frelu(acc[i][0] + bs.x);
                float v1 = frelu(acc[i][1] + bs.y);
                float v2 = frelu(acc[i][2] + bs.z);
                float v3 = frelu(acc[i][3] + bs.w);
                if (g != lastg) {
                    if (lastg >= 0) {
                        float* t = C + (size_t)lastg * 256 + col0;
                        atomicAdd(t + 0, r0); atomicAdd(t + 1, r1);
                        atomicAdd(t + 2, r2); atomicAdd(t + 3, r3);
                    }
                    lastg = g; r0 = v0; r1 = v1; r2 = v2; r3 = v3;
                } else {
                    r0 += v0; r1 += v1; r2 += v2; r3 += v3;
                }
            }
        }
        if (lastg >= 0) {
            float* t = C + (size_t)lastg * 256 + col0;
            atomicAdd(t + 0, r0); atomicAdd(t + 1, r1);
            atomicAdd(t + 2, r2); atomicAdd(t + 3, r3);
        }
    }
}

// ---------------------------------------------------------------------------
// Edge scatter: one warp per edge; agg[dst] += hW[src] (256 floats)
// ---------------------------------------------------------------------------
__global__ __launch_bounds__(256)
void scatter_kernel(const float* __restrict__ hW,
                    const int* __restrict__ src,
                    const int* __restrict__ dst,
                    float* __restrict__ agg, int nEdges)
{
    int warp = (blockIdx.x * blockDim.x + threadIdx.x) >> 5;
    int lane = threadIdx.x & 31;
    if (warp >= nEdges) return;
    int s = src[warp];
    int d = dst[warp];
    const float4* srow = reinterpret_cast<const float4*>(hW + (size_t)s * DFEAT);
    float* drow = agg + (size_t)d * DFEAT;
    #pragma unroll
    for (int j = 0; j < 2; j++) {
        float4 v = srow[lane + j * 32];
        int c = (lane + j * 32) * 4;
        atomicAdd(drow + c + 0, v.x);
        atomicAdd(drow + c + 1, v.y);
        atomicAdd(drow + c + 2, v.z);
        atomicAdd(drow + c + 3, v.w);
    }
}

__global__ void counts_kernel(const int* __restrict__ gid, int* __restrict__ counts, int M)
{
    int i = blockIdx.x * blockDim.x + threadIdx.x;
    if (i < M) atomicAdd(&counts[gid[i]], 1);
}

// ---------------------------------------------------------------------------
// Readout: gacc[g,:] += T[g,:] @ Ro[256,200] + counts[g]*rbo
// One block per graph.
// ---------------------------------------------------------------------------
__global__ __launch_bounds__(256)
void readout_kernel(const float* __restrict__ T,
                    const float* __restrict__ Ro,
                    const float* __restrict__ rbo,
                    const int* __restrict__ counts,
                    float* __restrict__ gacc)
{
    __shared__ float ts[DFEAT];
    int g = blockIdx.x;
    ts[threadIdx.x] = T[(size_t)g * DFEAT + threadIdx.x];
    __syncthreads();
    float cnt = (float)counts[g];
    for (int j = threadIdx.x; j < G_FEAT; j += blockDim.x) {
        float s = 0.f;
        #pragma unroll 8
        for (int k = 0; k < DFEAT; k++)
            s += ts[k] * Ro[(size_t)k * G_FEAT + j];
        gacc[(size_t)g * G_FEAT + j] += s + cnt * rbo[j];
    }
}

// ---------------------------------------------------------------------------
// Final: out[g] = dot(gacc[g,:], Wp[:,0]) + bp[0]
// ---------------------------------------------------------------------------
__global__ __launch_bounds__(256)
void final_kernel(const float* __restrict__ gacc,
                  const float* __restrict__ Wp,
                  const float* __restrict__ bp,
                  float* __restrict__ out)
{
    __shared__ float red[256];
    int g = blockIdx.x;
    float s = 0.f;
    for (int j = threadIdx.x; j < G_FEAT; j += blockDim.x)
        s += gacc[(size_t)g * G_FEAT + j] * Wp[j];
    red[threadIdx.x] = s;
    __syncthreads();
    #pragma unroll
    for (int st = 128; st > 0; st >>= 1) {
        if (threadIdx.x < st) red[threadIdx.x] += red[threadIdx.x + st];
        __syncthreads();
    }
    if (threadIdx.x == 0) out[g] = red[0] + bp[0];
}

// ---------------------------------------------------------------------------
extern "C" void kernel_launch(void* const* d_in, const int* in_sizes, int n_in,
                              void* d_out, int out_size)
{
    // metadata order (setup_inputs dict order):
    // 0 nf1, 1 ef1, 2 nf2, 3 ef2, 4 src1, 5 dst1, 6 gid1, 7 src2, 8 dst2, 9 gid2,
    // 10 W1, 11 b1, 12 Wr1, 13 br1, 14 W2, 15 b2, 16 Wr2, 17 br2,
    // 18 Ri1, 19 rbi1, 20 Ro1, 21 rbo1, 22 Ri2, 23 rbi2, 24 Ro2, 25 rbo2, 26 Wp, 27 bp
    const float* nf [2] = { (const float*)d_in[0],  (const float*)d_in[2]  };
    const int*   src[2] = { (const int*)  d_in[4],  (const int*)  d_in[7]  };
    const int*   dst[2] = { (const int*)  d_in[5],  (const int*)  d_in[8]  };
    const int*   gid[2] = { (const int*)  d_in[6],  (const int*)  d_in[9]  };
    const float* W  [2] = { (const float*)d_in[10], (const float*)d_in[14] };
    const float* b  [2] = { (const float*)d_in[11], (const float*)d_in[15] };
    const float* Wr [2] = { (const float*)d_in[12], (const float*)d_in[16] };
    const float* br [2] = { (const float*)d_in[13], (const float*)d_in[17] };
    const float* Ri [2] = { (const float*)d_in[18], (const float*)d_in[22] };
    const float* rbi[2] = { (const float*)d_in[19], (const float*)d_in[23] };
    const float* Ro [2] = { (const float*)d_in[20], (const float*)d_in[24] };
    const float* rbo[2] = { (const float*)d_in[21], (const float*)d_in[25] };
    const float* Wp  = (const float*)d_in[26];
    const float* bp  = (const float*)d_in[27];

    float *hW, *agg, *h1, *T, *gacc;
    int *counts;
    cudaGetSymbolAddress((void**)&hW,     g_hW);
    cudaGetSymbolAddress((void**)&agg,    g_agg);
    cudaGetSymbolAddress((void**)&h1,     g_h1);
    cudaGetSymbolAddress((void**)&T,      g_T);
    cudaGetSymbolAddress((void**)&gacc,   g_gacc);
    cudaGetSymbolAddress((void**)&counts, g_counts);

    cudaMemsetAsync(gacc, 0, (size_t)N_GRAPHS * G_FEAT * sizeof(float));

    dim3 gemm_grid((N_NODES + 127) / 128, DFEAT / 64);  // 391 x 4
    int scat_blocks = (N_EDGES * 32 + 255) / 256;       // one warp per edge

    for (int i = 0; i < 2; i++) {
        cudaMemsetAsync(agg,    0, (size_t)N_NODES * DFEAT * sizeof(float));
        cudaMemsetAsync(T,      0, (size_t)N_GRAPHS * DFEAT * sizeof(float));
        cudaMemsetAsync(counts, 0, N_GRAPHS * sizeof(int));

        // hW = h @ W
        gemm_kernel<0><<<gemm_grid, 256>>>(nf[i], W[i], nullptr, nullptr, nullptr,
                                           nullptr, hW, N_NODES, DFEAT);
        // agg[dst] += hW[src]
        scatter_kernel<<<scat_blocks, 256>>>(hW, src[i], dst[i], agg, N_EDGES);
        // h1 = relu(agg + b) + relu(h @ Wr + br)
        gemm_kernel<1><<<gemm_grid, 256>>>(nf[i], Wr[i], br[i], agg, b[i],
                                           nullptr, h1, N_NODES, DFEAT);
        // counts per graph
        counts_kernel<<<(N_NODES + 255) / 256, 256>>>(gid[i], counts, N_NODES);
        // T[g] = sum over nodes of relu(h1 @ Ri + rbi)
        gemm_kernel<2><<<gemm_grid, 256>>>(h1, Ri[i], rbi[i], nullptr, nullptr,
                                           gid[i], T, N_NODES, DFEAT);
        // gacc += T @ Ro + counts*rbo
        readout_kernel<<<N_GRAPHS, 256>>>(T, Ro[i], rbo[i], counts, gacc);
    }

    final_kernel<<<N_GRAPHS, 256>>>(gacc, Wp, bp, (float*)d_out);
}

// round 2
// speedup vs baseline: 1.5106x; 1.5106x over previous
#include <cuda_runtime.h>
#include <cuda_bf16.h>
#include <cstddef>

// ---------------------------------------------------------------------------
// mulGCN: two-branch GCN forward.
// Per branch:
//   hW  = h @ W                                    (GEMM MODE 0)
//   CSR build by dst (histogram -> scan -> fill)
//   agg[n] = sum_{e: dst=n} hW[src[e]]             (warp-per-node gather, no atomics)
//   h1  = relu(agg + b) + relu(h @ Wr + br)        (GEMM MODE 1, fused epilogue)
//   T[g] = segsum relu(h1 @ Ri + rbi)              (GEMM MODE 2, atomic epilogue)
//   gacc += T @ Ro + counts*rbo
// Final: out = gacc @ Wp + bp
// ---------------------------------------------------------------------------

#define N_NODES   50000
#define N_EDGES   800000
#define DFEAT     256
#define G_FEAT    200
#define N_GRAPHS  512

__device__ float g_hW  [(size_t)N_NODES * DFEAT];
__device__ float g_agg [(size_t)N_NODES * DFEAT];
__device__ float g_h1  [(size_t)N_NODES * DFEAT];
__device__ float g_T   [N_GRAPHS * DFEAT];
__device__ float g_gacc[N_GRAPHS * G_FEAT];
__device__ int   g_counts[N_GRAPHS];
__device__ int   g_deg     [N_NODES];
__device__ int   g_rowstart[N_NODES + 1];
__device__ int   g_cursor  [N_NODES];
__device__ int   g_csr_src [N_EDGES];

__device__ __forceinline__ float frelu(float x) { return x > 0.f ? x : 0.f; }

// ---------------------------------------------------------------------------
// Tiled fp32 GEMM: C[M,256] = epilogue(A[M,256] @ W[256,256])
// BM=128, BN=128, BK=16; 256 threads; 8x8 micro-tile.
// Thread covers rows rowBase+ty*8..+7, cols {colBase+tx*4..+3, colBase+64+tx*4..+3}
// ---------------------------------------------------------------------------
template<int MODE>
__global__ __launch_bounds__(256, 2)
void gemm_kernel(const float* __restrict__ A,
                 const float* __restrict__ W,
                 const float* __restrict__ bias,
                 const float* __restrict__ agg,
                 const float* __restrict__ bagg,
                 const int*   __restrict__ gid,
                 float* __restrict__ C,
                 int M)
{
    constexpr int BM = 128, BN = 128, BK = 16;
    constexpr int N  = 256;
    __shared__ float As[BK][BM + 4];
    __shared__ float Bs[BK][BN];

    const int tid = threadIdx.x;
    const int tx  = tid & 15;
    const int ty  = tid >> 4;
    const int rowBase = blockIdx.x * BM;
    const int colBase = blockIdx.y * BN;

    float acc[8][8];
    #pragma unroll
    for (int i = 0; i < 8; i++)
        #pragma unroll
        for (int j = 0; j < 8; j++) acc[i][j] = 0.f;

    for (int kt = 0; kt < 256; kt += BK) {
        // A tile 128x16 -> transposed As[k][row]
        #pragma unroll
        for (int i = 0; i < 2; i++) {
            int idx  = tid + i * 256;          // 0..511
            int arow = idx >> 2;
            int ak4  = (idx & 3) * 4;
            float4 v = make_float4(0.f, 0.f, 0.f, 0.f);
            int grow = rowBase + arow;
            if (grow < M)
                v = *reinterpret_cast<const float4*>(A + (size_t)grow * N + kt + ak4);
            As[ak4 + 0][arow] = v.x;
            As[ak4 + 1][arow] = v.y;
            As[ak4 + 2][arow] = v.z;
            As[ak4 + 3][arow] = v.w;
        }
        // B tile 16x128
        #pragma unroll
        for (int i = 0; i < 2; i++) {
            int idx  = tid + i * 256;          // 0..511
            int brow = idx >> 5;               // 0..15
            int bc4  = (idx & 31) * 4;         // 0..124
            float4 v = *reinterpret_cast<const float4*>(
                W + (size_t)(kt + brow) * N + colBase + bc4);
            *reinterpret_cast<float4*>(&Bs[brow][bc4]) = v;
        }
        __syncthreads();

        #pragma unroll
        for (int k = 0; k < BK; k++) {
            float a[8], b[8];
            *reinterpret_cast<float4*>(&a[0]) = *reinterpret_cast<float4*>(&As[k][ty * 8]);
            *reinterpret_cast<float4*>(&a[4]) = *reinterpret_cast<float4*>(&As[k][ty * 8 + 4]);
            *reinterpret_cast<float4*>(&b[0]) = *reinterpret_cast<float4*>(&Bs[k][tx * 4]);
            *reinterpret_cast<float4*>(&b[4]) = *reinterpret_cast<float4*>(&Bs[k][64 + tx * 4]);
            #pragma unroll
            for (int i = 0; i < 8; i++)
                #pragma unroll
                for (int j = 0; j < 8; j++)
                    acc[i][j] += a[i] * b[j];
        }
        __syncthreads();
    }

    const int colA = colBase + tx * 4;
    const int colB = colBase + 64 + tx * 4;

    if (MODE == 0) {
        #pragma unroll
        for (int i = 0; i < 8; i++) {
            int row = rowBase + ty * 8 + i;
            if (row < M) {
                *reinterpret_cast<float4*>(C + (size_t)row * N + colA) =
                    make_float4(acc[i][0], acc[i][1], acc[i][2], acc[i][3]);
                *reinterpret_cast<float4*>(C + (size_t)row * N + colB) =
                    make_float4(acc[i][4], acc[i][5], acc[i][6], acc[i][7]);
            }
        }
    } else if (MODE == 1) {
        float4 bsA  = *reinterpret_cast<const float4*>(bias + colA);
        float4 bsB  = *reinterpret_cast<const float4*>(bias + colB);
        float4 baA  = *reinterpret_cast<const float4*>(bagg + colA);
        float4 baB  = *reinterpret_cast<const float4*>(bagg + colB);
        #pragma unroll
        for (int i = 0; i < 8; i++) {
            int row = rowBase + ty * 8 + i;
            if (row < M) {
                float4 agA = *reinterpret_cast<const float4*>(agg + (size_t)row * N + colA);
                float4 agB = *reinterpret_cast<const float4*>(agg + (size_t)row * N + colB);
                float4 v;
                v.x = frelu(acc[i][0] + bsA.x) + frelu(agA.x + baA.x);
                v.y = frelu(acc[i][1] + bsA.y) + frelu(agA.y + baA.y);
                v.z = frelu(acc[i][2] + bsA.z) + frelu(agA.z + baA.z);
                v.w = frelu(acc[i][3] + bsA.w) + frelu(agA.w + baA.w);
                *reinterpret_cast<float4*>(C + (size_t)row * N + colA) = v;
                v.x = frelu(acc[i][4] + bsB.x) + frelu(agB.x + baB.x);
                v.y = frelu(acc[i][5] + bsB.y) + frelu(agB.y + baB.y);
                v.z = frelu(acc[i][6] + bsB.z) + frelu(agB.z + baB.z);
                v.w = frelu(acc[i][7] + bsB.w) + frelu(agB.w + baB.w);
                *reinterpret_cast<float4*>(C + (size_t)row * N + colB) = v;
            }
        }
    } else { // MODE 2: segment-sum into T[512][256] (gid sorted -> run-length merge)
        float4 bsA = *reinterpret_cast<const float4*>(bias + colA);
        float4 bsB = *reinterpret_cast<const float4*>(bias + colB);
        int   lastg = -1;
        float r[8];
        #pragma unroll
        for (int j = 0; j < 8; j++) r[j] = 0.f;
        #pragma unroll
        for (int i = 0; i < 8; i++) {
            int row = rowBase + ty * 8 + i;
            if (row < M) {
                int g = gid[row];
                float v[8];
                v[0] = frelu(acc[i][0] + bsA.x); v[1] = frelu(acc[i][1] + bsA.y);
                v[2] = frelu(acc[i][2] + bsA.z); v[3] = frelu(acc[i][3] + bsA.w);
                v[4] = frelu(acc[i][4] + bsB.x); v[5] = frelu(acc[i][5] + bsB.y);
                v[6] = frelu(acc[i][6] + bsB.z); v[7] = frelu(acc[i][7] + bsB.w);
                if (g != lastg) {
                    if (lastg >= 0) {
                        float* t = C + (size_t)lastg * 256;
                        #pragma unroll
                        for (int j = 0; j < 4; j++) atomicAdd(t + colA + j, r[j]);
                        #pragma unroll
                        for (int j = 0; j < 4; j++) atomicAdd(t + colB + j, r[4 + j]);
                    }
                    lastg = g;
                    #pragma unroll
                    for (int j = 0; j < 8; j++) r[j] = v[j];
                } else {
                    #pragma unroll
                    for (int j = 0; j < 8; j++) r[j] += v[j];
                }
            }
        }
        if (lastg >= 0) {
            float* t = C + (size_t)lastg * 256;
            #pragma unroll
            for (int j = 0; j < 4; j++) atomicAdd(t + colA + j, r[j]);
            #pragma unroll
            for (int j = 0; j < 4; j++) atomicAdd(t + colB + j, r[4 + j]);
        }
    }
}

// ---------------------------------------------------------------------------
// CSR build
// ---------------------------------------------------------------------------
__global__ void hist_kernel(const int* __restrict__ dst, int* __restrict__ deg, int nE)
{
    int e = blockIdx.x * blockDim.x + threadIdx.x;
    if (e < nE) atomicAdd(&deg[dst[e]], 1);
}

__global__ __launch_bounds__(1024)
void scan_kernel(const int* __restrict__ deg, int* __restrict__ rowstart,
                 int* __restrict__ cursor)
{
    __shared__ int warpsums[32];
    const int T = 1024;
    const int CH = (N_NODES + T - 1) / T;   // 49
    int t = threadIdx.x;
    int base = t * CH;
    int s = 0;
    for (int i = 0; i < CH; i++) {
        int idx = base + i;
        if (idx < N_NODES) s += deg[idx];
    }
    int lane = t & 31, w = t >> 5;
    int v = s;
    #pragma unroll
    for (int o = 1; o < 32; o <<= 1) {
        int n = __shfl_up_sync(0xFFFFFFFFu, v, o);
        if (lane >= o) v += n;
    }
    if (lane == 31) warpsums[w] = v;
    __syncthreads();
    if (w == 0) {
        int x = warpsums[lane];
        #pragma unroll
        for (int o = 1; o < 32; o <<= 1) {
            int n = __shfl_up_sync(0xFFFFFFFFu, x, o);
            if (lane >= o) x += n;
        }
        warpsums[lane] = x;
    }
    __syncthreads();
    int excl = v - s + (w > 0 ? warpsums[w - 1] : 0);
    int run = excl;
    for (int i = 0; i < CH; i++) {
        int idx = base + i;
        if (idx < N_NODES) {
            rowstart[idx] = run;
            cursor[idx]   = run;
            run += deg[idx];
        }
    }
    if (t == T - 1) rowstart[N_NODES] = run;
}

__global__ void fill_kernel(const int* __restrict__ src, const int* __restrict__ dst,
                            int* __restrict__ cursor, int* __restrict__ csr_src, int nE)
{
    int e = blockIdx.x * blockDim.x + threadIdx.x;
    if (e < nE) {
        int p = atomicAdd(&cursor[dst[e]], 1);
        csr_src[p] = src[e];
    }
}

// ---------------------------------------------------------------------------
// Warp-per-node gather: agg[n] = sum over in-edges of hW[src]
// ---------------------------------------------------------------------------
__global__ __launch_bounds__(256)
void gather_kernel(const float* __restrict__ hW,
                   const int* __restrict__ rowstart,
                   const int* __restrict__ csr_src,
                   float* __restrict__ agg)
{
    int node = (blockIdx.x * blockDim.x + threadIdx.x) >> 5;
    int lane = threadIdx.x & 31;
    if (node >= N_NODES) return;
    int beg = rowstart[node], end = rowstart[node + 1];
    float4 a0 = make_float4(0.f, 0.f, 0.f, 0.f);
    float4 a1 = make_float4(0.f, 0.f, 0.f, 0.f);
    for (int e = beg; e < end; e++) {
        const float4* row = reinterpret_cast<const float4*>(hW + (size_t)csr_src[e] * DFEAT);
        float4 v0 = row[lane];
        float4 v1 = row[lane + 32];
        a0.x += v0.x; a0.y += v0.y; a0.z += v0.z; a0.w += v0.w;
        a1.x += v1.x; a1.y += v1.y; a1.z += v1.z; a1.w += v1.w;
    }
    float4* out = reinterpret_cast<float4*>(agg + (size_t)node * DFEAT);
    out[lane]      = a0;
    out[lane + 32] = a1;
}

__global__ void counts_kernel(const int* __restrict__ gid, int* __restrict__ counts, int M)
{
    int i = blockIdx.x * blockDim.x + threadIdx.x;
    if (i < M) atomicAdd(&counts[gid[i]], 1);
}

// ---------------------------------------------------------------------------
__global__ __launch_bounds__(256)
void readout_kernel(const float* __restrict__ T,
                    const float* __restrict__ Ro,
                    const float* __restrict__ rbo,
                    const int* __restrict__ counts,
                    float* __restrict__ gacc)
{
    __shared__ float ts[DFEAT];
    int g = blockIdx.x;
    ts[threadIdx.x] = T[(size_t)g * DFEAT + threadIdx.x];
    __syncthreads();
    float cnt = (float)counts[g];
    for (int j = threadIdx.x; j < G_FEAT; j += blockDim.x) {
        float s = 0.f;
        #pragma unroll 8
        for (int k = 0; k < DFEAT; k++)
            s += ts[k] * Ro[(size_t)k * G_FEAT + j];
        gacc[(size_t)g * G_FEAT + j] += s + cnt * rbo[j];
    }
}

__global__ __launch_bounds__(256)
void final_kernel(const float* __restrict__ gacc,
                  const float* __restrict__ Wp,
                  const float* __restrict__ bp,
                  float* __restrict__ out)
{
    __shared__ float red[256];
    int g = blockIdx.x;
    float s = 0.f;
    for (int j = threadIdx.x; j < G_FEAT; j += blockDim.x)
        s += gacc[(size_t)g * G_FEAT + j] * Wp[j];
    red[threadIdx.x] = s;
    __syncthreads();
    #pragma unroll
    for (int st = 128; st > 0; st >>= 1) {
        if (threadIdx.x < st) red[threadIdx.x] += red[threadIdx.x + st];
        __syncthreads();
    }
    if (threadIdx.x == 0) out[g] = red[0] + bp[0];
}

// ---------------------------------------------------------------------------
extern "C" void kernel_launch(void* const* d_in, const int* in_sizes, int n_in,
                              void* d_out, int out_size)
{
    const float* nf [2] = { (const float*)d_in[0],  (const float*)d_in[2]  };
    const int*   src[2] = { (const int*)  d_in[4],  (const int*)  d_in[7]  };
    const int*   dst[2] = { (const int*)  d_in[5],  (const int*)  d_in[8]  };
    const int*   gid[2] = { (const int*)  d_in[6],  (const int*)  d_in[9]  };
    const float* W  [2] = { (const float*)d_in[10], (const float*)d_in[14] };
    const float* b  [2] = { (const float*)d_in[11], (const float*)d_in[15] };
    const float* Wr [2] = { (const float*)d_in[12], (const float*)d_in[16] };
    const float* br [2] = { (const float*)d_in[13], (const float*)d_in[17] };
    const float* Ri [2] = { (const float*)d_in[18], (const float*)d_in[22] };
    const float* rbi[2] = { (const float*)d_in[19], (const float*)d_in[23] };
    const float* Ro [2] = { (const float*)d_in[20], (const float*)d_in[24] };
    const float* rbo[2] = { (const float*)d_in[21], (const float*)d_in[25] };
    const float* Wp  = (const float*)d_in[26];
    const float* bp  = (const float*)d_in[27];

    float *hW, *agg, *h1, *T, *gacc;
    int *counts, *deg, *rowstart, *cursor, *csr_src;
    cudaGetSymbolAddress((void**)&hW,       g_hW);
    cudaGetSymbolAddress((void**)&agg,      g_agg);
    cudaGetSymbolAddress((void**)&h1,       g_h1);
    cudaGetSymbolAddress((void**)&T,        g_T);
    cudaGetSymbolAddress((void**)&gacc,     g_gacc);
    cudaGetSymbolAddress((void**)&counts,   g_counts);
    cudaGetSymbolAddress((void**)&deg,      g_deg);
    cudaGetSymbolAddress((void**)&rowstart, g_rowstart);
    cudaGetSymbolAddress((void**)&cursor,   g_cursor);
    cudaGetSymbolAddress((void**)&csr_src,  g_csr_src);

    cudaMemsetAsync(gacc, 0, (size_t)N_GRAPHS * G_FEAT * sizeof(float));

    dim3 gemm_grid((N_NODES + 127) / 128, 2);
    int eb = (N_EDGES + 255) / 256;

    for (int i = 0; i < 2; i++) {
        cudaMemsetAsync(T,      0, (size_t)N_GRAPHS * DFEAT * sizeof(float));
        cudaMemsetAsync(counts, 0, N_GRAPHS * sizeof(int));
        cudaMemsetAsync(deg,    0, N_NODES * sizeof(int));

        // CSR build (overlappable with hW GEMM in-stream order: hist/scan/fill
        // only touch dst; GEMM only touches nf/W)
        hist_kernel<<<eb, 256>>>(dst[i], deg, N_EDGES);
        scan_kernel<<<1, 1024>>>(deg, rowstart, cursor);
        fill_kernel<<<eb, 256>>>(src[i], dst[i], cursor, csr_src, N_EDGES);

        // hW = h @ W
        gemm_kernel<0><<<gemm_grid, 256>>>(nf[i], W[i], nullptr, nullptr, nullptr,
                                           nullptr, hW, N_NODES);
        // agg = gather-sum of hW rows
        gather_kernel<<<(N_NODES * 32 + 255) / 256, 256>>>(hW, rowstart, csr_src, agg);
        // h1 = relu(agg + b) + relu(h @ Wr + br)
        gemm_kernel<1><<<gemm_grid, 256>>>(nf[i], Wr[i], br[i], agg, b[i],
                                           nullptr, h1, N_NODES);
        // per-graph node counts
        counts_kernel<<<(N_NODES + 255) / 256, 256>>>(gid[i], counts, N_NODES);
        // T[g] = segsum relu(h1 @ Ri + rbi)
        gemm_kernel<2><<<gemm_grid, 256>>>(h1, Ri[i], rbi[i], nullptr, nullptr,
                                           gid[i], T, N_NODES);
        // gacc += T @ Ro + counts*rbo
        readout_kernel<<<N_GRAPHS, 256>>>(T, Ro[i], rbo[i], counts, gacc);
    }

    final_kernel<<<N_GRAPHS, 256>>>(gacc, Wp, bp, (float*)d_out);
}

// round 4
// speedup vs baseline: 2.3500x; 1.5556x over previous
#include <cuda_runtime.h>
#include <cuda_bf16.h>
#include <cstdint>
#include <cstddef>

// ---------------------------------------------------------------------------
// mulGCN: two-branch GCN forward, split-bf16 mma.sync GEMMs (sm_103-safe).
// Per branch:
//   CSR build by dst (hist -> scan -> fill)
//   hW  = h @ W                                    (MMA GEMM MODE 0)
//   agg[n] = sum_{e: dst=n} hW[src[e]]             (warp-per-node gather)
//   h1  = relu(agg + b) + relu(h @ Wr + br)        (MMA GEMM MODE 1)
//   h2  = relu(h1 @ Ri + rbi)                      (MMA GEMM MODE 2)
//   T[g] = segsum of h2 rows (gid sorted)          (no atomics)
//   gacc += T @ Ro + counts*rbo
// Final: out = gacc @ Wp + bp
// Split-bf16: x = hi(trunc bf16, exact) + lo(bf16 of remainder);
// A@B ~= AhiBhi + AhiBlo + AloBhi, fp32 accum -> ~1e-5 rel error.
// ---------------------------------------------------------------------------

#define N_NODES   50000
#define N_EDGES   800000
#define DFEAT     256
#define G_FEAT    200
#define N_GRAPHS  512

__device__ float g_hW  [(size_t)N_NODES * DFEAT];   // reused as h2
__device__ float g_agg [(size_t)N_NODES * DFEAT];
__device__ float g_h1  [(size_t)N_NODES * DFEAT];
__device__ float g_T   [N_GRAPHS * DFEAT];
__device__ float g_gacc[N_GRAPHS * G_FEAT];
__device__ int   g_counts[N_GRAPHS];
__device__ int   g_deg     [N_NODES];
__device__ int   g_rowstart[N_NODES + 1];
__device__ int   g_cursor  [N_NODES];
__device__ int   g_csr_src [N_EDGES];

__device__ __forceinline__ float frelu(float x) { return x > 0.f ? x : 0.f; }

// ------------------------- mma helpers -------------------------------------
__device__ __forceinline__ void mma16816(float* c, const uint32_t* a,
                                         uint32_t b0, uint32_t b1) {
    asm volatile(
        "mma.sync.aligned.m16n8k16.row.col.f32.bf16.bf16.f32 "
        "{%0,%1,%2,%3}, {%4,%5,%6,%7}, {%8,%9}, {%0,%1,%2,%3};\n"
        : "+f"(c[0]), "+f"(c[1]), "+f"(c[2]), "+f"(c[3])
        : "r"(a[0]), "r"(a[1]), "r"(a[2]), "r"(a[3]), "r"(b0), "r"(b1));
}

// hi word: low16 = high-half of x, high16 = high-half of y  (truncated bf16)
__device__ __forceinline__ uint32_t pack_hi(float x, float y) {
    return __byte_perm(__float_as_uint(x), __float_as_uint(y), 0x7632);
}
// lo word: bf16_rn(x - hi(x)) in low16, same for y in high16
__device__ __forceinline__ uint32_t pack_lo(float x, float y) {
    float hx = __uint_as_float(__float_as_uint(x) & 0xFFFF0000u);
    float hy = __uint_as_float(__float_as_uint(y) & 0xFFFF0000u);
    __nv_bfloat162 t;
    t.x = __float2bfloat16(x - hx);
    t.y = __float2bfloat16(y - hy);
    return *reinterpret_cast<uint32_t*>(&t);
}

// SMEM layout (uint32 words), per buffer:
//   AH[128][20]  (2560)   rows x k2-pairs, pad 20 -> conflict-free frags
//   AL[128][20]  (2560)
//   BH[16][136]  (2176)   k2 x cols, pad 136 -> conflict-free frags
//   BL[16][136]  (2176)
static constexpr int W_AH = 0, W_AL = 2560, W_BH = 5120, W_BL = 7296;
static constexpr int WBUF = 9472;
static constexpr int SMEM_WORDS = 2 * WBUF;            // 18944
static constexpr int SMEM_BYTES = SMEM_WORDS * 4;      // 75776

__device__ __forceinline__ void ldg_chunk(const float* __restrict__ A,
                                          const float* __restrict__ Wm,
                                          int M, int rowBase, int colBase, int kt,
                                          int tid, float4 av[4],
                                          float4 b0[2], float4 b1[2])
{
    #pragma unroll
    for (int t = 0; t < 4; t++) {
        int idx = tid + t * 256;          // 1024 float4 covering 128x32
        int r   = idx >> 3;
        int kf  = (idx & 7) * 4;
        int row = rowBase + r;
        av[t] = (row < M)
            ? *reinterpret_cast<const float4*>(A + (size_t)row * 256 + kt + kf)
            : make_float4(0.f, 0.f, 0.f, 0.f);
    }
    #pragma unroll
    for (int t = 0; t < 2; t++) {
        int idx = tid + t * 256;          // 512 pair-loads covering 32x128
        int kp  = idx >> 5;               // 0..15
        int n4  = (idx & 31) * 4;         // 0..124
        const float* base = Wm + (size_t)(kt + kp * 2) * 256 + colBase + n4;
        b0[t] = *reinterpret_cast<const float4*>(base);
        b1[t] = *reinterpret_cast<const float4*>(base + 256);
    }
}

__device__ __forceinline__ void sts_chunk(uint32_t* __restrict__ buf, int tid,
                                          const float4 av[4],
                                          const float4 b0[2], const float4 b1[2])
{
    uint32_t* AH = buf + W_AH;
    uint32_t* AL = buf + W_AL;
    uint32_t* BH = buf + W_BH;
    uint32_t* BL = buf + W_BL;
    #pragma unroll
    for (int t = 0; t < 4; t++) {
        int idx = tid + t * 256;
        int r   = idx >> 3;
        int k2  = (idx & 7) * 2;
        float4 v = av[t];
        uint2 h = make_uint2(pack_hi(v.x, v.y), pack_hi(v.z, v.w));
        uint2 l = make_uint2(pack_lo(v.x, v.y), pack_lo(v.z, v.w));
        *reinterpret_cast<uint2*>(&AH[r * 20 + k2]) = h;
        *reinterpret_cast<uint2*>(&AL[r * 20 + k2]) = l;
    }
    #pragma unroll
    for (int t = 0; t < 2; t++) {
        int idx = tid + t * 256;
        int kp  = idx >> 5;
        int n4  = (idx & 31) * 4;
        float4 p = b0[t], q = b1[t];
        uint4 h = make_uint4(pack_hi(p.x, q.x), pack_hi(p.y, q.y),
                             pack_hi(p.z, q.z), pack_hi(p.w, q.w));
        uint4 l = make_uint4(pack_lo(p.x, q.x), pack_lo(p.y, q.y),
                             pack_lo(p.z, q.z), pack_lo(p.w, q.w));
        *reinterpret_cast<uint4*>(&BH[kp * 136 + n4]) = h;
        *reinterpret_cast<uint4*>(&BL[kp * 136 + n4]) = l;
    }
}

// ---------------------------------------------------------------------------
// mma GEMM: C[M,256] = epilogue(A[M,256] @ W[256,256])
// Grid (ceil(M/128), 2); block 256 = 8 warps (4 m x 2 n); warp tile 32x64.
// MODE 0: C = acc;  MODE 1: C = relu(acc+bias)+relu(agg+bagg);  MODE 2: relu(acc+bias)
// ---------------------------------------------------------------------------
template<int MODE>
__global__ __launch_bounds__(256, 1)
void gemm_mma(const float* __restrict__ A,
              const float* __restrict__ Wm,
              const float* __restrict__ bias,
              const float* __restrict__ agg,
              const float* __restrict__ bagg,
              float* __restrict__ C,
              int M)
{
    extern __shared__ uint32_t sm[];
    const int tid  = threadIdx.x;
    const int lane = tid & 31;
    const int wid  = tid >> 5;
    const int wm   = wid & 3;            // 0..3 -> rows
    const int wn   = wid >> 2;           // 0..1 -> cols
    const int gid  = lane >> 2;          // 0..7
    const int tig  = lane & 3;           // 0..3
    const int rowBase = blockIdx.x * 128;
    const int colBase = blockIdx.y * 128;

    float acc[2][8][4];
    #pragma unroll
    for (int mt = 0; mt < 2; mt++)
        #pragma unroll
        for (int nt = 0; nt < 8; nt++)
            #pragma unroll
            for (int q = 0; q < 4; q++) acc[mt][nt][q] = 0.f;

    float4 av[4], bv0[2], bv1[2];

    // prologue: chunk 0 into buf 0
    ldg_chunk(A, Wm, M, rowBase, colBase, 0, tid, av, bv0, bv1);
    sts_chunk(sm, tid, av, bv0, bv1);
    __syncthreads();

    #pragma unroll
    for (int c = 0; c < 8; c++) {
        if (c < 7)
            ldg_chunk(A, Wm, M, rowBase, colBase, (c + 1) * 32, tid, av, bv0, bv1);

        uint32_t* buf = sm + (c & 1) * WBUF;
        const uint32_t* AH = buf + W_AH;
        const uint32_t* AL = buf + W_AL;
        const uint32_t* BH = buf + W_BH;
        const uint32_t* BL = buf + W_BL;

        #pragma unroll
        for (int ks = 0; ks < 2; ks++) {
            uint32_t aH[2][4], aL[2][4];
            #pragma unroll
            for (int mt = 0; mt < 2; mt++) {
                int off = (wm * 32 + mt * 16 + gid) * 20 + ks * 8 + tig;
                aH[mt][0] = AH[off];       aH[mt][1] = AH[off + 160];
                aH[mt][2] = AH[off + 4];   aH[mt][3] = AH[off + 164];
                aL[mt][0] = AL[off];       aL[mt][1] = AL[off + 160];
                aL[mt][2] = AL[off + 4];   aL[mt][3] = AL[off + 164];
            }
            #pragma unroll
            for (int nt = 0; nt < 8; nt++) {
                int bi = (ks * 8 + tig) * 136 + wn * 64 + nt * 8 + gid;
                uint32_t bh0 = BH[bi], bh1 = BH[bi + 544];
                uint32_t bl0 = BL[bi], bl1 = BL[bi + 544];
                #pragma unroll
                for (int mt = 0; mt < 2; mt++) {
                    mma16816(acc[mt][nt], aH[mt], bh0, bh1);
                    mma16816(acc[mt][nt], aH[mt], bl0, bl1);
                    mma16816(acc[mt][nt], aL[mt], bh0, bh1);
                }
            }
        }

        if (c < 7)
            sts_chunk(sm + ((c + 1) & 1) * WBUF, tid, av, bv0, bv1);
        __syncthreads();
    }

    // ------------------------------ epilogue -------------------------------
    #pragma unroll
    for (int mt = 0; mt < 2; mt++) {
        #pragma unroll
        for (int nt = 0; nt < 8; nt++) {
            int r0  = rowBase + wm * 32 + mt * 16 + gid;
            int r1  = r0 + 8;
            int col = colBase + wn * 64 + nt * 8 + 2 * tig;
            float* a4 = acc[mt][nt];
            if (MODE == 0) {
                if (r0 < M)
                    *reinterpret_cast<float2*>(C + (size_t)r0 * 256 + col) =
                        make_float2(a4[0], a4[1]);
                if (r1 < M)
                    *reinterpret_cast<float2*>(C + (size_t)r1 * 256 + col) =
                        make_float2(a4[2], a4[3]);
            } else if (MODE == 1) {
                float2 bs = *reinterpret_cast<const float2*>(bias + col);
                float2 ba = *reinterpret_cast<const float2*>(bagg + col);
                if (r0 < M) {
                    float2 ag = *reinterpret_cast<const float2*>(agg + (size_t)r0 * 256 + col);
                    *reinterpret_cast<float2*>(C + (size_t)r0 * 256 + col) =
                        make_float2(frelu(a4[0] + bs.x) + frelu(ag.x + ba.x),
                                    frelu(a4[1] + bs.y) + frelu(ag.y + ba.y));
                }
                if (r1 < M) {
                    float2 ag = *reinterpret_cast<const float2*>(agg + (size_t)r1 * 256 + col);
                    *reinterpret_cast<float2*>(C + (size_t)r1 * 256 + col) =
                        make_float2(frelu(a4[2] + bs.x) + frelu(ag.x + ba.x),
                                    frelu(a4[3] + bs.y) + frelu(ag.y + ba.y));
                }
            } else {
                float2 bs = *reinterpret_cast<const float2*>(bias + col);
                if (r0 < M)
                    *reinterpret_cast<float2*>(C + (size_t)r0 * 256 + col) =
                        make_float2(frelu(a4[0] + bs.x), frelu(a4[1] + bs.y));
                if (r1 < M)
                    *reinterpret_cast<float2*>(C + (size_t)r1 * 256 + col) =
                        make_float2(frelu(a4[2] + bs.x), frelu(a4[3] + bs.y));
            }
        }
    }
}

// ---------------------------------------------------------------------------
// CSR build
// ---------------------------------------------------------------------------
__global__ void hist_kernel(const int* __restrict__ dst, int* __restrict__ deg, int nE)
{
    int e = blockIdx.x * blockDim.x + threadIdx.x;
    if (e < nE) atomicAdd(&deg[dst[e]], 1);
}

__global__ __launch_bounds__(1024)
void scan_kernel(const int* __restrict__ deg, int* __restrict__ rowstart,
                 int* __restrict__ cursor)
{
    __shared__ int warpsums[32];
    const int T = 1024;
    const int CH = (N_NODES + T - 1) / T;
    int t = threadIdx.x;
    int base = t * CH;
    int s = 0;
    for (int i = 0; i < CH; i++) {
        int idx = base + i;
        if (idx < N_NODES) s += deg[idx];
    }
    int lane = t & 31, w = t >> 5;
    int v = s;
    #pragma unroll
    for (int o = 1; o < 32; o <<= 1) {
        int n = __shfl_up_sync(0xFFFFFFFFu, v, o);
        if (lane >= o) v += n;
    }
    if (lane == 31) warpsums[w] = v;
    __syncthreads();
    if (w == 0) {
        int x = warpsums[lane];
        #pragma unroll
        for (int o = 1; o < 32; o <<= 1) {
            int n = __shfl_up_sync(0xFFFFFFFFu, x, o);
            if (lane >= o) x += n;
        }
        warpsums[lane] = x;
    }
    __syncthreads();
    int excl = v - s + (w > 0 ? warpsums[w - 1] : 0);
    int run = excl;
    for (int i = 0; i < CH; i++) {
        int idx = base + i;
        if (idx < N_NODES) {
            rowstart[idx] = run;
            cursor[idx]   = run;
            run += deg[idx];
        }
    }
    if (t == T - 1) rowstart[N_NODES] = run;
}

__global__ void fill_kernel(const int* __restrict__ src, const int* __restrict__ dst,
                            int* __restrict__ cursor, int* __restrict__ csr_src, int nE)
{
    int e = blockIdx.x * blockDim.x + threadIdx.x;
    if (e < nE) {
        int p = atomicAdd(&cursor[dst[e]], 1);
        csr_src[p] = src[e];
    }
}

// ---------------------------------------------------------------------------
// Warp-per-node gather: agg[n] = sum over in-edges of hW[src]
// ---------------------------------------------------------------------------
__global__ __launch_bounds__(256)
void gather_kernel(const float* __restrict__ hW,
                   const int* __restrict__ rowstart,
                   const int* __restrict__ csr_src,
                   float* __restrict__ agg)
{
    int node = (blockIdx.x * blockDim.x + threadIdx.x) >> 5;
    int lane = threadIdx.x & 31;
    if (node >= N_NODES) return;
    int beg = rowstart[node], end = rowstart[node + 1];
    float4 a0 = make_float4(0.f, 0.f, 0.f, 0.f);
    float4 a1 = make_float4(0.f, 0.f, 0.f, 0.f);
    for (int e = beg; e < end; e++) {
        const float4* row = reinterpret_cast<const float4*>(hW + (size_t)csr_src[e] * DFEAT);
        float4 v0 = row[lane];
        float4 v1 = row[lane + 32];
        a0.x += v0.x; a0.y += v0.y; a0.z += v0.z; a0.w += v0.w;
        a1.x += v1.x; a1.y += v1.y; a1.z += v1.z; a1.w += v1.w;
    }
    float4* out = reinterpret_cast<float4*>(agg + (size_t)node * DFEAT);
    out[lane]      = a0;
    out[lane + 32] = a1;
}

// ---------------------------------------------------------------------------
// Segment sum over contiguous (sorted gid) row ranges, binary-searched.
// Block = graph; thread = column. Also produces counts.
// ---------------------------------------------------------------------------
__global__ __launch_bounds__(256)
void segsum_kernel(const float* __restrict__ h2, const int* __restrict__ gid,
                   float* __restrict__ T, int* __restrict__ counts)
{
    __shared__ int sb, se;
    int g = blockIdx.x;
    if (threadIdx.x == 0) {
        int lo = 0, hi = N_NODES;
        while (lo < hi) { int m = (lo + hi) >> 1; if (gid[m] < g) lo = m + 1; else hi = m; }
        sb = lo;
        lo = sb; hi = N_NODES;
        while (lo < hi) { int m = (lo + hi) >> 1; if (gid[m] < g + 1) lo = m + 1; else hi = m; }
        se = lo;
        counts[g] = se - sb;
    }
    __syncthreads();
    int beg = sb, end = se, c = threadIdx.x;
    float s = 0.f;
    for (int r = beg; r < end; r++)
        s += h2[(size_t)r * DFEAT + c];
    T[(size_t)g * DFEAT + c] = s;
}

// ---------------------------------------------------------------------------
__global__ __launch_bounds__(256)
void readout_kernel(const float* __restrict__ T,
                    const float* __restrict__ Ro,
                    const float* __restrict__ rbo,
                    const int* __restrict__ counts,
                    float* __restrict__ gacc)
{
    __shared__ float ts[DFEAT];
    int g = blockIdx.x;
    ts[threadIdx.x] = T[(size_t)g * DFEAT + threadIdx.x];
    __syncthreads();
    float cnt = (float)counts[g];
    for (int j = threadIdx.x; j < G_FEAT; j += blockDim.x) {
        float s = 0.f;
        #pragma unroll 8
        for (int k = 0; k < DFEAT; k++)
            s += ts[k] * Ro[(size_t)k * G_FEAT + j];
        gacc[(size_t)g * G_FEAT + j] += s + cnt * rbo[j];
    }
}

__global__ __launch_bounds__(256)
void final_kernel(const float* __restrict__ gacc,
                  const float* __restrict__ Wp,
                  const float* __restrict__ bp,
                  float* __restrict__ out)
{
    __shared__ float red[256];
    int g = blockIdx.x;
    float s = 0.f;
    for (int j = threadIdx.x; j < G_FEAT; j += blockDim.x)
        s += gacc[(size_t)g * G_FEAT + j] * Wp[j];
    red[threadIdx.x] = s;
    __syncthreads();
    #pragma unroll
    for (int st = 128; st > 0; st >>= 1) {
        if (threadIdx.x < st) red[threadIdx.x] += red[threadIdx.x + st];
        __syncthreads();
    }
    if (threadIdx.x == 0) out[g] = red[0] + bp[0];
}

// ---------------------------------------------------------------------------
extern "C" void kernel_launch(void* const* d_in, const int* in_sizes, int n_in,
                              void* d_out, int out_size)
{
    const float* nf [2] = { (const float*)d_in[0],  (const float*)d_in[2]  };
    const int*   src[2] = { (const int*)  d_in[4],  (const int*)  d_in[7]  };
    const int*   dst[2] = { (const int*)  d_in[5],  (const int*)  d_in[8]  };
    const int*   gid[2] = { (const int*)  d_in[6],  (const int*)  d_in[9]  };
    const float* W  [2] = { (const float*)d_in[10], (const float*)d_in[14] };
    const float* b  [2] = { (const float*)d_in[11], (const float*)d_in[15] };
    const float* Wr [2] = { (const float*)d_in[12], (const float*)d_in[16] };
    const float* br [2] = { (const float*)d_in[13], (const float*)d_in[17] };
    const float* Ri [2] = { (const float*)d_in[18], (const float*)d_in[22] };
    const float* rbi[2] = { (const float*)d_in[19], (const float*)d_in[23] };
    const float* Ro [2] = { (const float*)d_in[20], (const float*)d_in[24] };
    const float* rbo[2] = { (const float*)d_in[21], (const float*)d_in[25] };
    const float* Wp  = (const float*)d_in[26];
    const float* bp  = (const float*)d_in[27];

    float *hW, *agg, *h1, *T, *gacc;
    int *counts, *deg, *rowstart, *cursor, *csr_src;
    cudaGetSymbolAddress((void**)&hW,       g_hW);
    cudaGetSymbolAddress((void**)&agg,      g_agg);
    cudaGetSymbolAddress((void**)&h1,       g_h1);
    cudaGetSymbolAddress((void**)&T,        g_T);
    cudaGetSymbolAddress((void**)&gacc,     g_gacc);
    cudaGetSymbolAddress((void**)&counts,   g_counts);
    cudaGetSymbolAddress((void**)&deg,      g_deg);
    cudaGetSymbolAddress((void**)&rowstart, g_rowstart);
    cudaGetSymbolAddress((void**)&cursor,   g_cursor);
    cudaGetSymbolAddress((void**)&csr_src,  g_csr_src);

    cudaFuncSetAttribute(gemm_mma<0>, cudaFuncAttributeMaxDynamicSharedMemorySize, SMEM_BYTES);
    cudaFuncSetAttribute(gemm_mma<1>, cudaFuncAttributeMaxDynamicSharedMemorySize, SMEM_BYTES);
    cudaFuncSetAttribute(gemm_mma<2>, cudaFuncAttributeMaxDynamicSharedMemorySize, SMEM_BYTES);

    cudaMemsetAsync(gacc, 0, (size_t)N_GRAPHS * G_FEAT * sizeof(float));

    dim3 gemm_grid((N_NODES + 127) / 128, 2);   // 391 x 2
    int eb = (N_EDGES + 255) / 256;

    for (int i = 0; i < 2; i++) {
        cudaMemsetAsync(deg, 0, N_NODES * sizeof(int));

        hist_kernel<<<eb, 256>>>(dst[i], deg, N_EDGES);
        scan_kernel<<<1, 1024>>>(deg, rowstart, cursor);
        fill_kernel<<<eb, 256>>>(src[i], dst[i], cursor, csr_src, N_EDGES);

        // hW = h @ W
        gemm_mma<0><<<gemm_grid, 256, SMEM_BYTES>>>(nf[i], W[i], nullptr, nullptr,
                                                    nullptr, hW, N_NODES);
        // agg = gather-sum of hW rows
        gather_kernel<<<(N_NODES * 32 + 255) / 256, 256>>>(hW, rowstart, csr_src, agg);
        // h1 = relu(agg + b) + relu(h @ Wr + br)
        gemm_mma<1><<<gemm_grid, 256, SMEM_BYTES>>>(nf[i], Wr[i], br[i], agg, b[i],
                                                    h1, N_NODES);
        // h2 = relu(h1 @ Ri + rbi)   (reuse hW buffer)
        gemm_mma<2><<<gemm_grid, 256, SMEM_BYTES>>>(h1, Ri[i], rbi[i], nullptr,
                                                    nullptr, hW, N_NODES);
        // T[g] = segsum of h2 rows; counts
        segsum_kernel<<<N_GRAPHS, 256>>>(hW, gid[i], T, counts);
        // gacc += T @ Ro + counts*rbo
        readout_kernel<<<N_GRAPHS, 256>>>(T, Ro[i], rbo[i], counts, gacc);
    }

    final_kernel<<<N_GRAPHS, 256>>>(gacc, Wp, bp, (float*)d_out);
}

// round 5
// speedup vs baseline: 2.3632x; 1.0056x over previous
#include <cuda_runtime.h>
#include <cuda_bf16.h>
#include <cstdint>
#include <cstddef>

// ---------------------------------------------------------------------------
// mulGCN: two-branch GCN forward, split-bf16 mma.sync GEMMs (sm_103-safe).
// Both branches fused into each launch (grid.z / index-range selects branch).
//   CSR build by dst (hist -> scan -> fill)          [both branches]
//   hW  = h @ W                                      (MMA GEMM MODE 0)
//   agg[n] = sum_{e: dst=n} hW[src[e]]               (warp-per-node gather)
//   h1  = relu(agg + b) + relu(h @ Wr + br)          (MMA GEMM MODE 1)
//   h2  = relu(h1 @ Ri + rbi)                        (MMA GEMM MODE 2)
//   T[g] = segsum of h2 rows (gid sorted, no atomics)
//   out[g] = (T1@Ro1 + c1*rbo1 + T2@Ro2 + c2*rbo2) . Wp + bp   (fused)
// Split-bf16: x = hi(trunc bf16, exact) + lo(bf16 of remainder);
// A@B ~= AhiBhi + AhiBlo + AloBhi, fp32 accum -> ~2e-5 rel error.
// ---------------------------------------------------------------------------

#define N_NODES   50000
#define N_EDGES   800000
#define DFEAT     256
#define G_FEAT    200
#define N_GRAPHS  512

__device__ float g_hW  [2][(size_t)N_NODES * DFEAT];   // reused as h2
__device__ float g_agg [2][(size_t)N_NODES * DFEAT];
__device__ float g_h1  [2][(size_t)N_NODES * DFEAT];
__device__ float g_T   [2][N_GRAPHS * DFEAT];
__device__ int   g_counts  [2][N_GRAPHS];
__device__ int   g_deg     [2][N_NODES];
__device__ int   g_rowstart[2][N_NODES + 1];
__device__ int   g_cursor  [2][N_NODES];
__device__ int   g_csr_src [2][N_EDGES];

__device__ __forceinline__ float frelu(float x) { return x > 0.f ? x : 0.f; }

// ------------------------- mma helpers -------------------------------------
__device__ __forceinline__ void mma16816(float* c, const uint32_t* a,
                                         uint32_t b0, uint32_t b1) {
    asm volatile(
        "mma.sync.aligned.m16n8k16.row.col.f32.bf16.bf16.f32 "
        "{%0,%1,%2,%3}, {%4,%5,%6,%7}, {%8,%9}, {%0,%1,%2,%3};\n"
        : "+f"(c[0]), "+f"(c[1]), "+f"(c[2]), "+f"(c[3])
        : "r"(a[0]), "r"(a[1]), "r"(a[2]), "r"(a[3]), "r"(b0), "r"(b1));
}

__device__ __forceinline__ uint32_t pack_hi(float x, float y) {
    return __byte_perm(__float_as_uint(x), __float_as_uint(y), 0x7632);
}
__device__ __forceinline__ uint32_t pack_lo(float x, float y) {
    float hx = __uint_as_float(__float_as_uint(x) & 0xFFFF0000u);
    float hy = __uint_as_float(__float_as_uint(y) & 0xFFFF0000u);
    __nv_bfloat162 t;
    t.x = __float2bfloat16(x - hx);
    t.y = __float2bfloat16(y - hy);
    return *reinterpret_cast<uint32_t*>(&t);
}

// SMEM words per buffer: AH[128][20] AL[128][20] BH[16][136] BL[16][136]
static constexpr int W_AH = 0, W_AL = 2560, W_BH = 5120, W_BL = 7296;
static constexpr int WBUF = 9472;
static constexpr int SMEM_BYTES = 2 * WBUF * 4;        // 75776

__device__ __forceinline__ void ldgA(const float* __restrict__ A, int M,
                                     int rowBase, int kt, int tid, float4 av[4])
{
    #pragma unroll
    for (int t = 0; t < 4; t++) {
        int idx = tid + t * 256;          // 1024 float4 covering 128x32
        int r   = idx >> 3;
        int kf  = (idx & 7) * 4;
        int row = rowBase + r;
        av[t] = (row < M)
            ? *reinterpret_cast<const float4*>(A + (size_t)row * 256 + kt + kf)
            : make_float4(0.f, 0.f, 0.f, 0.f);
    }
}

__device__ __forceinline__ void stsA(uint32_t* __restrict__ buf, int tid,
                                     const float4 av[4])
{
    uint32_t* AH = buf + W_AH;
    uint32_t* AL = buf + W_AL;
    #pragma unroll
    for (int t = 0; t < 4; t++) {
        int idx = tid + t * 256;
        int r   = idx >> 3;
        int k2  = (idx & 7) * 2;
        float4 v = av[t];
        uint2 h = make_uint2(pack_hi(v.x, v.y), pack_hi(v.z, v.w));
        uint2 l = make_uint2(pack_lo(v.x, v.y), pack_lo(v.z, v.w));
        *reinterpret_cast<uint2*>(&AH[r * 20 + k2]) = h;
        *reinterpret_cast<uint2*>(&AL[r * 20 + k2]) = l;
    }
}

__device__ __forceinline__ void ldstB(const float* __restrict__ Wm,
                                      uint32_t* __restrict__ buf,
                                      int colBase, int kt, int tid)
{
    uint32_t* BH = buf + W_BH;
    uint32_t* BL = buf + W_BL;
    #pragma unroll
    for (int t = 0; t < 2; t++) {
        int idx = tid + t * 256;          // 512 covering 32x128 (pairs of k)
        int kp  = idx >> 5;               // 0..15
        int n4  = (idx & 31) * 4;         // 0..124
        const float* base = Wm + (size_t)(kt + kp * 2) * 256 + colBase + n4;
        float4 p = *reinterpret_cast<const float4*>(base);
        float4 q = *reinterpret_cast<const float4*>(base + 256);
        uint4 h = make_uint4(pack_hi(p.x, q.x), pack_hi(p.y, q.y),
                             pack_hi(p.z, q.z), pack_hi(p.w, q.w));
        uint4 l = make_uint4(pack_lo(p.x, q.x), pack_lo(p.y, q.y),
                             pack_lo(p.z, q.z), pack_lo(p.w, q.w));
        *reinterpret_cast<uint4*>(&BH[kp * 136 + n4]) = h;
        *reinterpret_cast<uint4*>(&BL[kp * 136 + n4]) = l;
    }
}

// ---------------------------------------------------------------------------
// mma GEMM: C[M,256] = epilogue(A[M,256] @ W[256,256]); both branches (grid.z)
// Grid (ceil(M/128), 2, 2); block 256 = 8 warps (4 m x 2 n); warp tile 32x64.
// MODE 0: C = acc;  MODE 1: C = relu(acc+bias)+relu(agg+bagg);  MODE 2: relu(acc+bias)
// ---------------------------------------------------------------------------
template<int MODE>
__global__ __launch_bounds__(256, 2)
void gemm_mma(const float* __restrict__ A1, const float* __restrict__ A2,
              const float* __restrict__ W1, const float* __restrict__ W2,
              const float* __restrict__ bias1, const float* __restrict__ bias2,
              const float* __restrict__ agg1, const float* __restrict__ agg2,
              const float* __restrict__ bagg1, const float* __restrict__ bagg2,
              float* __restrict__ C1, float* __restrict__ C2,
              int M)
{
    extern __shared__ uint32_t sm[];
    const int br = blockIdx.z;
    const float* A    = br ? A2 : A1;
    const float* Wm   = br ? W2 : W1;
    const float* bias = br ? bias2 : bias1;
    const float* agg  = br ? agg2 : agg1;
    const float* bagg = br ? bagg2 : bagg1;
    float*       C    = br ? C2 : C1;

    const int tid  = threadIdx.x;
    const int lane = tid & 31;
    const int wid  = tid >> 5;
    const int wm   = wid & 3;
    const int wn   = wid >> 2;
    const int gid  = lane >> 2;
    const int tig  = lane & 3;
    const int rowBase = blockIdx.x * 128;
    const int colBase = blockIdx.y * 128;

    float acc[2][8][4];
    #pragma unroll
    for (int mt = 0; mt < 2; mt++)
        #pragma unroll
        for (int nt = 0; nt < 8; nt++)
            #pragma unroll
            for (int q = 0; q < 4; q++) acc[mt][nt][q] = 0.f;

    float4 av[4];

    // prologue: chunk 0 into buf 0
    ldgA(A, M, rowBase, 0, tid, av);
    stsA(sm, tid, av);
    ldstB(Wm, sm, colBase, 0, tid);
    __syncthreads();

    #pragma unroll
    for (int c = 0; c < 8; c++) {
        if (c < 7) ldgA(A, M, rowBase, (c + 1) * 32, tid, av);  // A prefetch only

        uint32_t* buf = sm + (c & 1) * WBUF;
        const uint32_t* AH = buf + W_AH;
        const uint32_t* AL = buf + W_AL;
        const uint32_t* BH = buf + W_BH;
        const uint32_t* BL = buf + W_BL;

        #pragma unroll
        for (int ks = 0; ks < 2; ks++) {
            uint32_t aH[2][4], aL[2][4];
            #pragma unroll
            for (int mt = 0; mt < 2; mt++) {
                int off = (wm * 32 + mt * 16 + gid) * 20 + ks * 8 + tig;
                aH[mt][0] = AH[off];       aH[mt][1] = AH[off + 160];
                aH[mt][2] = AH[off + 4];   aH[mt][3] = AH[off + 164];
                aL[mt][0] = AL[off];       aL[mt][1] = AL[off + 160];
                aL[mt][2] = AL[off + 4];   aL[mt][3] = AL[off + 164];
            }
            #pragma unroll
            for (int nt = 0; nt < 8; nt++) {
                int bi = (ks * 8 + tig) * 136 + wn * 64 + nt * 8 + gid;
                uint32_t bh0 = BH[bi], bh1 = BH[bi + 544];
                uint32_t bl0 = BL[bi], bl1 = BL[bi + 544];
                #pragma unroll
                for (int mt = 0; mt < 2; mt++) {
                    mma16816(acc[mt][nt], aH[mt], bh0, bh1);
                    mma16816(acc[mt][nt], aH[mt], bl0, bl1);
                    mma16816(acc[mt][nt], aL[mt], bh0, bh1);
                }
            }
        }

        if (c < 7) {
            uint32_t* nbuf = sm + ((c + 1) & 1) * WBUF;
            stsA(nbuf, tid, av);
            ldstB(Wm, nbuf, colBase, (c + 1) * 32, tid);
        }
        __syncthreads();
    }

    // ------------------------------ epilogue -------------------------------
    #pragma unroll
    for (int mt = 0; mt < 2; mt++) {
        #pragma unroll
        for (int nt = 0; nt < 8; nt++) {
            int r0  = rowBase + wm * 32 + mt * 16 + gid;
            int r1  = r0 + 8;
            int col = colBase + wn * 64 + nt * 8 + 2 * tig;
            float* a4 = acc[mt][nt];
            if (MODE == 0) {
                if (r0 < M)
                    *reinterpret_cast<float2*>(C + (size_t)r0 * 256 + col) =
                        make_float2(a4[0], a4[1]);
                if (r1 < M)
                    *reinterpret_cast<float2*>(C + (size_t)r1 * 256 + col) =
                        make_float2(a4[2], a4[3]);
            } else if (MODE == 1) {
                float2 bs = *reinterpret_cast<const float2*>(bias + col);
                float2 ba = *reinterpret_cast<const float2*>(bagg + col);
                if (r0 < M) {
                    float2 ag = *reinterpret_cast<const float2*>(agg + (size_t)r0 * 256 + col);
                    *reinterpret_cast<float2*>(C + (size_t)r0 * 256 + col) =
                        make_float2(frelu(a4[0] + bs.x) + frelu(ag.x + ba.x),
                                    frelu(a4[1] + bs.y) + frelu(ag.y + ba.y));
                }
                if (r1 < M) {
                    float2 ag = *reinterpret_cast<const float2*>(agg + (size_t)r1 * 256 + col);
                    *reinterpret_cast<float2*>(C + (size_t)r1 * 256 + col) =
                        make_float2(frelu(a4[2] + bs.x) + frelu(ag.x + ba.x),
                                    frelu(a4[3] + bs.y) + frelu(ag.y + ba.y));
                }
            } else {
                float2 bs = *reinterpret_cast<const float2*>(bias + col);
                if (r0 < M)
                    *reinterpret_cast<float2*>(C + (size_t)r0 * 256 + col) =
                        make_float2(frelu(a4[0] + bs.x), frelu(a4[1] + bs.y));
                if (r1 < M)
                    *reinterpret_cast<float2*>(C + (size_t)r1 * 256 + col) =
                        make_float2(frelu(a4[2] + bs.x), frelu(a4[3] + bs.y));
            }
        }
    }
}

// ---------------------------------------------------------------------------
// CSR build, both branches in one launch
// ---------------------------------------------------------------------------
__global__ void hist_kernel(const int* __restrict__ dst1, const int* __restrict__ dst2,
                            int* __restrict__ deg /* [2][N] */)
{
    int idx = blockIdx.x * blockDim.x + threadIdx.x;
    if (idx < 2 * N_EDGES) {
        int br = idx >= N_EDGES;
        int e  = idx - br * N_EDGES;
        int d  = br ? dst2[e] : dst1[e];
        atomicAdd(&deg[br * N_NODES + d], 1);
    }
}

__global__ __launch_bounds__(1024)
void scan_kernel(const int* __restrict__ degAll, int* __restrict__ rowstartAll,
                 int* __restrict__ cursorAll)
{
    const int br = blockIdx.x;
    const int* deg      = degAll      + br * N_NODES;
    int*       rowstart = rowstartAll + br * (N_NODES + 1);
    int*       cursor   = cursorAll   + br * N_NODES;
    __shared__ int warpsums[32];
    const int T = 1024;
    const int CH = (N_NODES + T - 1) / T;
    int t = threadIdx.x;
    int base = t * CH;
    int s = 0;
    for (int i = 0; i < CH; i++) {
        int idx = base + i;
        if (idx < N_NODES) s += deg[idx];
    }
    int lane = t & 31, w = t >> 5;
    int v = s;
    #pragma unroll
    for (int o = 1; o < 32; o <<= 1) {
        int n = __shfl_up_sync(0xFFFFFFFFu, v, o);
        if (lane >= o) v += n;
    }
    if (lane == 31) warpsums[w] = v;
    __syncthreads();
    if (w == 0) {
        int x = warpsums[lane];
        #pragma unroll
        for (int o = 1; o < 32; o <<= 1) {
            int n = __shfl_up_sync(0xFFFFFFFFu, x, o);
            if (lane >= o) x += n;
        }
        warpsums[lane] = x;
    }
    __syncthreads();
    int excl = v - s + (w > 0 ? warpsums[w - 1] : 0);
    int run = excl;
    for (int i = 0; i < CH; i++) {
        int idx = base + i;
        if (idx < N_NODES) {
            rowstart[idx] = run;
            cursor[idx]   = run;
            run += deg[idx];
        }
    }
    if (t == T - 1) rowstart[N_NODES] = run;
}

__global__ void fill_kernel(const int* __restrict__ src1, const int* __restrict__ dst1,
                            const int* __restrict__ src2, const int* __restrict__ dst2,
                            int* __restrict__ cursorAll, int* __restrict__ csrAll)
{
    int idx = blockIdx.x * blockDim.x + threadIdx.x;
    if (idx < 2 * N_EDGES) {
        int br = idx >= N_EDGES;
        int e  = idx - br * N_EDGES;
        int d  = br ? dst2[e] : dst1[e];
        int s  = br ? src2[e] : src1[e];
        int p  = atomicAdd(&cursorAll[br * N_NODES + d], 1);
        csrAll[br * N_EDGES + p] = s;
    }
}

// ---------------------------------------------------------------------------
// Warp-per-node gather, both branches: agg[n] = sum over in-edges of hW[src]
// ---------------------------------------------------------------------------
__global__ __launch_bounds__(256)
void gather_kernel(const float* __restrict__ hWAll,   // [2][N][256]
                   const int* __restrict__ rowstartAll,
                   const int* __restrict__ csrAll,
                   float* __restrict__ aggAll)
{
    int gn = (blockIdx.x * blockDim.x + threadIdx.x) >> 5;
    int lane = threadIdx.x & 31;
    if (gn >= 2 * N_NODES) return;
    int br   = gn >= N_NODES;
    int node = gn - br * N_NODES;
    const int*   rowstart = rowstartAll + br * (N_NODES + 1);
    const int*   csr      = csrAll + (size_t)br * N_EDGES;
    const float* hW       = hWAll  + (size_t)br * N_NODES * DFEAT;

    int beg = rowstart[node], end = rowstart[node + 1];
    float4 a0 = make_float4(0.f, 0.f, 0.f, 0.f);
    float4 a1 = make_float4(0.f, 0.f, 0.f, 0.f);
    float4 b0 = make_float4(0.f, 0.f, 0.f, 0.f);
    float4 b1 = make_float4(0.f, 0.f, 0.f, 0.f);
    int e = beg;
    for (; e + 1 < end; e += 2) {
        const float4* r0 = reinterpret_cast<const float4*>(hW + (size_t)csr[e]     * DFEAT);
        const float4* r1 = reinterpret_cast<const float4*>(hW + (size_t)csr[e + 1] * DFEAT);
        float4 u0 = r0[lane], u1 = r0[lane + 32];
        float4 v0 = r1[lane], v1 = r1[lane + 32];
        a0.x += u0.x; a0.y += u0.y; a0.z += u0.z; a0.w += u0.w;
        a1.x += u1.x; a1.y += u1.y; a1.z += u1.z; a1.w += u1.w;
        b0.x += v0.x; b0.y += v0.y; b0.z += v0.z; b0.w += v0.w;
        b1.x += v1.x; b1.y += v1.y; b1.z += v1.z; b1.w += v1.w;
    }
    if (e < end) {
        const float4* r0 = reinterpret_cast<const float4*>(hW + (size_t)csr[e] * DFEAT);
        float4 u0 = r0[lane], u1 = r0[lane + 32];
        a0.x += u0.x; a0.y += u0.y; a0.z += u0.z; a0.w += u0.w;
        a1.x += u1.x; a1.y += u1.y; a1.z += u1.z; a1.w += u1.w;
    }
    a0.x += b0.x; a0.y += b0.y; a0.z += b0.z; a0.w += b0.w;
    a1.x += b1.x; a1.y += b1.y; a1.z += b1.z; a1.w += b1.w;
    float4* out = reinterpret_cast<float4*>(aggAll + ((size_t)br * N_NODES + node) * DFEAT);
    out[lane]      = a0;
    out[lane + 32] = a1;
}

// ---------------------------------------------------------------------------
// Segment sum (sorted gid, binary search), both branches; produces counts.
// ---------------------------------------------------------------------------
__global__ __launch_bounds__(256)
void segsum_kernel(const float* __restrict__ h2All, const int* __restrict__ gid1,
                   const int* __restrict__ gid2,
                   float* __restrict__ TAll, int* __restrict__ countsAll)
{
    __shared__ int sb, se;
    int bidx = blockIdx.x;
    int br   = bidx >> 9;          // 0..1
    int g    = bidx & 511;
    const int* gid = br ? gid2 : gid1;
    const float* h2 = h2All + (size_t)br * N_NODES * DFEAT;
    if (threadIdx.x == 0) {
        int lo = 0, hi = N_NODES;
        while (lo < hi) { int m = (lo + hi) >> 1; if (gid[m] < g) lo = m + 1; else hi = m; }
        sb = lo;
        lo = sb; hi = N_NODES;
        while (lo < hi) { int m = (lo + hi) >> 1; if (gid[m] < g + 1) lo = m + 1; else hi = m; }
        se = lo;
        countsAll[br * N_GRAPHS + g] = se - sb;
    }
    __syncthreads();
    int beg = sb, end = se, c = threadIdx.x;
    float s = 0.f;
    for (int r = beg; r < end; r++)
        s += h2[(size_t)r * DFEAT + c];
    TAll[((size_t)br * N_GRAPHS + g) * DFEAT + c] = s;
}

// ---------------------------------------------------------------------------
// Fused readout + predictor:
// out[g] = sum_j [ (T1[g]@Ro1 + c1*rbo1 + T2[g]@Ro2 + c2*rbo2)_j * Wp[j] ] + bp
// ---------------------------------------------------------------------------
__global__ __launch_bounds__(256)
void readout_final(const float* __restrict__ TAll, const int* __restrict__ countsAll,
                   const float* __restrict__ Ro1, const float* __restrict__ rbo1,
                   const float* __restrict__ Ro2, const float* __restrict__ rbo2,
                   const float* __restrict__ Wp, const float* __restrict__ bp,
                   float* __restrict__ out)
{
    __shared__ float ts1[DFEAT], ts2[DFEAT];
    __shared__ float red[256];
    int g = blockIdx.x;
    int t = threadIdx.x;
    ts1[t] = TAll[(size_t)g * DFEAT + t];
    ts2[t] = TAll[((size_t)N_GRAPHS + g) * DFEAT + t];
    __syncthreads();
    float c1 = (float)countsAll[g];
    float c2 = (float)countsAll[N_GRAPHS + g];
    float partial = 0.f;
    if (t < G_FEAT) {
        float s = c1 * rbo1[t] + c2 * rbo2[t];
        #pragma unroll 8
        for (int k = 0; k < DFEAT; k++)
            s += ts1[k] * Ro1[(size_t)k * G_FEAT + t]
               + ts2[k] * Ro2[(size_t)k * G_FEAT + t];
        partial = s * Wp[t];
    }
    red[t] = partial;
    __syncthreads();
    #pragma unroll
    for (int st = 128; st > 0; st >>= 1) {
        if (t < st) red[t] += red[t + st];
        __syncthreads();
    }
    if (t == 0) out[g] = red[0] + bp[0];
}

// ---------------------------------------------------------------------------
extern "C" void kernel_launch(void* const* d_in, const int* in_sizes, int n_in,
                              void* d_out, int out_size)
{
    const float* nf1 = (const float*)d_in[0];
    const float* nf2 = (const float*)d_in[2];
    const int* src1 = (const int*)d_in[4];
    const int* dst1 = (const int*)d_in[5];
    const int* gid1 = (const int*)d_in[6];
    const int* src2 = (const int*)d_in[7];
    const int* dst2 = (const int*)d_in[8];
    const int* gid2 = (const int*)d_in[9];
    const float* W1  = (const float*)d_in[10]; const float* b1  = (const float*)d_in[11];
    const float* Wr1 = (const float*)d_in[12]; const float* br1 = (const float*)d_in[13];
    const float* W2  = (const float*)d_in[14]; const float* b2  = (const float*)d_in[15];
    const float* Wr2 = (const float*)d_in[16]; const float* br2 = (const float*)d_in[17];
    const float* Ri1 = (const float*)d_in[18]; const float* rbi1 = (const float*)d_in[19];
    const float* Ro1 = (const float*)d_in[20]; const float* rbo1 = (const float*)d_in[21];
    const float* Ri2 = (const float*)d_in[22]; const float* rbi2 = (const float*)d_in[23];
    const float* Ro2 = (const float*)d_in[24]; const float* rbo2 = (const float*)d_in[25];
    const float* Wp  = (const float*)d_in[26]; const float* bp   = (const float*)d_in[27];

    float *hW, *agg, *h1, *T;
    int *counts, *deg, *rowstart, *cursor, *csr_src;
    cudaGetSymbolAddress((void**)&hW,       g_hW);
    cudaGetSymbolAddress((void**)&agg,      g_agg);
    cudaGetSymbolAddress((void**)&h1,       g_h1);
    cudaGetSymbolAddress((void**)&T,        g_T);
    cudaGetSymbolAddress((void**)&counts,   g_counts);
    cudaGetSymbolAddress((void**)&deg,      g_deg);
    cudaGetSymbolAddress((void**)&rowstart, g_rowstart);
    cudaGetSymbolAddress((void**)&cursor,   g_cursor);
    cudaGetSymbolAddress((void**)&csr_src,  g_csr_src);

    cudaFuncSetAttribute(gemm_mma<0>, cudaFuncAttributeMaxDynamicSharedMemorySize, SMEM_BYTES);
    cudaFuncSetAttribute(gemm_mma<1>, cudaFuncAttributeMaxDynamicSharedMemorySize, SMEM_BYTES);
    cudaFuncSetAttribute(gemm_mma<2>, cudaFuncAttributeMaxDynamicSharedMemorySize, SMEM_BYTES);

    float* hW1  = hW;            float* hW2  = hW  + (size_t)N_NODES * DFEAT;
    float* agg1 = agg;           float* agg2 = agg + (size_t)N_NODES * DFEAT;
    float* h11  = h1;            float* h12  = h1  + (size_t)N_NODES * DFEAT;

    dim3 gemm_grid((N_NODES + 127) / 128, 2, 2);   // 391 x 2 x 2
    int eb2 = (2 * N_EDGES + 255) / 256;

    cudaMemsetAsync(deg, 0, 2 * N_NODES * sizeof(int));
    hist_kernel<<<eb2, 256>>>(dst1, dst2, deg);
    scan_kernel<<<2, 1024>>>(deg, rowstart, cursor);
    fill_kernel<<<eb2, 256>>>(src1, dst1, src2, dst2, cursor, csr_src);

    // hW = h @ W (both branches)
    gemm_mma<0><<<gemm_grid, 256, SMEM_BYTES>>>(nf1, nf2, W1, W2,
                                                nullptr, nullptr, nullptr, nullptr,
                                                nullptr, nullptr, hW1, hW2, N_NODES);
    // agg = gather-sum of hW rows (both branches)
    gather_kernel<<<(2 * N_NODES * 32 + 255) / 256, 256>>>(hW, rowstart, csr_src, agg);
    // h1 = relu(agg + b) + relu(h @ Wr + br)
    gemm_mma<1><<<gemm_grid, 256, SMEM_BYTES>>>(nf1, nf2, Wr1, Wr2,
                                                br1, br2, agg1, agg2, b1, b2,
                                                h11, h12, N_NODES);
    // h2 = relu(h1 @ Ri + rbi)   (reuse hW buffers)
    gemm_mma<2><<<gemm_grid, 256, SMEM_BYTES>>>(h11, h12, Ri1, Ri2,
                                                rbi1, rbi2, nullptr, nullptr,
                                                nullptr, nullptr, hW1, hW2, N_NODES);
    // T[g] = segsum of h2 rows; counts (both branches)
    segsum_kernel<<<2 * N_GRAPHS, 256>>>(hW, gid1, gid2, T, counts);
    // fused readout + predictor
    readout_final<<<N_GRAPHS, 256>>>(T, counts, Ro1, rbo1, Ro2, rbo2, Wp, bp,
                                     (float*)d_out);
}

// round 6
// speedup vs baseline: 2.7409x; 1.1599x over previous
#include <cuda_runtime.h>
#include <cuda_bf16.h>
#include <cstdint>
#include <cstddef>

// ---------------------------------------------------------------------------
// mulGCN: two-branch GCN forward, split-bf16 mma.sync GEMMs with pre-split
// operands + cp.async double-buffered pipeline.
//   conv_nf / conv_W: fp32 -> (hi,lo) bf16 pair arrays (once per call)
//   CSR build by dst (hist -> scan -> fill)          [both branches]
//   hW  = h @ W                                      (GEMM MODE 0, fp32 out)
//   agg[n] = sum_{e: dst=n} hW[src[e]]               (warp-per-node gather)
//   h1  = relu(agg+b) + relu(h@Wr+br)                (GEMM MODE 1, split out)
//   h2  = relu(h1 @ Ri + rbi)                        (GEMM MODE 2, fp32 out)
//   T[g] = segsum of h2 rows (gid sorted, no atomics)
//   out[g] = (T1@Ro1 + c1*rbo1 + T2@Ro2 + c2*rbo2) . Wp + bp
// Split-bf16: x = hi(trunc bf16, exact) + lo(bf16 rn of remainder);
// A@B ~= AhiBhi + AhiBlo + AloBhi, fp32 accum -> ~2e-5 rel error.
// ---------------------------------------------------------------------------

#define N_NODES   50000
#define N_EDGES   800000
#define DFEAT     256
#define G_FEAT    200
#define N_GRAPHS  512

#define NW   (N_NODES * 128)          // words per branch for split arrays

__device__ float    g_hW  [2][(size_t)N_NODES * DFEAT];   // reused as h2
__device__ float    g_agg [2][(size_t)N_NODES * DFEAT];
__device__ uint32_t g_nfH [2][(size_t)NW];
__device__ uint32_t g_nfL [2][(size_t)NW];
__device__ uint32_t g_h1H [2][(size_t)NW];
__device__ uint32_t g_h1L [2][(size_t)NW];
__device__ uint32_t g_WH  [6][128 * 256];
__device__ uint32_t g_WL  [6][128 * 256];
__device__ float    g_T   [2][N_GRAPHS * DFEAT];
__device__ int      g_counts  [2][N_GRAPHS];
__device__ int      g_deg     [2][N_NODES];
__device__ int      g_rowstart[2][N_NODES + 1];
__device__ int      g_cursor  [2][N_NODES];
__device__ int      g_csr_src [2][N_EDGES];

__device__ __forceinline__ float frelu(float x) { return x > 0.f ? x : 0.f; }

// ------------------------- mma / pack helpers ------------------------------
__device__ __forceinline__ void mma16816(float* c, const uint32_t* a,
                                         uint32_t b0, uint32_t b1) {
    asm volatile(
        "mma.sync.aligned.m16n8k16.row.col.f32.bf16.bf16.f32 "
        "{%0,%1,%2,%3}, {%4,%5,%6,%7}, {%8,%9}, {%0,%1,%2,%3};\n"
        : "+f"(c[0]), "+f"(c[1]), "+f"(c[2]), "+f"(c[3])
        : "r"(a[0]), "r"(a[1]), "r"(a[2]), "r"(a[3]), "r"(b0), "r"(b1));
}

__device__ __forceinline__ uint32_t pack_hi(float x, float y) {
    return __byte_perm(__float_as_uint(x), __float_as_uint(y), 0x7632);
}
__device__ __forceinline__ uint32_t pack_lo(float x, float y) {
    float hx = __uint_as_float(__float_as_uint(x) & 0xFFFF0000u);
    float hy = __uint_as_float(__float_as_uint(y) & 0xFFFF0000u);
    __nv_bfloat162 t;
    t.x = __float2bfloat16(x - hx);
    t.y = __float2bfloat16(y - hy);
    return *reinterpret_cast<uint32_t*>(&t);
}

// ------------------------- cp.async helpers --------------------------------
__device__ __forceinline__ void cp16(uint32_t dst, const void* src) {
    asm volatile("cp.async.cg.shared.global [%0], [%1], 16;"
                 :: "r"(dst), "l"(src));
}
__device__ __forceinline__ void cp16z(uint32_t dst, const void* src, bool ok) {
    int b = ok ? 16 : 0;
    asm volatile("cp.async.cg.shared.global [%0], [%1], 16, %2;"
                 :: "r"(dst), "l"(src), "r"(b));
}
#define CP_COMMIT()  asm volatile("cp.async.commit_group;" ::: "memory")
#define CP_WAIT1()   asm volatile("cp.async.wait_group 1;" ::: "memory")
#define CP_WAIT0()   asm volatile("cp.async.wait_group 0;" ::: "memory")

// SMEM words per buffer: AH[128][20] AL[128][20] BH[16][136] BL[16][136]
static constexpr int W_AH = 0, W_AL = 2560, W_BH = 5120, W_BL = 7296;
static constexpr int WBUF = 9472;
static constexpr int SMEM_BYTES = 2 * WBUF * 4;        // 75776

// A fill: 128 rows x 16 words (hi) + 16 words (lo) per chunk, 1024 cp16
__device__ __forceinline__ void cpA(uint32_t sb, const uint32_t* __restrict__ AH,
                                    const uint32_t* __restrict__ AL,
                                    int M, int rowBase, int c, int tid)
{
    #pragma unroll
    for (int t = 0; t < 4; t++) {
        int idx = tid + t * 256;          // 0..1023
        int r   = idx >> 3;
        int seg = idx & 7;                // 0..7 (0-3 hi, 4-7 lo)
        int row = rowBase + r;
        bool ok = row < M;
        int rowc = ok ? row : 0;
        int s4 = (seg & 3) * 4;
        const uint32_t* src = (seg < 4 ? AH : AL) + (size_t)rowc * 128 + c * 16 + s4;
        uint32_t dst = sb + ((seg < 4 ? W_AH : W_AL) + r * 20 + s4) * 4;
        cp16z(dst, src, ok);
    }
}

// B fill: 16 kp-rows x 128 words x {hi,lo} per chunk, 1024 cp16
__device__ __forceinline__ void cpB(uint32_t sb, const uint32_t* __restrict__ WH,
                                    const uint32_t* __restrict__ WL,
                                    int colBase, int c, int tid)
{
    #pragma unroll
    for (int t = 0; t < 4; t++) {
        int idx  = tid + t * 256;         // 0..1023
        int kp   = idx >> 6;              // 0..15
        int rest = idx & 63;
        int arr  = rest >> 5;             // 0 hi, 1 lo
        int s4   = (rest & 31) * 4;
        const uint32_t* src = (arr ? WL : WH) + (size_t)(c * 16 + kp) * 256 + colBase + s4;
        uint32_t dst = sb + ((arr ? W_BL : W_BH) + kp * 136 + s4) * 4;
        cp16(dst, src);
    }
}

// ---------------------------------------------------------------------------
// mma GEMM: 256 threads, 8 warps (4m x 2n), warp tile 32x64, both branches.
// MODE 0: C fp32 = acc
// MODE 1: CH/CL split = pack(relu(acc+bias)+relu(agg+bagg))
// MODE 2: C fp32 = relu(acc+bias)
// ---------------------------------------------------------------------------
template<int MODE>
__global__ __launch_bounds__(256, 2)
void gemm_mma(const uint32_t* __restrict__ AH1, const uint32_t* __restrict__ AL1,
              const uint32_t* __restrict__ AH2, const uint32_t* __restrict__ AL2,
              const uint32_t* __restrict__ WH1, const uint32_t* __restrict__ WL1,
              const uint32_t* __restrict__ WH2, const uint32_t* __restrict__ WL2,
              const float* __restrict__ bias1, const float* __restrict__ bias2,
              const float* __restrict__ agg1,  const float* __restrict__ agg2,
              const float* __restrict__ bagg1, const float* __restrict__ bagg2,
              float* __restrict__ C1, float* __restrict__ C2,
              uint32_t* __restrict__ CH1, uint32_t* __restrict__ CL1,
              uint32_t* __restrict__ CH2, uint32_t* __restrict__ CL2,
              int M)
{
    extern __shared__ uint32_t sm[];
    const int br = blockIdx.z;
    const uint32_t* AH  = br ? AH2 : AH1;
    const uint32_t* AL  = br ? AL2 : AL1;
    const uint32_t* WH  = br ? WH2 : WH1;
    const uint32_t* WL  = br ? WL2 : WL1;
    const float* bias = br ? bias2 : bias1;
    const float* agg  = br ? agg2 : agg1;
    const float* bagg = br ? bagg2 : bagg1;
    float*    C  = br ? C2 : C1;
    uint32_t* CH = br ? CH2 : CH1;
    uint32_t* CL = br ? CL2 : CL1;

    const int tid  = threadIdx.x;
    const int lane = tid & 31;
    const int wid  = tid >> 5;
    const int wm   = wid & 3;
    const int wn   = wid >> 2;
    const int gid  = lane >> 2;
    const int tig  = lane & 3;
    const int rowBase = blockIdx.x * 128;
    const int colBase = blockIdx.y * 128;

    uint32_t sbase;
    {
        uint64_t a = __cvta_generic_to_shared(sm);
        sbase = (uint32_t)a;
    }

    float acc[2][8][4];
    #pragma unroll
    for (int mt = 0; mt < 2; mt++)
        #pragma unroll
        for (int nt = 0; nt < 8; nt++)
            #pragma unroll
            for (int q = 0; q < 4; q++) acc[mt][nt][q] = 0.f;

    // prologue: chunk 0 -> buf 0
    cpA(sbase, AH, AL, M, rowBase, 0, tid);
    cpB(sbase, WH, WL, colBase, 0, tid);
    CP_COMMIT();

    #pragma unroll
    for (int c = 0; c < 8; c++) {
        if (c < 7) {
            uint32_t nb = sbase + ((c + 1) & 1) * WBUF * 4;
            cpA(nb, AH, AL, M, rowBase, c + 1, tid);
            cpB(nb, WH, WL, colBase, c + 1, tid);
            CP_COMMIT();
            CP_WAIT1();
        } else {
            CP_WAIT0();
        }
        __syncthreads();

        const uint32_t* buf = sm + (c & 1) * WBUF;
        const uint32_t* sAH = buf + W_AH;
        const uint32_t* sAL = buf + W_AL;
        const uint32_t* sBH = buf + W_BH;
        const uint32_t* sBL = buf + W_BL;

        #pragma unroll
        for (int ks = 0; ks < 2; ks++) {
            uint32_t aH[2][4], aL[2][4];
            #pragma unroll
            for (int mt = 0; mt < 2; mt++) {
                int off = (wm * 32 + mt * 16 + gid) * 20 + ks * 8 + tig;
                aH[mt][0] = sAH[off];       aH[mt][1] = sAH[off + 160];
                aH[mt][2] = sAH[off + 4];   aH[mt][3] = sAH[off + 164];
                aL[mt][0] = sAL[off];       aL[mt][1] = sAL[off + 160];
                aL[mt][2] = sAL[off + 4];   aL[mt][3] = sAL[off + 164];
            }
            #pragma unroll
            for (int nt = 0; nt < 8; nt++) {
                int bi = (ks * 8 + tig) * 136 + wn * 64 + nt * 8 + gid;
                uint32_t bh0 = sBH[bi], bh1 = sBH[bi + 544];
                uint32_t bl0 = sBL[bi], bl1 = sBL[bi + 544];
                #pragma unroll
                for (int mt = 0; mt < 2; mt++) {
                    mma16816(acc[mt][nt], aH[mt], bh0, bh1);
                    mma16816(acc[mt][nt], aH[mt], bl0, bl1);
                    mma16816(acc[mt][nt], aL[mt], bh0, bh1);
                }
            }
        }
        __syncthreads();
    }

    // ------------------------------ epilogue -------------------------------
    #pragma unroll
    for (int mt = 0; mt < 2; mt++) {
        #pragma unroll
        for (int nt = 0; nt < 8; nt++) {
            int r0  = rowBase + wm * 32 + mt * 16 + gid;
            int r1  = r0 + 8;
            int col = colBase + wn * 64 + nt * 8 + 2 * tig;
            float* a4 = acc[mt][nt];
            if (MODE == 0) {
                if (r0 < M)
                    *reinterpret_cast<float2*>(C + (size_t)r0 * 256 + col) =
                        make_float2(a4[0], a4[1]);
                if (r1 < M)
                    *reinterpret_cast<float2*>(C + (size_t)r1 * 256 + col) =
                        make_float2(a4[2], a4[3]);
            } else if (MODE == 1) {
                float2 bs = *reinterpret_cast<const float2*>(bias + col);
                float2 ba = *reinterpret_cast<const float2*>(bagg + col);
                if (r0 < M) {
                    float2 ag = *reinterpret_cast<const float2*>(agg + (size_t)r0 * 256 + col);
                    float v0 = frelu(a4[0] + bs.x) + frelu(ag.x + ba.x);
                    float v1 = frelu(a4[1] + bs.y) + frelu(ag.y + ba.y);
                    CH[(size_t)r0 * 128 + (col >> 1)] = pack_hi(v0, v1);
                    CL[(size_t)r0 * 128 + (col >> 1)] = pack_lo(v0, v1);
                }
                if (r1 < M) {
                    float2 ag = *reinterpret_cast<const float2*>(agg + (size_t)r1 * 256 + col);
                    float v0 = frelu(a4[2] + bs.x) + frelu(ag.x + ba.x);
                    float v1 = frelu(a4[3] + bs.y) + frelu(ag.y + ba.y);
                    CH[(size_t)r1 * 128 + (col >> 1)] = pack_hi(v0, v1);
                    CL[(size_t)r1 * 128 + (col >> 1)] = pack_lo(v0, v1);
                }
            } else {
                float2 bs = *reinterpret_cast<const float2*>(bias + col);
                if (r0 < M)
                    *reinterpret_cast<float2*>(C + (size_t)r0 * 256 + col) =
                        make_float2(frelu(a4[0] + bs.x), frelu(a4[1] + bs.y));
                if (r1 < M)
                    *reinterpret_cast<float2*>(C + (size_t)r1 * 256 + col) =
                        make_float2(frelu(a4[2] + bs.x), frelu(a4[3] + bs.y));
            }
        }
    }
}

// ---------------------------------------------------------------------------
// Conversion kernels
// ---------------------------------------------------------------------------
__global__ __launch_bounds__(256)
void conv_nf(const float* __restrict__ n1, const float* __restrict__ n2,
             uint32_t* __restrict__ H, uint32_t* __restrict__ L)   // [2][NW]
{
    size_t idx = (size_t)blockIdx.x * blockDim.x + threadIdx.x;
    if (idx >= 2 * (size_t)NW) return;
    int br = idx >= (size_t)NW;
    size_t w = idx - (size_t)br * NW;
    const float* nf = br ? n2 : n1;
    float2 v = *reinterpret_cast<const float2*>(nf + w * 2);
    H[idx] = pack_hi(v.x, v.y);
    L[idx] = pack_lo(v.x, v.y);
}

__global__ __launch_bounds__(256)
void conv_W(const float* __restrict__ m0, const float* __restrict__ m1,
            const float* __restrict__ m2, const float* __restrict__ m3,
            const float* __restrict__ m4, const float* __restrict__ m5,
            uint32_t* __restrict__ WH, uint32_t* __restrict__ WL)  // [6][128*256]
{
    int idx = blockIdx.x * blockDim.x + threadIdx.x;
    if (idx >= 6 * 128 * 256) return;
    int m    = idx >> 15;
    int rest = idx & 32767;
    int k2   = rest >> 8;
    int n    = rest & 255;
    const float* Wm = (m == 0) ? m0 : (m == 1) ? m1 : (m == 2) ? m2
                    : (m == 3) ? m3 : (m == 4) ? m4 : m5;
    float a = Wm[(size_t)(2 * k2) * 256 + n];
    float b = Wm[(size_t)(2 * k2 + 1) * 256 + n];
    WH[idx] = pack_hi(a, b);
    WL[idx] = pack_lo(a, b);
}

// ---------------------------------------------------------------------------
// CSR build, both branches
// ---------------------------------------------------------------------------
__global__ void hist_kernel(const int* __restrict__ dst1, const int* __restrict__ dst2,
                            int* __restrict__ deg)
{
    int idx = blockIdx.x * blockDim.x + threadIdx.x;
    if (idx < 2 * N_EDGES) {
        int br = idx >= N_EDGES;
        int e  = idx - br * N_EDGES;
        int d  = br ? dst2[e] : dst1[e];
        atomicAdd(&deg[br * N_NODES + d], 1);
    }
}

__global__ __launch_bounds__(1024)
void scan_kernel(const int* __restrict__ degAll, int* __restrict__ rowstartAll,
                 int* __restrict__ cursorAll)
{
    const int br = blockIdx.x;
    const int* deg      = degAll      + br * N_NODES;
    int*       rowstart = rowstartAll + br * (N_NODES + 1);
    int*       cursor   = cursorAll   + br * N_NODES;
    __shared__ int warpsums[32];
    const int T = 1024;
    const int CH = (N_NODES + T - 1) / T;
    int t = threadIdx.x;
    int base = t * CH;
    int s = 0;
    for (int i = 0; i < CH; i++) {
        int idx = base + i;
        if (idx < N_NODES) s += deg[idx];
    }
    int lane = t & 31, w = t >> 5;
    int v = s;
    #pragma unroll
    for (int o = 1; o < 32; o <<= 1) {
        int n = __shfl_up_sync(0xFFFFFFFFu, v, o);
        if (lane >= o) v += n;
    }
    if (lane == 31) warpsums[w] = v;
    __syncthreads();
    if (w == 0) {
        int x = warpsums[lane];
        #pragma unroll
        for (int o = 1; o < 32; o <<= 1) {
            int n = __shfl_up_sync(0xFFFFFFFFu, x, o);
            if (lane >= o) x += n;
        }
        warpsums[lane] = x;
    }
    __syncthreads();
    int excl = v - s + (w > 0 ? warpsums[w - 1] : 0);
    int run = excl;
    for (int i = 0; i < CH; i++) {
        int idx = base + i;
        if (idx < N_NODES) {
            rowstart[idx] = run;
            cursor[idx]   = run;
            run += deg[idx];
        }
    }
    if (t == T - 1) rowstart[N_NODES] = run;
}

__global__ void fill_kernel(const int* __restrict__ src1, const int* __restrict__ dst1,
                            const int* __restrict__ src2, const int* __restrict__ dst2,
                            int* __restrict__ cursorAll, int* __restrict__ csrAll)
{
    int idx = blockIdx.x * blockDim.x + threadIdx.x;
    if (idx < 2 * N_EDGES) {
        int br = idx >= N_EDGES;
        int e  = idx - br * N_EDGES;
        int d  = br ? dst2[e] : dst1[e];
        int s  = br ? src2[e] : src1[e];
        int p  = atomicAdd(&cursorAll[br * N_NODES + d], 1);
        csrAll[br * N_EDGES + p] = s;
    }
}

// ---------------------------------------------------------------------------
// Warp-per-node gather, both branches
// ---------------------------------------------------------------------------
__global__ __launch_bounds__(256)
void gather_kernel(const float* __restrict__ hWAll,
                   const int* __restrict__ rowstartAll,
                   const int* __restrict__ csrAll,
                   float* __restrict__ aggAll)
{
    int gn = (blockIdx.x * blockDim.x + threadIdx.x) >> 5;
    int lane = threadIdx.x & 31;
    if (gn >= 2 * N_NODES) return;
    int br   = gn >= N_NODES;
    int node = gn - br * N_NODES;
    const int*   rowstart = rowstartAll + br * (N_NODES + 1);
    const int*   csr      = csrAll + (size_t)br * N_EDGES;
    const float* hW       = hWAll  + (size_t)br * N_NODES * DFEAT;

    int beg = rowstart[node], end = rowstart[node + 1];
    float4 a0 = make_float4(0.f, 0.f, 0.f, 0.f);
    float4 a1 = make_float4(0.f, 0.f, 0.f, 0.f);
    float4 b0 = make_float4(0.f, 0.f, 0.f, 0.f);
    float4 b1 = make_float4(0.f, 0.f, 0.f, 0.f);
    int e = beg;
    for (; e + 1 < end; e += 2) {
        const float4* r0 = reinterpret_cast<const float4*>(hW + (size_t)csr[e]     * DFEAT);
        const float4* r1 = reinterpret_cast<const float4*>(hW + (size_t)csr[e + 1] * DFEAT);
        float4 u0 = r0[lane], u1 = r0[lane + 32];
        float4 v0 = r1[lane], v1 = r1[lane + 32];
        a0.x += u0.x; a0.y += u0.y; a0.z += u0.z; a0.w += u0.w;
        a1.x += u1.x; a1.y += u1.y; a1.z += u1.z; a1.w += u1.w;
        b0.x += v0.x; b0.y += v0.y; b0.z += v0.z; b0.w += v0.w;
        b1.x += v1.x; b1.y += v1.y; b1.z += v1.z; b1.w += v1.w;
    }
    if (e < end) {
        const float4* r0 = reinterpret_cast<const float4*>(hW + (size_t)csr[e] * DFEAT);
        float4 u0 = r0[lane], u1 = r0[lane + 32];
        a0.x += u0.x; a0.y += u0.y; a0.z += u0.z; a0.w += u0.w;
        a1.x += u1.x; a1.y += u1.y; a1.z += u1.z; a1.w += u1.w;
    }
    a0.x += b0.x; a0.y += b0.y; a0.z += b0.z; a0.w += b0.w;
    a1.x += b1.x; a1.y += b1.y; a1.z += b1.z; a1.w += b1.w;
    float4* out = reinterpret_cast<float4*>(aggAll + ((size_t)br * N_NODES + node) * DFEAT);
    out[lane]      = a0;
    out[lane + 32] = a1;
}

// ---------------------------------------------------------------------------
// Segment sum (sorted gid), both branches
// ---------------------------------------------------------------------------
__global__ __launch_bounds__(256)
void segsum_kernel(const float* __restrict__ h2All, const int* __restrict__ gid1,
                   const int* __restrict__ gid2,
                   float* __restrict__ TAll, int* __restrict__ countsAll)
{
    __shared__ int sb, se;
    int bidx = blockIdx.x;
    int br   = bidx >> 9;
    int g    = bidx & 511;
    const int* gid = br ? gid2 : gid1;
    const float* h2 = h2All + (size_t)br * N_NODES * DFEAT;
    if (threadIdx.x == 0) {
        int lo = 0, hi = N_NODES;
        while (lo < hi) { int m = (lo + hi) >> 1; if (gid[m] < g) lo = m + 1; else hi = m; }
        sb = lo;
        lo = sb; hi = N_NODES;
        while (lo < hi) { int m = (lo + hi) >> 1; if (gid[m] < g + 1) lo = m + 1; else hi = m; }
        se = lo;
        countsAll[br * N_GRAPHS + g] = se - sb;
    }
    __syncthreads();
    int beg = sb, end = se, c = threadIdx.x;
    float s = 0.f;
    for (int r = beg; r < end; r++)
        s += h2[(size_t)r * DFEAT + c];
    TAll[((size_t)br * N_GRAPHS + g) * DFEAT + c] = s;
}

// ---------------------------------------------------------------------------
// Fused readout + predictor
// ---------------------------------------------------------------------------
__global__ __launch_bounds__(256)
void readout_final(const float* __restrict__ TAll, const int* __restrict__ countsAll,
                   const float* __restrict__ Ro1, const float* __restrict__ rbo1,
                   const float* __restrict__ Ro2, const float* __restrict__ rbo2,
                   const float* __restrict__ Wp, const float* __restrict__ bp,
                   float* __restrict__ out)
{
    __shared__ float ts1[DFEAT], ts2[DFEAT];
    __shared__ float red[256];
    int g = blockIdx.x;
    int t = threadIdx.x;
    ts1[t] = TAll[(size_t)g * DFEAT + t];
    ts2[t] = TAll[((size_t)N_GRAPHS + g) * DFEAT + t];
    __syncthreads();
    float c1 = (float)countsAll[g];
    float c2 = (float)countsAll[N_GRAPHS + g];
    float partial = 0.f;
    if (t < G_FEAT) {
        float s = c1 * rbo1[t] + c2 * rbo2[t];
        #pragma unroll 8
        for (int k = 0; k < DFEAT; k++)
            s += ts1[k] * Ro1[(size_t)k * G_FEAT + t]
               + ts2[k] * Ro2[(size_t)k * G_FEAT + t];
        partial = s * Wp[t];
    }
    red[t] = partial;
    __syncthreads();
    #pragma unroll
    for (int st = 128; st > 0; st >>= 1) {
        if (t < st) red[t] += red[t + st];
        __syncthreads();
    }
    if (t == 0) out[g] = red[0] + bp[0];
}

// ---------------------------------------------------------------------------
extern "C" void kernel_launch(void* const* d_in, const int* in_sizes, int n_in,
                              void* d_out, int out_size)
{
    const float* nf1 = (const float*)d_in[0];
    const float* nf2 = (const float*)d_in[2];
    const int* src1 = (const int*)d_in[4];
    const int* dst1 = (const int*)d_in[5];
    const int* gid1 = (const int*)d_in[6];
    const int* src2 = (const int*)d_in[7];
    const int* dst2 = (const int*)d_in[8];
    const int* gid2 = (const int*)d_in[9];
    const float* W1  = (const float*)d_in[10]; const float* b1  = (const float*)d_in[11];
    const float* Wr1 = (const float*)d_in[12]; const float* br1 = (const float*)d_in[13];
    const float* W2  = (const float*)d_in[14]; const float* b2  = (const float*)d_in[15];
    const float* Wr2 = (const float*)d_in[16]; const float* br2 = (const float*)d_in[17];
    const float* Ri1 = (const float*)d_in[18]; const float* rbi1 = (const float*)d_in[19];
    const float* Ro1 = (const float*)d_in[20]; const float* rbo1 = (const float*)d_in[21];
    const float* Ri2 = (const float*)d_in[22]; const float* rbi2 = (const float*)d_in[23];
    const float* Ro2 = (const float*)d_in[24]; const float* rbo2 = (const float*)d_in[25];
    const float* Wp  = (const float*)d_in[26]; const float* bp   = (const float*)d_in[27];

    float *hW, *agg, *T;
    uint32_t *nfH, *nfL, *h1H, *h1L, *WH, *WL;
    int *counts, *deg, *rowstart, *cursor, *csr_src;
    cudaGetSymbolAddress((void**)&hW,       g_hW);
    cudaGetSymbolAddress((void**)&agg,      g_agg);
    cudaGetSymbolAddress((void**)&nfH,      g_nfH);
    cudaGetSymbolAddress((void**)&nfL,      g_nfL);
    cudaGetSymbolAddress((void**)&h1H,      g_h1H);
    cudaGetSymbolAddress((void**)&h1L,      g_h1L);
    cudaGetSymbolAddress((void**)&WH,       g_WH);
    cudaGetSymbolAddress((void**)&WL,       g_WL);
    cudaGetSymbolAddress((void**)&T,        g_T);
    cudaGetSymbolAddress((void**)&counts,   g_counts);
    cudaGetSymbolAddress((void**)&deg,      g_deg);
    cudaGetSymbolAddress((void**)&rowstart, g_rowstart);
    cudaGetSymbolAddress((void**)&cursor,   g_cursor);
    cudaGetSymbolAddress((void**)&csr_src,  g_csr_src);

    cudaFuncSetAttribute(gemm_mma<0>, cudaFuncAttributeMaxDynamicSharedMemorySize, SMEM_BYTES);
    cudaFuncSetAttribute(gemm_mma<1>, cudaFuncAttributeMaxDynamicSharedMemorySize, SMEM_BYTES);
    cudaFuncSetAttribute(gemm_mma<2>, cudaFuncAttributeMaxDynamicSharedMemorySize, SMEM_BYTES);

    float* hW1  = hW;   float* hW2  = hW  + (size_t)N_NODES * DFEAT;
    float* agg1 = agg;  float* agg2 = agg + (size_t)N_NODES * DFEAT;
    uint32_t* nfH1 = nfH; uint32_t* nfH2 = nfH + (size_t)NW;
    uint32_t* nfL1 = nfL; uint32_t* nfL2 = nfL + (size_t)NW;
    uint32_t* h1H1 = h1H; uint32_t* h1H2 = h1H + (size_t)NW;
    uint32_t* h1L1 = h1L; uint32_t* h1L2 = h1L + (size_t)NW;
    // weight slots: 0=W1 1=Wr1 2=Ri1 3=W2 4=Wr2 5=Ri2
    uint32_t* WH_ = WH;  uint32_t* WL_ = WL;
    const int WSZ = 128 * 256;

    dim3 gemm_grid((N_NODES + 127) / 128, 2, 2);   // 391 x 2 x 2
    int eb2 = (2 * N_EDGES + 255) / 256;

    cudaMemsetAsync(deg, 0, 2 * N_NODES * sizeof(int));
    conv_nf<<<(int)((2 * (size_t)NW + 255) / 256), 256>>>(nf1, nf2, nfH, nfL);
    conv_W<<<(6 * 128 * 256 + 255) / 256, 256>>>(W1, Wr1, Ri1, W2, Wr2, Ri2, WH, WL);
    hist_kernel<<<eb2, 256>>>(dst1, dst2, deg);
    scan_kernel<<<2, 1024>>>(deg, rowstart, cursor);
    fill_kernel<<<eb2, 256>>>(src1, dst1, src2, dst2, cursor, csr_src);

    // hW = h @ W (both branches)
    gemm_mma<0><<<gemm_grid, 256, SMEM_BYTES>>>(
        nfH1, nfL1, nfH2, nfL2,
        WH_ + 0 * WSZ, WL_ + 0 * WSZ, WH_ + 3 * WSZ, WL_ + 3 * WSZ,
        nullptr, nullptr, nullptr, nullptr, nullptr, nullptr,
        hW1, hW2, nullptr, nullptr, nullptr, nullptr, N_NODES);
    // agg = gather-sum of hW rows
    gather_kernel<<<(2 * N_NODES * 32 + 255) / 256, 256>>>(hW, rowstart, csr_src, agg);
    // h1 = relu(agg + b) + relu(h @ Wr + br)  -> split output
    gemm_mma<1><<<gemm_grid, 256, SMEM_BYTES>>>(
        nfH1, nfL1, nfH2, nfL2,
        WH_ + 1 * WSZ, WL_ + 1 * WSZ, WH_ + 4 * WSZ, WL_ + 4 * WSZ,
        br1, br2, agg1, agg2, b1, b2,
        nullptr, nullptr, h1H1, h1L1, h1H2, h1L2, N_NODES);
    // h2 = relu(h1 @ Ri + rbi) -> fp32 (reuse hW buffers)
    gemm_mma<2><<<gemm_grid, 256, SMEM_BYTES>>>(
        h1H1, h1L1, h1H2, h1L2,
        WH_ + 2 * WSZ, WL_ + 2 * WSZ, WH_ + 5 * WSZ, WL_ + 5 * WSZ,
        rbi1, rbi2, nullptr, nullptr, nullptr, nullptr,
        hW1, hW2, nullptr, nullptr, nullptr, nullptr, N_NODES);
    // T[g] = segsum of h2 rows; counts
    segsum_kernel<<<2 * N_GRAPHS, 256>>>(hW, gid1, gid2, T, counts);
    // fused readout + predictor
    readout_final<<<N_GRAPHS, 256>>>(T, counts, Ro1, rbo1, Ro2, rbo2, Wp, bp,
                                     (float*)d_out);
}

// round 7
// speedup vs baseline: 3.0611x; 1.1168x over previous
#include <cuda_runtime.h>
#include <cuda_bf16.h>
#include <cstdint>
#include <cstddef>

// ---------------------------------------------------------------------------
// mulGCN: two-branch GCN forward, split-bf16 mma.sync GEMMs with pre-split
// operands + cp.async double-buffered pipeline. Multi-block CSR scan.
//   conv_nf / conv_W: fp32 -> (hi,lo) bf16 pair arrays (once per call)
//   CSR build by dst (hist -> scan1/scan2 -> fill)   [both branches]
//   hW  = h @ W                                      (GEMM MODE 0, fp32 out)
//   agg[n] = sum_{e: dst=n} hW[src[e]]               (warp-per-node gather)
//   h1  = relu(agg+b) + relu(h@Wr+br)                (GEMM MODE 1, split out)
//   h2  = relu(h1 @ Ri + rbi)                        (GEMM MODE 2, fp32 out)
//   T[g] = segsum of h2 rows (gid sorted, no atomics)
//   out[g] = (T1@Ro1 + c1*rbo1 + T2@Ro2 + c2*rbo2) . Wp + bp
// Split-bf16: x = hi(trunc bf16, exact) + lo(bf16 rn of remainder);
// A@B ~= AhiBhi + AhiBlo + AloBhi, fp32 accum -> ~2e-5 rel error.
// ---------------------------------------------------------------------------

#define N_NODES   50000
#define N_EDGES   800000
#define DFEAT     256
#define G_FEAT    200
#define N_GRAPHS  512

#define NW   (N_NODES * 128)          // words per branch for split arrays

#define SCAN_BLKS   49                // ceil(50000/1024)
#define SCAN_CHUNK  1024

__device__ float    g_hW  [2][(size_t)N_NODES * DFEAT];   // reused as h2
__device__ float    g_agg [2][(size_t)N_NODES * DFEAT];
__device__ uint32_t g_nfH [2][(size_t)NW];
__device__ uint32_t g_nfL [2][(size_t)NW];
__device__ uint32_t g_h1H [2][(size_t)NW];
__device__ uint32_t g_h1L [2][(size_t)NW];
__device__ uint32_t g_WH  [6][128 * 256];
__device__ uint32_t g_WL  [6][128 * 256];
__device__ float    g_T   [2][N_GRAPHS * DFEAT];
__device__ int      g_counts  [2][N_GRAPHS];
__device__ int      g_deg     [2][N_NODES];
__device__ int      g_rowstart[2][N_NODES + 1];
__device__ int      g_cursor  [2][N_NODES];
__device__ int      g_csr_src [2][N_EDGES];
__device__ int      g_bsums   [2 * SCAN_BLKS];

__device__ __forceinline__ float frelu(float x) { return x > 0.f ? x : 0.f; }

// ------------------------- mma / pack helpers ------------------------------
__device__ __forceinline__ void mma16816(float* c, const uint32_t* a,
                                         uint32_t b0, uint32_t b1) {
    asm volatile(
        "mma.sync.aligned.m16n8k16.row.col.f32.bf16.bf16.f32 "
        "{%0,%1,%2,%3}, {%4,%5,%6,%7}, {%8,%9}, {%0,%1,%2,%3};\n"
        : "+f"(c[0]), "+f"(c[1]), "+f"(c[2]), "+f"(c[3])
        : "r"(a[0]), "r"(a[1]), "r"(a[2]), "r"(a[3]), "r"(b0), "r"(b1));
}

__device__ __forceinline__ uint32_t pack_hi(float x, float y) {
    return __byte_perm(__float_as_uint(x), __float_as_uint(y), 0x7632);
}
__device__ __forceinline__ uint32_t pack_lo(float x, float y) {
    float hx = __uint_as_float(__float_as_uint(x) & 0xFFFF0000u);
    float hy = __uint_as_float(__float_as_uint(y) & 0xFFFF0000u);
    __nv_bfloat162 t;
    t.x = __float2bfloat16(x - hx);
    t.y = __float2bfloat16(y - hy);
    return *reinterpret_cast<uint32_t*>(&t);
}

// ------------------------- cp.async helpers --------------------------------
__device__ __forceinline__ void cp16(uint32_t dst, const void* src) {
    asm volatile("cp.async.cg.shared.global [%0], [%1], 16;"
                 :: "r"(dst), "l"(src));
}
__device__ __forceinline__ void cp16z(uint32_t dst, const void* src, bool ok) {
    int b = ok ? 16 : 0;
    asm volatile("cp.async.cg.shared.global [%0], [%1], 16, %2;"
                 :: "r"(dst), "l"(src), "r"(b));
}
#define CP_COMMIT()  asm volatile("cp.async.commit_group;" ::: "memory")
#define CP_WAIT1()   asm volatile("cp.async.wait_group 1;" ::: "memory")
#define CP_WAIT0()   asm volatile("cp.async.wait_group 0;" ::: "memory")

// SMEM words per buffer: AH[128][20] AL[128][20] BH[16][136] BL[16][136]
static constexpr int W_AH = 0, W_AL = 2560, W_BH = 5120, W_BL = 7296;
static constexpr int WBUF = 9472;
static constexpr int SMEM_BYTES = 2 * WBUF * 4;        // 75776

__device__ __forceinline__ void cpA(uint32_t sb, const uint32_t* __restrict__ AH,
                                    const uint32_t* __restrict__ AL,
                                    int M, int rowBase, int c, int tid)
{
    #pragma unroll
    for (int t = 0; t < 4; t++) {
        int idx = tid + t * 256;          // 0..1023
        int r   = idx >> 3;
        int seg = idx & 7;                // 0..7 (0-3 hi, 4-7 lo)
        int row = rowBase + r;
        bool ok = row < M;
        int rowc = ok ? row : 0;
        int s4 = (seg & 3) * 4;
        const uint32_t* src = (seg < 4 ? AH : AL) + (size_t)rowc * 128 + c * 16 + s4;
        uint32_t dst = sb + ((seg < 4 ? W_AH : W_AL) + r * 20 + s4) * 4;
        cp16z(dst, src, ok);
    }
}

__device__ __forceinline__ void cpB(uint32_t sb, const uint32_t* __restrict__ WH,
                                    const uint32_t* __restrict__ WL,
                                    int colBase, int c, int tid)
{
    #pragma unroll
    for (int t = 0; t < 4; t++) {
        int idx  = tid + t * 256;         // 0..1023
        int kp   = idx >> 6;              // 0..15
        int rest = idx & 63;
        int arr  = rest >> 5;             // 0 hi, 1 lo
        int s4   = (rest & 31) * 4;
        const uint32_t* src = (arr ? WL : WH) + (size_t)(c * 16 + kp) * 256 + colBase + s4;
        uint32_t dst = sb + ((arr ? W_BL : W_BH) + kp * 136 + s4) * 4;
        cp16(dst, src);
    }
}

// ---------------------------------------------------------------------------
// mma GEMM: 256 threads, 8 warps (4m x 2n), warp tile 32x64, both branches.
// ---------------------------------------------------------------------------
template<int MODE>
__global__ __launch_bounds__(256, 2)
void gemm_mma(const uint32_t* __restrict__ AH1, const uint32_t* __restrict__ AL1,
              const uint32_t* __restrict__ AH2, const uint32_t* __restrict__ AL2,
              const uint32_t* __restrict__ WH1, const uint32_t* __restrict__ WL1,
              const uint32_t* __restrict__ WH2, const uint32_t* __restrict__ WL2,
              const float* __restrict__ bias1, const float* __restrict__ bias2,
              const float* __restrict__ agg1,  const float* __restrict__ agg2,
              const float* __restrict__ bagg1, const float* __restrict__ bagg2,
              float* __restrict__ C1, float* __restrict__ C2,
              uint32_t* __restrict__ CH1, uint32_t* __restrict__ CL1,
              uint32_t* __restrict__ CH2, uint32_t* __restrict__ CL2,
              int M)
{
    extern __shared__ uint32_t sm[];
    const int br = blockIdx.z;
    const uint32_t* AH  = br ? AH2 : AH1;
    const uint32_t* AL  = br ? AL2 : AL1;
    const uint32_t* WH  = br ? WH2 : WH1;
    const uint32_t* WL  = br ? WL2 : WL1;
    const float* bias = br ? bias2 : bias1;
    const float* agg  = br ? agg2 : agg1;
    const float* bagg = br ? bagg2 : bagg1;
    float*    C  = br ? C2 : C1;
    uint32_t* CH = br ? CH2 : CH1;
    uint32_t* CL = br ? CL2 : CL1;

    const int tid  = threadIdx.x;
    const int lane = tid & 31;
    const int wid  = tid >> 5;
    const int wm   = wid & 3;
    const int wn   = wid >> 2;
    const int gid  = lane >> 2;
    const int tig  = lane & 3;
    const int rowBase = blockIdx.x * 128;
    const int colBase = blockIdx.y * 128;

    uint32_t sbase;
    {
        uint64_t a = __cvta_generic_to_shared(sm);
        sbase = (uint32_t)a;
    }

    float acc[2][8][4];
    #pragma unroll
    for (int mt = 0; mt < 2; mt++)
        #pragma unroll
        for (int nt = 0; nt < 8; nt++)
            #pragma unroll
            for (int q = 0; q < 4; q++) acc[mt][nt][q] = 0.f;

    cpA(sbase, AH, AL, M, rowBase, 0, tid);
    cpB(sbase, WH, WL, colBase, 0, tid);
    CP_COMMIT();

    #pragma unroll
    for (int c = 0; c < 8; c++) {
        if (c < 7) {
            uint32_t nb = sbase + ((c + 1) & 1) * WBUF * 4;
            cpA(nb, AH, AL, M, rowBase, c + 1, tid);
            cpB(nb, WH, WL, colBase, c + 1, tid);
            CP_COMMIT();
            CP_WAIT1();
        } else {
            CP_WAIT0();
        }
        __syncthreads();

        const uint32_t* buf = sm + (c & 1) * WBUF;
        const uint32_t* sAH = buf + W_AH;
        const uint32_t* sAL = buf + W_AL;
        const uint32_t* sBH = buf + W_BH;
        const uint32_t* sBL = buf + W_BL;

        #pragma unroll
        for (int ks = 0; ks < 2; ks++) {
            uint32_t aH[2][4], aL[2][4];
            #pragma unroll
            for (int mt = 0; mt < 2; mt++) {
                int off = (wm * 32 + mt * 16 + gid) * 20 + ks * 8 + tig;
                aH[mt][0] = sAH[off];       aH[mt][1] = sAH[off + 160];
                aH[mt][2] = sAH[off + 4];   aH[mt][3] = sAH[off + 164];
                aL[mt][0] = sAL[off];       aL[mt][1] = sAL[off + 160];
                aL[mt][2] = sAL[off + 4];   aL[mt][3] = sAL[off + 164];
            }
            #pragma unroll
            for (int nt = 0; nt < 8; nt++) {
                int bi = (ks * 8 + tig) * 136 + wn * 64 + nt * 8 + gid;
                uint32_t bh0 = sBH[bi], bh1 = sBH[bi + 544];
                uint32_t bl0 = sBL[bi], bl1 = sBL[bi + 544];
                #pragma unroll
                for (int mt = 0; mt < 2; mt++) {
                    mma16816(acc[mt][nt], aH[mt], bh0, bh1);
                    mma16816(acc[mt][nt], aH[mt], bl0, bl1);
                    mma16816(acc[mt][nt], aL[mt], bh0, bh1);
                }
            }
        }
        __syncthreads();
    }

    // ------------------------------ epilogue -------------------------------
    #pragma unroll
    for (int mt = 0; mt < 2; mt++) {
        #pragma unroll
        for (int nt = 0; nt < 8; nt++) {
            int r0  = rowBase + wm * 32 + mt * 16 + gid;
            int r1  = r0 + 8;
            int col = colBase + wn * 64 + nt * 8 + 2 * tig;
            float* a4 = acc[mt][nt];
            if (MODE == 0) {
                if (r0 < M)
                    *reinterpret_cast<float2*>(C + (size_t)r0 * 256 + col) =
                        make_float2(a4[0], a4[1]);
                if (r1 < M)
                    *reinterpret_cast<float2*>(C + (size_t)r1 * 256 + col) =
                        make_float2(a4[2], a4[3]);
            } else if (MODE == 1) {
                float2 bs = *reinterpret_cast<const float2*>(bias + col);
                float2 ba = *reinterpret_cast<const float2*>(bagg + col);
                if (r0 < M) {
                    float2 ag = *reinterpret_cast<const float2*>(agg + (size_t)r0 * 256 + col);
                    float v0 = frelu(a4[0] + bs.x) + frelu(ag.x + ba.x);
                    float v1 = frelu(a4[1] + bs.y) + frelu(ag.y + ba.y);
                    CH[(size_t)r0 * 128 + (col >> 1)] = pack_hi(v0, v1);
                    CL[(size_t)r0 * 128 + (col >> 1)] = pack_lo(v0, v1);
                }
                if (r1 < M) {
                    float2 ag = *reinterpret_cast<const float2*>(agg + (size_t)r1 * 256 + col);
                    float v0 = frelu(a4[2] + bs.x) + frelu(ag.x + ba.x);
                    float v1 = frelu(a4[3] + bs.y) + frelu(ag.y + ba.y);
                    CH[(size_t)r1 * 128 + (col >> 1)] = pack_hi(v0, v1);
                    CL[(size_t)r1 * 128 + (col >> 1)] = pack_lo(v0, v1);
                }
            } else {
                float2 bs = *reinterpret_cast<const float2*>(bias + col);
                if (r0 < M)
                    *reinterpret_cast<float2*>(C + (size_t)r0 * 256 + col) =
                        make_float2(frelu(a4[0] + bs.x), frelu(a4[1] + bs.y));
                if (r1 < M)
                    *reinterpret_cast<float2*>(C + (size_t)r1 * 256 + col) =
                        make_float2(frelu(a4[2] + bs.x), frelu(a4[3] + bs.y));
            }
        }
    }
}

// ---------------------------------------------------------------------------
// Conversion kernels
// ---------------------------------------------------------------------------
__global__ __launch_bounds__(256)
void conv_nf(const float* __restrict__ n1, const float* __restrict__ n2,
             uint32_t* __restrict__ H, uint32_t* __restrict__ L)
{
    size_t idx = (size_t)blockIdx.x * blockDim.x + threadIdx.x;
    if (idx >= 2 * (size_t)NW) return;
    int br = idx >= (size_t)NW;
    size_t w = idx - (size_t)br * NW;
    const float* nf = br ? n2 : n1;
    float2 v = *reinterpret_cast<const float2*>(nf + w * 2);
    H[idx] = pack_hi(v.x, v.y);
    L[idx] = pack_lo(v.x, v.y);
}

__global__ __launch_bounds__(256)
void conv_W(const float* __restrict__ m0, const float* __restrict__ m1,
            const float* __restrict__ m2, const float* __restrict__ m3,
            const float* __restrict__ m4, const float* __restrict__ m5,
            uint32_t* __restrict__ WH, uint32_t* __restrict__ WL)
{
    int idx = blockIdx.x * blockDim.x + threadIdx.x;
    if (idx >= 6 * 128 * 256) return;
    int m    = idx >> 15;
    int rest = idx & 32767;
    int k2   = rest >> 8;
    int n    = rest & 255;
    const float* Wm = (m == 0) ? m0 : (m == 1) ? m1 : (m == 2) ? m2
                    : (m == 3) ? m3 : (m == 4) ? m4 : m5;
    float a = Wm[(size_t)(2 * k2) * 256 + n];
    float b = Wm[(size_t)(2 * k2 + 1) * 256 + n];
    WH[idx] = pack_hi(a, b);
    WL[idx] = pack_lo(a, b);
}

// ---------------------------------------------------------------------------
// CSR build, both branches
// ---------------------------------------------------------------------------
__global__ void hist_kernel(const int* __restrict__ dst1, const int* __restrict__ dst2,
                            int* __restrict__ deg)
{
    int idx = blockIdx.x * blockDim.x + threadIdx.x;
    if (idx < 2 * N_EDGES) {
        int br = idx >= N_EDGES;
        int e  = idx - br * N_EDGES;
        int d  = br ? dst2[e] : dst1[e];
        atomicAdd(&deg[br * N_NODES + d], 1);
    }
}

// Phase 1: per-block (1024 elems) exclusive scan into rowstart-local + block sums
__global__ __launch_bounds__(256)
void scan1_kernel(const int* __restrict__ degAll, int* __restrict__ rowstartAll,
                  int* __restrict__ bsums)
{
    __shared__ int wsum[8];
    int br  = blockIdx.x / SCAN_BLKS;
    int blk = blockIdx.x % SCAN_BLKS;
    int t = threadIdx.x, lane = t & 31, w = t >> 5;
    const int* deg = degAll + br * N_NODES;
    int* rowstart  = rowstartAll + br * (N_NODES + 1);

    int base = blk * SCAN_CHUNK + t * 4;
    int v[4];
    #pragma unroll
    for (int i = 0; i < 4; i++)
        v[i] = (base + i < N_NODES) ? deg[base + i] : 0;
    int s = v[0] + v[1] + v[2] + v[3];

    // warp inclusive scan of thread sums
    int x = s;
    #pragma unroll
    for (int o = 1; o < 32; o <<= 1) {
        int n = __shfl_up_sync(0xFFFFFFFFu, x, o);
        if (lane >= o) x += n;
    }
    if (lane == 31) wsum[w] = x;
    __syncthreads();
    if (w == 0 && lane < 8) {
        int y = wsum[lane];
        #pragma unroll
        for (int o = 1; o < 8; o <<= 1) {
            int n = __shfl_up_sync(0xFFu, y, o);
            if (lane >= o) y += n;
        }
        wsum[lane] = y;
    }
    __syncthreads();
    int excl = x - s + (w > 0 ? wsum[w - 1] : 0);

    int run = excl;
    #pragma unroll
    for (int i = 0; i < 4; i++) {
        if (base + i < N_NODES) rowstart[base + i] = run;
        run += v[i];
    }
    if (t == 255) bsums[br * SCAN_BLKS + blk] = wsum[7];
}

// Phase 2: add block offsets (serial 49-prefix per block), write cursor
__global__ __launch_bounds__(256)
void scan2_kernel(const int* __restrict__ bsums, int* __restrict__ rowstartAll,
                  int* __restrict__ cursorAll)
{
    __shared__ int soff;
    int br  = blockIdx.x / SCAN_BLKS;
    int blk = blockIdx.x % SCAN_BLKS;
    int t = threadIdx.x;
    int* rowstart = rowstartAll + br * (N_NODES + 1);
    int* cursor   = cursorAll   + br * N_NODES;

    if (t == 0) {
        int off = 0;
        for (int j = 0; j < blk; j++) off += bsums[br * SCAN_BLKS + j];
        soff = off;
        if (blockIdx.x == 0) {
            rowstartAll[N_NODES] = N_EDGES;                   // branch 0 total
            rowstartAll[(N_NODES + 1) + N_NODES] = N_EDGES;   // branch 1 total
        }
    }
    __syncthreads();
    int off = soff;
    int base = blk * SCAN_CHUNK + t * 4;
    #pragma unroll
    for (int i = 0; i < 4; i++) {
        int g = base + i;
        if (g < N_NODES) {
            int val = rowstart[g] + off;
            rowstart[g] = val;
            cursor[g]   = val;
        }
    }
}

__global__ void fill_kernel(const int* __restrict__ src1, const int* __restrict__ dst1,
                            const int* __restrict__ src2, const int* __restrict__ dst2,
                            int* __restrict__ cursorAll, int* __restrict__ csrAll)
{
    int idx = blockIdx.x * blockDim.x + threadIdx.x;
    if (idx < 2 * N_EDGES) {
        int br = idx >= N_EDGES;
        int e  = idx - br * N_EDGES;
        int d  = br ? dst2[e] : dst1[e];
        int s  = br ? src2[e] : src1[e];
        int p  = atomicAdd(&cursorAll[br * N_NODES + d], 1);
        csrAll[br * N_EDGES + p] = s;
    }
}

// ---------------------------------------------------------------------------
// Warp-per-node gather, both branches
// ---------------------------------------------------------------------------
__global__ __launch_bounds__(256)
void gather_kernel(const float* __restrict__ hWAll,
                   const int* __restrict__ rowstartAll,
                   const int* __restrict__ csrAll,
                   float* __restrict__ aggAll)
{
    int gn = (blockIdx.x * blockDim.x + threadIdx.x) >> 5;
    int lane = threadIdx.x & 31;
    if (gn >= 2 * N_NODES) return;
    int br   = gn >= N_NODES;
    int node = gn - br * N_NODES;
    const int*   rowstart = rowstartAll + br * (N_NODES + 1);
    const int*   csr      = csrAll + (size_t)br * N_EDGES;
    const float* hW       = hWAll  + (size_t)br * N_NODES * DFEAT;

    int beg = rowstart[node], end = rowstart[node + 1];
    float4 a0 = make_float4(0.f, 0.f, 0.f, 0.f);
    float4 a1 = make_float4(0.f, 0.f, 0.f, 0.f);
    float4 b0 = make_float4(0.f, 0.f, 0.f, 0.f);
    float4 b1 = make_float4(0.f, 0.f, 0.f, 0.f);
    int e = beg;
    for (; e + 1 < end; e += 2) {
        const float4* r0 = reinterpret_cast<const float4*>(hW + (size_t)csr[e]     * DFEAT);
        const float4* r1 = reinterpret_cast<const float4*>(hW + (size_t)csr[e + 1] * DFEAT);
        float4 u0 = r0[lane], u1 = r0[lane + 32];
        float4 v0 = r1[lane], v1 = r1[lane + 32];
        a0.x += u0.x; a0.y += u0.y; a0.z += u0.z; a0.w += u0.w;
        a1.x += u1.x; a1.y += u1.y; a1.z += u1.z; a1.w += u1.w;
        b0.x += v0.x; b0.y += v0.y; b0.z += v0.z; b0.w += v0.w;
        b1.x += v1.x; b1.y += v1.y; b1.z += v1.z; b1.w += v1.w;
    }
    if (e < end) {
        const float4* r0 = reinterpret_cast<const float4*>(hW + (size_t)csr[e] * DFEAT);
        float4 u0 = r0[lane], u1 = r0[lane + 32];
        a0.x += u0.x; a0.y += u0.y; a0.z += u0.z; a0.w += u0.w;
        a1.x += u1.x; a1.y += u1.y; a1.z += u1.z; a1.w += u1.w;
    }
    a0.x += b0.x; a0.y += b0.y; a0.z += b0.z; a0.w += b0.w;
    a1.x += b1.x; a1.y += b1.y; a1.z += b1.z; a1.w += b1.w;
    float4* out = reinterpret_cast<float4*>(aggAll + ((size_t)br * N_NODES + node) * DFEAT);
    out[lane]      = a0;
    out[lane + 32] = a1;
}

// ---------------------------------------------------------------------------
// Segment sum (sorted gid), both branches
// ---------------------------------------------------------------------------
__global__ __launch_bounds__(256)
void segsum_kernel(const float* __restrict__ h2All, const int* __restrict__ gid1,
                   const int* __restrict__ gid2,
                   float* __restrict__ TAll, int* __restrict__ countsAll)
{
    __shared__ int sb, se;
    int bidx = blockIdx.x;
    int br   = bidx >> 9;
    int g    = bidx & 511;
    const int* gid = br ? gid2 : gid1;
    const float* h2 = h2All + (size_t)br * N_NODES * DFEAT;
    if (threadIdx.x == 0) {
        int lo = 0, hi = N_NODES;
        while (lo < hi) { int m = (lo + hi) >> 1; if (gid[m] < g) lo = m + 1; else hi = m; }
        sb = lo;
        lo = sb; hi = N_NODES;
        while (lo < hi) { int m = (lo + hi) >> 1; if (gid[m] < g + 1) lo = m + 1; else hi = m; }
        se = lo;
        countsAll[br * N_GRAPHS + g] = se - sb;
    }
    __syncthreads();
    int beg = sb, end = se, c = threadIdx.x;
    float s = 0.f;
    for (int r = beg; r < end; r++)
        s += h2[(size_t)r * DFEAT + c];
    TAll[((size_t)br * N_GRAPHS + g) * DFEAT + c] = s;
}

// ---------------------------------------------------------------------------
// Fused readout + predictor
// ---------------------------------------------------------------------------
__global__ __launch_bounds__(256)
void readout_final(const float* __restrict__ TAll, const int* __restrict__ countsAll,
                   const float* __restrict__ Ro1, const float* __restrict__ rbo1,
                   const float* __restrict__ Ro2, const float* __restrict__ rbo2,
                   const float* __restrict__ Wp, const float* __restrict__ bp,
                   float* __restrict__ out)
{
    __shared__ float ts1[DFEAT], ts2[DFEAT];
    __shared__ float red[256];
    int g = blockIdx.x;
    int t = threadIdx.x;
    ts1[t] = TAll[(size_t)g * DFEAT + t];
    ts2[t] = TAll[((size_t)N_GRAPHS + g) * DFEAT + t];
    __syncthreads();
    float c1 = (float)countsAll[g];
    float c2 = (float)countsAll[N_GRAPHS + g];
    float partial = 0.f;
    if (t < G_FEAT) {
        float s = c1 * rbo1[t] + c2 * rbo2[t];
        #pragma unroll 8
        for (int k = 0; k < DFEAT; k++)
            s += ts1[k] * Ro1[(size_t)k * G_FEAT + t]
               + ts2[k] * Ro2[(size_t)k * G_FEAT + t];
        partial = s * Wp[t];
    }
    red[t] = partial;
    __syncthreads();
    #pragma unroll
    for (int st = 128; st > 0; st >>= 1) {
        if (t < st) red[t] += red[t + st];
        __syncthreads();
    }
    if (t == 0) out[g] = red[0] + bp[0];
}

// ---------------------------------------------------------------------------
extern "C" void kernel_launch(void* const* d_in, const int* in_sizes, int n_in,
                              void* d_out, int out_size)
{
    const float* nf1 = (const float*)d_in[0];
    const float* nf2 = (const float*)d_in[2];
    const int* src1 = (const int*)d_in[4];
    const int* dst1 = (const int*)d_in[5];
    const int* gid1 = (const int*)d_in[6];
    const int* src2 = (const int*)d_in[7];
    const int* dst2 = (const int*)d_in[8];
    const int* gid2 = (const int*)d_in[9];
    const float* W1  = (const float*)d_in[10]; const float* b1  = (const float*)d_in[11];
    const float* Wr1 = (const float*)d_in[12]; const float* br1 = (const float*)d_in[13];
    const float* W2  = (const float*)d_in[14]; const float* b2  = (const float*)d_in[15];
    const float* Wr2 = (const float*)d_in[16]; const float* br2 = (const float*)d_in[17];
    const float* Ri1 = (const float*)d_in[18]; const float* rbi1 = (const float*)d_in[19];
    const float* Ro1 = (const float*)d_in[20]; const float* rbo1 = (const float*)d_in[21];
    const float* Ri2 = (const float*)d_in[22]; const float* rbi2 = (const float*)d_in[23];
    const float* Ro2 = (const float*)d_in[24]; const float* rbo2 = (const float*)d_in[25];
    const float* Wp  = (const float*)d_in[26]; const float* bp   = (const float*)d_in[27];

    float *hW, *agg, *T;
    uint32_t *nfH, *nfL, *h1H, *h1L, *WH, *WL;
    int *counts, *deg, *rowstart, *cursor, *csr_src, *bsums;
    cudaGetSymbolAddress((void**)&hW,       g_hW);
    cudaGetSymbolAddress((void**)&agg,      g_agg);
    cudaGetSymbolAddress((void**)&nfH,      g_nfH);
    cudaGetSymbolAddress((void**)&nfL,      g_nfL);
    cudaGetSymbolAddress((void**)&h1H,      g_h1H);
    cudaGetSymbolAddress((void**)&h1L,      g_h1L);
    cudaGetSymbolAddress((void**)&WH,       g_WH);
    cudaGetSymbolAddress((void**)&WL,       g_WL);
    cudaGetSymbolAddress((void**)&T,        g_T);
    cudaGetSymbolAddress((void**)&counts,   g_counts);
    cudaGetSymbolAddress((void**)&deg,      g_deg);
    cudaGetSymbolAddress((void**)&rowstart, g_rowstart);
    cudaGetSymbolAddress((void**)&cursor,   g_cursor);
    cudaGetSymbolAddress((void**)&csr_src,  g_csr_src);
    cudaGetSymbolAddress((void**)&bsums,    g_bsums);

    cudaFuncSetAttribute(gemm_mma<0>, cudaFuncAttributeMaxDynamicSharedMemorySize, SMEM_BYTES);
    cudaFuncSetAttribute(gemm_mma<1>, cudaFuncAttributeMaxDynamicSharedMemorySize, SMEM_BYTES);
    cudaFuncSetAttribute(gemm_mma<2>, cudaFuncAttributeMaxDynamicSharedMemorySize, SMEM_BYTES);

    float* hW1  = hW;   float* hW2  = hW  + (size_t)N_NODES * DFEAT;
    float* agg1 = agg;  float* agg2 = agg + (size_t)N_NODES * DFEAT;
    uint32_t* nfH1 = nfH; uint32_t* nfH2 = nfH + (size_t)NW;
    uint32_t* nfL1 = nfL; uint32_t* nfL2 = nfL + (size_t)NW;
    uint32_t* h1H1 = h1H; uint32_t* h1H2 = h1H + (size_t)NW;
    uint32_t* h1L1 = h1L; uint32_t* h1L2 = h1L + (size_t)NW;
    uint32_t* WH_ = WH;  uint32_t* WL_ = WL;
    const int WSZ = 128 * 256;

    dim3 gemm_grid((N_NODES + 127) / 128, 2, 2);   // 391 x 2 x 2
    int eb2 = (2 * N_EDGES + 255) / 256;

    cudaMemsetAsync(deg, 0, 2 * N_NODES * sizeof(int));
    conv_nf<<<(int)((2 * (size_t)NW + 255) / 256), 256>>>(nf1, nf2, nfH, nfL);
    conv_W<<<(6 * 128 * 256 + 255) / 256, 256>>>(W1, Wr1, Ri1, W2, Wr2, Ri2, WH, WL);
    hist_kernel<<<eb2, 256>>>(dst1, dst2, deg);
    scan1_kernel<<<2 * SCAN_BLKS, 256>>>(deg, rowstart, bsums);
    scan2_kernel<<<2 * SCAN_BLKS, 256>>>(bsums, rowstart, cursor);
    fill_kernel<<<eb2, 256>>>(src1, dst1, src2, dst2, cursor, csr_src);

    // hW = h @ W (both branches)
    gemm_mma<0><<<gemm_grid, 256, SMEM_BYTES>>>(
        nfH1, nfL1, nfH2, nfL2,
        WH_ + 0 * WSZ, WL_ + 0 * WSZ, WH_ + 3 * WSZ, WL_ + 3 * WSZ,
        nullptr, nullptr, nullptr, nullptr, nullptr, nullptr,
        hW1, hW2, nullptr, nullptr, nullptr, nullptr, N_NODES);
    // agg = gather-sum of hW rows
    gather_kernel<<<(2 * N_NODES * 32 + 255) / 256, 256>>>(hW, rowstart, csr_src, agg);
    // h1 = relu(agg + b) + relu(h @ Wr + br)  -> split output
    gemm_mma<1><<<gemm_grid, 256, SMEM_BYTES>>>(
        nfH1, nfL1, nfH2, nfL2,
        WH_ + 1 * WSZ, WL_ + 1 * WSZ, WH_ + 4 * WSZ, WL_ + 4 * WSZ,
        br1, br2, agg1, agg2, b1, b2,
        nullptr, nullptr, h1H1, h1L1, h1H2, h1L2, N_NODES);
    // h2 = relu(h1 @ Ri + rbi) -> fp32 (reuse hW buffers)
    gemm_mma<2><<<gemm_grid, 256, SMEM_BYTES>>>(
        h1H1, h1L1, h1H2, h1L2,
        WH_ + 2 * WSZ, WL_ + 2 * WSZ, WH_ + 5 * WSZ, WL_ + 5 * WSZ,
        rbi1, rbi2, nullptr, nullptr, nullptr, nullptr,
        hW1, hW2, nullptr, nullptr, nullptr, nullptr, N_NODES);
    // T[g] = segsum of h2 rows; counts
    segsum_kernel<<<2 * N_GRAPHS, 256>>>(hW, gid1, gid2, T, counts);
    // fused readout + predictor
    readout_final<<<N_GRAPHS, 256>>>(T, counts, Ro1, rbo1, Ro2, rbo2, Wp, bp,
                                     (float*)d_out);
}

// round 8
// speedup vs baseline: 3.1564x; 1.0311x over previous
#include <cuda_runtime.h>
#include <cuda_bf16.h>
#include <cstdint>
#include <cstddef>

// ---------------------------------------------------------------------------
// mulGCN: two-branch GCN forward, split-bf16 mma.sync GEMMs with pre-split
// operands + cp.async double-buffered pipeline. Multi-block CSR scan.
// R8: CSR build chain runs on a second stream, overlapped with conv+GEMM0
// (fork/join via events; both chains are independent until gather).
//   conv_nf / conv_W: fp32 -> (hi,lo) bf16 pair arrays (once per call)
//   CSR build by dst (hist -> scan1/scan2 -> fill)   [stream 2]
//   hW  = h @ W                                      (GEMM MODE 0, fp32 out)
//   agg[n] = sum_{e: dst=n} hW[src[e]]               (warp-per-node gather)
//   h1  = relu(agg+b) + relu(h@Wr+br)                (GEMM MODE 1, split out)
//   h2  = relu(h1 @ Ri + rbi)                        (GEMM MODE 2, fp32 out)
//   T[g] = segsum of h2 rows (gid sorted, no atomics)
//   out[g] = (T1@Ro1 + c1*rbo1 + T2@Ro2 + c2*rbo2) . Wp + bp
// Split-bf16: x = hi(trunc bf16, exact) + lo(bf16 rn of remainder);
// A@B ~= AhiBhi + AhiBlo + AloBhi, fp32 accum -> ~2e-5 rel error.
// ---------------------------------------------------------------------------

#define N_NODES   50000
#define N_EDGES   800000
#define DFEAT     256
#define G_FEAT    200
#define N_GRAPHS  512

#define NW   (N_NODES * 128)          // words per branch for split arrays

#define SCAN_BLKS   49                // ceil(50000/1024)
#define SCAN_CHUNK  1024

__device__ float    g_hW  [2][(size_t)N_NODES * DFEAT];   // reused as h2
__device__ float    g_agg [2][(size_t)N_NODES * DFEAT];
__device__ uint32_t g_nfH [2][(size_t)NW];
__device__ uint32_t g_nfL [2][(size_t)NW];
__device__ uint32_t g_h1H [2][(size_t)NW];
__device__ uint32_t g_h1L [2][(size_t)NW];
__device__ uint32_t g_WH  [6][128 * 256];
__device__ uint32_t g_WL  [6][128 * 256];
__device__ float    g_T   [2][N_GRAPHS * DFEAT];
__device__ int      g_counts  [2][N_GRAPHS];
__device__ int      g_deg     [2][N_NODES];
__device__ int      g_rowstart[2][N_NODES + 1];
__device__ int      g_cursor  [2][N_NODES];
__device__ int      g_csr_src [2][N_EDGES];
__device__ int      g_bsums   [2 * SCAN_BLKS];

__device__ __forceinline__ float frelu(float x) { return x > 0.f ? x : 0.f; }

// ------------------------- mma / pack helpers ------------------------------
__device__ __forceinline__ void mma16816(float* c, const uint32_t* a,
                                         uint32_t b0, uint32_t b1) {
    asm volatile(
        "mma.sync.aligned.m16n8k16.row.col.f32.bf16.bf16.f32 "
        "{%0,%1,%2,%3}, {%4,%5,%6,%7}, {%8,%9}, {%0,%1,%2,%3};\n"
        : "+f"(c[0]), "+f"(c[1]), "+f"(c[2]), "+f"(c[3])
        : "r"(a[0]), "r"(a[1]), "r"(a[2]), "r"(a[3]), "r"(b0), "r"(b1));
}

__device__ __forceinline__ uint32_t pack_hi(float x, float y) {
    return __byte_perm(__float_as_uint(x), __float_as_uint(y), 0x7632);
}
__device__ __forceinline__ uint32_t pack_lo(float x, float y) {
    float hx = __uint_as_float(__float_as_uint(x) & 0xFFFF0000u);
    float hy = __uint_as_float(__float_as_uint(y) & 0xFFFF0000u);
    __nv_bfloat162 t;
    t.x = __float2bfloat16(x - hx);
    t.y = __float2bfloat16(y - hy);
    return *reinterpret_cast<uint32_t*>(&t);
}

// ------------------------- cp.async helpers --------------------------------
__device__ __forceinline__ void cp16(uint32_t dst, const void* src) {
    asm volatile("cp.async.cg.shared.global [%0], [%1], 16;"
                 :: "r"(dst), "l"(src));
}
__device__ __forceinline__ void cp16z(uint32_t dst, const void* src, bool ok) {
    int b = ok ? 16 : 0;
    asm volatile("cp.async.cg.shared.global [%0], [%1], 16, %2;"
                 :: "r"(dst), "l"(src), "r"(b));
}
#define CP_COMMIT()  asm volatile("cp.async.commit_group;" ::: "memory")
#define CP_WAIT1()   asm volatile("cp.async.wait_group 1;" ::: "memory")
#define CP_WAIT0()   asm volatile("cp.async.wait_group 0;" ::: "memory")

// SMEM words per buffer: AH[128][20] AL[128][20] BH[16][136] BL[16][136]
static constexpr int W_AH = 0, W_AL = 2560, W_BH = 5120, W_BL = 7296;
static constexpr int WBUF = 9472;
static constexpr int SMEM_BYTES = 2 * WBUF * 4;        // 75776

__device__ __forceinline__ void cpA(uint32_t sb, const uint32_t* __restrict__ AH,
                                    const uint32_t* __restrict__ AL,
                                    int M, int rowBase, int c, int tid)
{
    #pragma unroll
    for (int t = 0; t < 4; t++) {
        int idx = tid + t * 256;          // 0..1023
        int r   = idx >> 3;
        int seg = idx & 7;                // 0..7 (0-3 hi, 4-7 lo)
        int row = rowBase + r;
        bool ok = row < M;
        int rowc = ok ? row : 0;
        int s4 = (seg & 3) * 4;
        const uint32_t* src = (seg < 4 ? AH : AL) + (size_t)rowc * 128 + c * 16 + s4;
        uint32_t dst = sb + ((seg < 4 ? W_AH : W_AL) + r * 20 + s4) * 4;
        cp16z(dst, src, ok);
    }
}

__device__ __forceinline__ void cpB(uint32_t sb, const uint32_t* __restrict__ WH,
                                    const uint32_t* __restrict__ WL,
                                    int colBase, int c, int tid)
{
    #pragma unroll
    for (int t = 0; t < 4; t++) {
        int idx  = tid + t * 256;         // 0..1023
        int kp   = idx >> 6;              // 0..15
        int rest = idx & 63;
        int arr  = rest >> 5;             // 0 hi, 1 lo
        int s4   = (rest & 31) * 4;
        const uint32_t* src = (arr ? WL : WH) + (size_t)(c * 16 + kp) * 256 + colBase + s4;
        uint32_t dst = sb + ((arr ? W_BL : W_BH) + kp * 136 + s4) * 4;
        cp16(dst, src);
    }
}

// ---------------------------------------------------------------------------
// mma GEMM: 256 threads, 8 warps (4m x 2n), warp tile 32x64, both branches.
// ---------------------------------------------------------------------------
template<int MODE>
__global__ __launch_bounds__(256, 2)
void gemm_mma(const uint32_t* __restrict__ AH1, const uint32_t* __restrict__ AL1,
              const uint32_t* __restrict__ AH2, const uint32_t* __restrict__ AL2,
              const uint32_t* __restrict__ WH1, const uint32_t* __restrict__ WL1,
              const uint32_t* __restrict__ WH2, const uint32_t* __restrict__ WL2,
              const float* __restrict__ bias1, const float* __restrict__ bias2,
              const float* __restrict__ agg1,  const float* __restrict__ agg2,
              const float* __restrict__ bagg1, const float* __restrict__ bagg2,
              float* __restrict__ C1, float* __restrict__ C2,
              uint32_t* __restrict__ CH1, uint32_t* __restrict__ CL1,
              uint32_t* __restrict__ CH2, uint32_t* __restrict__ CL2,
              int M)
{
    extern __shared__ uint32_t sm[];
    const int br = blockIdx.z;
    const uint32_t* AH  = br ? AH2 : AH1;
    const uint32_t* AL  = br ? AL2 : AL1;
    const uint32_t* WH  = br ? WH2 : WH1;
    const uint32_t* WL  = br ? WL2 : WL1;
    const float* bias = br ? bias2 : bias1;
    const float* agg  = br ? agg2 : agg1;
    const float* bagg = br ? bagg2 : bagg1;
    float*    C  = br ? C2 : C1;
    uint32_t* CH = br ? CH2 : CH1;
    uint32_t* CL = br ? CL2 : CL1;

    const int tid  = threadIdx.x;
    const int lane = tid & 31;
    const int wid  = tid >> 5;
    const int wm   = wid & 3;
    const int wn   = wid >> 2;
    const int gid  = lane >> 2;
    const int tig  = lane & 3;
    const int rowBase = blockIdx.x * 128;
    const int colBase = blockIdx.y * 128;

    uint32_t sbase;
    {
        uint64_t a = __cvta_generic_to_shared(sm);
        sbase = (uint32_t)a;
    }

    float acc[2][8][4];
    #pragma unroll
    for (int mt = 0; mt < 2; mt++)
        #pragma unroll
        for (int nt = 0; nt < 8; nt++)
            #pragma unroll
            for (int q = 0; q < 4; q++) acc[mt][nt][q] = 0.f;

    cpA(sbase, AH, AL, M, rowBase, 0, tid);
    cpB(sbase, WH, WL, colBase, 0, tid);
    CP_COMMIT();

    #pragma unroll
    for (int c = 0; c < 8; c++) {
        if (c < 7) {
            uint32_t nb = sbase + ((c + 1) & 1) * WBUF * 4;
            cpA(nb, AH, AL, M, rowBase, c + 1, tid);
            cpB(nb, WH, WL, colBase, c + 1, tid);
            CP_COMMIT();
            CP_WAIT1();
        } else {
            CP_WAIT0();
        }
        __syncthreads();

        const uint32_t* buf = sm + (c & 1) * WBUF;
        const uint32_t* sAH = buf + W_AH;
        const uint32_t* sAL = buf + W_AL;
        const uint32_t* sBH = buf + W_BH;
        const uint32_t* sBL = buf + W_BL;

        #pragma unroll
        for (int ks = 0; ks < 2; ks++) {
            uint32_t aH[2][4], aL[2][4];
            #pragma unroll
            for (int mt = 0; mt < 2; mt++) {
                int off = (wm * 32 + mt * 16 + gid) * 20 + ks * 8 + tig;
                aH[mt][0] = sAH[off];       aH[mt][1] = sAH[off + 160];
                aH[mt][2] = sAH[off + 4];   aH[mt][3] = sAH[off + 164];
                aL[mt][0] = sAL[off];       aL[mt][1] = sAL[off + 160];
                aL[mt][2] = sAL[off + 4];   aL[mt][3] = sAL[off + 164];
            }
            #pragma unroll
            for (int nt = 0; nt < 8; nt++) {
                int bi = (ks * 8 + tig) * 136 + wn * 64 + nt * 8 + gid;
                uint32_t bh0 = sBH[bi], bh1 = sBH[bi + 544];
                uint32_t bl0 = sBL[bi], bl1 = sBL[bi + 544];
                #pragma unroll
                for (int mt = 0; mt < 2; mt++) {
                    mma16816(acc[mt][nt], aH[mt], bh0, bh1);
                    mma16816(acc[mt][nt], aH[mt], bl0, bl1);
                    mma16816(acc[mt][nt], aL[mt], bh0, bh1);
                }
            }
        }
        __syncthreads();
    }

    // ------------------------------ epilogue -------------------------------
    #pragma unroll
    for (int mt = 0; mt < 2; mt++) {
        #pragma unroll
        for (int nt = 0; nt < 8; nt++) {
            int r0  = rowBase + wm * 32 + mt * 16 + gid;
            int r1  = r0 + 8;
            int col = colBase + wn * 64 + nt * 8 + 2 * tig;
            float* a4 = acc[mt][nt];
            if (MODE == 0) {
                if (r0 < M)
                    *reinterpret_cast<float2*>(C + (size_t)r0 * 256 + col) =
                        make_float2(a4[0], a4[1]);
                if (r1 < M)
                    *reinterpret_cast<float2*>(C + (size_t)r1 * 256 + col) =
                        make_float2(a4[2], a4[3]);
            } else if (MODE == 1) {
                float2 bs = *reinterpret_cast<const float2*>(bias + col);
                float2 ba = *reinterpret_cast<const float2*>(bagg + col);
                if (r0 < M) {
                    float2 ag = *reinterpret_cast<const float2*>(agg + (size_t)r0 * 256 + col);
                    float v0 = frelu(a4[0] + bs.x) + frelu(ag.x + ba.x);
                    float v1 = frelu(a4[1] + bs.y) + frelu(ag.y + ba.y);
                    CH[(size_t)r0 * 128 + (col >> 1)] = pack_hi(v0, v1);
                    CL[(size_t)r0 * 128 + (col >> 1)] = pack_lo(v0, v1);
                }
                if (r1 < M) {
                    float2 ag = *reinterpret_cast<const float2*>(agg + (size_t)r1 * 256 + col);
                    float v0 = frelu(a4[2] + bs.x) + frelu(ag.x + ba.x);
                    float v1 = frelu(a4[3] + bs.y) + frelu(ag.y + ba.y);
                    CH[(size_t)r1 * 128 + (col >> 1)] = pack_hi(v0, v1);
                    CL[(size_t)r1 * 128 + (col >> 1)] = pack_lo(v0, v1);
                }
            } else {
                float2 bs = *reinterpret_cast<const float2*>(bias + col);
                if (r0 < M)
                    *reinterpret_cast<float2*>(C + (size_t)r0 * 256 + col) =
                        make_float2(frelu(a4[0] + bs.x), frelu(a4[1] + bs.y));
                if (r1 < M)
                    *reinterpret_cast<float2*>(C + (size_t)r1 * 256 + col) =
                        make_float2(frelu(a4[2] + bs.x), frelu(a4[3] + bs.y));
            }
        }
    }
}

// ---------------------------------------------------------------------------
// Conversion kernels
// ---------------------------------------------------------------------------
__global__ __launch_bounds__(256)
void conv_nf(const float* __restrict__ n1, const float* __restrict__ n2,
             uint32_t* __restrict__ H, uint32_t* __restrict__ L)
{
    size_t idx = (size_t)blockIdx.x * blockDim.x + threadIdx.x;
    if (idx >= 2 * (size_t)NW) return;
    int br = idx >= (size_t)NW;
    size_t w = idx - (size_t)br * NW;
    const float* nf = br ? n2 : n1;
    float2 v = *reinterpret_cast<const float2*>(nf + w * 2);
    H[idx] = pack_hi(v.x, v.y);
    L[idx] = pack_lo(v.x, v.y);
}

__global__ __launch_bounds__(256)
void conv_W(const float* __restrict__ m0, const float* __restrict__ m1,
            const float* __restrict__ m2, const float* __restrict__ m3,
            const float* __restrict__ m4, const float* __restrict__ m5,
            uint32_t* __restrict__ WH, uint32_t* __restrict__ WL)
{
    int idx = blockIdx.x * blockDim.x + threadIdx.x;
    if (idx >= 6 * 128 * 256) return;
    int m    = idx >> 15;
    int rest = idx & 32767;
    int k2   = rest >> 8;
    int n    = rest & 255;
    const float* Wm = (m == 0) ? m0 : (m == 1) ? m1 : (m == 2) ? m2
                    : (m == 3) ? m3 : (m == 4) ? m4 : m5;
    float a = Wm[(size_t)(2 * k2) * 256 + n];
    float b = Wm[(size_t)(2 * k2 + 1) * 256 + n];
    WH[idx] = pack_hi(a, b);
    WL[idx] = pack_lo(a, b);
}

// ---------------------------------------------------------------------------
// CSR build, both branches
// ---------------------------------------------------------------------------
__global__ void hist_kernel(const int* __restrict__ dst1, const int* __restrict__ dst2,
                            int* __restrict__ deg)
{
    int idx = blockIdx.x * blockDim.x + threadIdx.x;
    if (idx < 2 * N_EDGES) {
        int br = idx >= N_EDGES;
        int e  = idx - br * N_EDGES;
        int d  = br ? dst2[e] : dst1[e];
        atomicAdd(&deg[br * N_NODES + d], 1);
    }
}

__global__ __launch_bounds__(256)
void scan1_kernel(const int* __restrict__ degAll, int* __restrict__ rowstartAll,
                  int* __restrict__ bsums)
{
    __shared__ int wsum[8];
    int br  = blockIdx.x / SCAN_BLKS;
    int blk = blockIdx.x % SCAN_BLKS;
    int t = threadIdx.x, lane = t & 31, w = t >> 5;
    const int* deg = degAll + br * N_NODES;
    int* rowstart  = rowstartAll + br * (N_NODES + 1);

    int base = blk * SCAN_CHUNK + t * 4;
    int v[4];
    #pragma unroll
    for (int i = 0; i < 4; i++)
        v[i] = (base + i < N_NODES) ? deg[base + i] : 0;
    int s = v[0] + v[1] + v[2] + v[3];

    int x = s;
    #pragma unroll
    for (int o = 1; o < 32; o <<= 1) {
        int n = __shfl_up_sync(0xFFFFFFFFu, x, o);
        if (lane >= o) x += n;
    }
    if (lane == 31) wsum[w] = x;
    __syncthreads();
    if (w == 0 && lane < 8) {
        int y = wsum[lane];
        #pragma unroll
        for (int o = 1; o < 8; o <<= 1) {
            int n = __shfl_up_sync(0xFFu, y, o);
            if (lane >= o) y += n;
        }
        wsum[lane] = y;
    }
    __syncthreads();
    int excl = x - s + (w > 0 ? wsum[w - 1] : 0);

    int run = excl;
    #pragma unroll
    for (int i = 0; i < 4; i++) {
        if (base + i < N_NODES) rowstart[base + i] = run;
        run += v[i];
    }
    if (t == 255) bsums[br * SCAN_BLKS + blk] = wsum[7];
}

__global__ __launch_bounds__(256)
void scan2_kernel(const int* __restrict__ bsums, int* __restrict__ rowstartAll,
                  int* __restrict__ cursorAll)
{
    __shared__ int soff;
    int br  = blockIdx.x / SCAN_BLKS;
    int blk = blockIdx.x % SCAN_BLKS;
    int t = threadIdx.x;
    int* rowstart = rowstartAll + br * (N_NODES + 1);
    int* cursor   = cursorAll   + br * N_NODES;

    if (t == 0) {
        int off = 0;
        for (int j = 0; j < blk; j++) off += bsums[br * SCAN_BLKS + j];
        soff = off;
        if (blockIdx.x == 0) {
            rowstartAll[N_NODES] = N_EDGES;
            rowstartAll[(N_NODES + 1) + N_NODES] = N_EDGES;
        }
    }
    __syncthreads();
    int off = soff;
    int base = blk * SCAN_CHUNK + t * 4;
    #pragma unroll
    for (int i = 0; i < 4; i++) {
        int g = base + i;
        if (g < N_NODES) {
            int val = rowstart[g] + off;
            rowstart[g] = val;
            cursor[g]   = val;
        }
    }
}

__global__ void fill_kernel(const int* __restrict__ src1, const int* __restrict__ dst1,
                            const int* __restrict__ src2, const int* __restrict__ dst2,
                            int* __restrict__ cursorAll, int* __restrict__ csrAll)
{
    int idx = blockIdx.x * blockDim.x + threadIdx.x;
    if (idx < 2 * N_EDGES) {
        int br = idx >= N_EDGES;
        int e  = idx - br * N_EDGES;
        int d  = br ? dst2[e] : dst1[e];
        int s  = br ? src2[e] : src1[e];
        int p  = atomicAdd(&cursorAll[br * N_NODES + d], 1);
        csrAll[br * N_EDGES + p] = s;
    }
}

// ---------------------------------------------------------------------------
// Warp-per-node gather, both branches
// ---------------------------------------------------------------------------
__global__ __launch_bounds__(256)
void gather_kernel(const float* __restrict__ hWAll,
                   const int* __restrict__ rowstartAll,
                   const int* __restrict__ csrAll,
                   float* __restrict__ aggAll)
{
    int gn = (blockIdx.x * blockDim.x + threadIdx.x) >> 5;
    int lane = threadIdx.x & 31;
    if (gn >= 2 * N_NODES) return;
    int br   = gn >= N_NODES;
    int node = gn - br * N_NODES;
    const int*   rowstart = rowstartAll + br * (N_NODES + 1);
    const int*   csr      = csrAll + (size_t)br * N_EDGES;
    const float* hW       = hWAll  + (size_t)br * N_NODES * DFEAT;

    int beg = rowstart[node], end = rowstart[node + 1];
    float4 a0 = make_float4(0.f, 0.f, 0.f, 0.f);
    float4 a1 = make_float4(0.f, 0.f, 0.f, 0.f);
    float4 b0 = make_float4(0.f, 0.f, 0.f, 0.f);
    float4 b1 = make_float4(0.f, 0.f, 0.f, 0.f);
    int e = beg;
    for (; e + 1 < end; e += 2) {
        const float4* r0 = reinterpret_cast<const float4*>(hW + (size_t)csr[e]     * DFEAT);
        const float4* r1 = reinterpret_cast<const float4*>(hW + (size_t)csr[e + 1] * DFEAT);
        float4 u0 = r0[lane], u1 = r0[lane + 32];
        float4 v0 = r1[lane], v1 = r1[lane + 32];
        a0.x += u0.x; a0.y += u0.y; a0.z += u0.z; a0.w += u0.w;
        a1.x += u1.x; a1.y += u1.y; a1.z += u1.z; a1.w += u1.w;
        b0.x += v0.x; b0.y += v0.y; b0.z += v0.z; b0.w += v0.w;
        b1.x += v1.x; b1.y += v1.y; b1.z += v1.z; b1.w += v1.w;
    }
    if (e < end) {
        const float4* r0 = reinterpret_cast<const float4*>(hW + (size_t)csr[e] * DFEAT);
        float4 u0 = r0[lane], u1 = r0[lane + 32];
        a0.x += u0.x; a0.y += u0.y; a0.z += u0.z; a0.w += u0.w;
        a1.x += u1.x; a1.y += u1.y; a1.z += u1.z; a1.w += u1.w;
    }
    a0.x += b0.x; a0.y += b0.y; a0.z += b0.z; a0.w += b0.w;
    a1.x += b1.x; a1.y += b1.y; a1.z += b1.z; a1.w += b1.w;
    float4* out = reinterpret_cast<float4*>(aggAll + ((size_t)br * N_NODES + node) * DFEAT);
    out[lane]      = a0;
    out[lane + 32] = a1;
}

// ---------------------------------------------------------------------------
// Segment sum (sorted gid), both branches
// ---------------------------------------------------------------------------
__global__ __launch_bounds__(256)
void segsum_kernel(const float* __restrict__ h2All, const int* __restrict__ gid1,
                   const int* __restrict__ gid2,
                   float* __restrict__ TAll, int* __restrict__ countsAll)
{
    __shared__ int sb, se;
    int bidx = blockIdx.x;
    int br   = bidx >> 9;
    int g    = bidx & 511;
    const int* gid = br ? gid2 : gid1;
    const float* h2 = h2All + (size_t)br * N_NODES * DFEAT;
    if (threadIdx.x == 0) {
        int lo = 0, hi = N_NODES;
        while (lo < hi) { int m = (lo + hi) >> 1; if (gid[m] < g) lo = m + 1; else hi = m; }
        sb = lo;
        lo = sb; hi = N_NODES;
        while (lo < hi) { int m = (lo + hi) >> 1; if (gid[m] < g + 1) lo = m + 1; else hi = m; }
        se = lo;
        countsAll[br * N_GRAPHS + g] = se - sb;
    }
    __syncthreads();
    int beg = sb, end = se, c = threadIdx.x;
    float s = 0.f;
    for (int r = beg; r < end; r++)
        s += h2[(size_t)r * DFEAT + c];
    TAll[((size_t)br * N_GRAPHS + g) * DFEAT + c] = s;
}

// ---------------------------------------------------------------------------
// Fused readout + predictor
// ---------------------------------------------------------------------------
__global__ __launch_bounds__(256)
void readout_final(const float* __restrict__ TAll, const int* __restrict__ countsAll,
                   const float* __restrict__ Ro1, const float* __restrict__ rbo1,
                   const float* __restrict__ Ro2, const float* __restrict__ rbo2,
                   const float* __restrict__ Wp, const float* __restrict__ bp,
                   float* __restrict__ out)
{
    __shared__ float ts1[DFEAT], ts2[DFEAT];
    __shared__ float red[256];
    int g = blockIdx.x;
    int t = threadIdx.x;
    ts1[t] = TAll[(size_t)g * DFEAT + t];
    ts2[t] = TAll[((size_t)N_GRAPHS + g) * DFEAT + t];
    __syncthreads();
    float c1 = (float)countsAll[g];
    float c2 = (float)countsAll[N_GRAPHS + g];
    float partial = 0.f;
    if (t < G_FEAT) {
        float s = c1 * rbo1[t] + c2 * rbo2[t];
        #pragma unroll 8
        for (int k = 0; k < DFEAT; k++)
            s += ts1[k] * Ro1[(size_t)k * G_FEAT + t]
               + ts2[k] * Ro2[(size_t)k * G_FEAT + t];
        partial = s * Wp[t];
    }
    red[t] = partial;
    __syncthreads();
    #pragma unroll
    for (int st = 128; st > 0; st >>= 1) {
        if (t < st) red[t] += red[t + st];
        __syncthreads();
    }
    if (t == 0) out[g] = red[0] + bp[0];
}

// ---------------------------------------------------------------------------
extern "C" void kernel_launch(void* const* d_in, const int* in_sizes, int n_in,
                              void* d_out, int out_size)
{
    const float* nf1 = (const float*)d_in[0];
    const float* nf2 = (const float*)d_in[2];
    const int* src1 = (const int*)d_in[4];
    const int* dst1 = (const int*)d_in[5];
    const int* gid1 = (const int*)d_in[6];
    const int* src2 = (const int*)d_in[7];
    const int* dst2 = (const int*)d_in[8];
    const int* gid2 = (const int*)d_in[9];
    const float* W1  = (const float*)d_in[10]; const float* b1  = (const float*)d_in[11];
    const float* Wr1 = (const float*)d_in[12]; const float* br1 = (const float*)d_in[13];
    const float* W2  = (const float*)d_in[14]; const float* b2  = (const float*)d_in[15];
    const float* Wr2 = (const float*)d_in[16]; const float* br2 = (const float*)d_in[17];
    const float* Ri1 = (const float*)d_in[18]; const float* rbi1 = (const float*)d_in[19];
    const float* Ro1 = (const float*)d_in[20]; const float* rbo1 = (const float*)d_in[21];
    const float* Ri2 = (const float*)d_in[22]; const float* rbi2 = (const float*)d_in[23];
    const float* Ro2 = (const float*)d_in[24]; const float* rbo2 = (const float*)d_in[25];
    const float* Wp  = (const float*)d_in[26]; const float* bp   = (const float*)d_in[27];

    float *hW, *agg, *T;
    uint32_t *nfH, *nfL, *h1H, *h1L, *WH, *WL;
    int *counts, *deg, *rowstart, *cursor, *csr_src, *bsums;
    cudaGetSymbolAddress((void**)&hW,       g_hW);
    cudaGetSymbolAddress((void**)&agg,      g_agg);
    cudaGetSymbolAddress((void**)&nfH,      g_nfH);
    cudaGetSymbolAddress((void**)&nfL,      g_nfL);
    cudaGetSymbolAddress((void**)&h1H,      g_h1H);
    cudaGetSymbolAddress((void**)&h1L,      g_h1L);
    cudaGetSymbolAddress((void**)&WH,       g_WH);
    cudaGetSymbolAddress((void**)&WL,       g_WL);
    cudaGetSymbolAddress((void**)&T,        g_T);
    cudaGetSymbolAddress((void**)&counts,   g_counts);
    cudaGetSymbolAddress((void**)&deg,      g_deg);
    cudaGetSymbolAddress((void**)&rowstart, g_rowstart);
    cudaGetSymbolAddress((void**)&cursor,   g_cursor);
    cudaGetSymbolAddress((void**)&csr_src,  g_csr_src);
    cudaGetSymbolAddress((void**)&bsums,    g_bsums);

    cudaFuncSetAttribute(gemm_mma<0>, cudaFuncAttributeMaxDynamicSharedMemorySize, SMEM_BYTES);
    cudaFuncSetAttribute(gemm_mma<1>, cudaFuncAttributeMaxDynamicSharedMemorySize, SMEM_BYTES);
    cudaFuncSetAttribute(gemm_mma<2>, cudaFuncAttributeMaxDynamicSharedMemorySize, SMEM_BYTES);

    // Lazy second stream + events. First harness call is the (uncaptured)
    // correctness run, so these exist before graph capture begins. During
    // capture the fork/join events become graph edges (documented pattern).
    static cudaStream_t s_s2 = nullptr;
    static cudaEvent_t  s_evF = nullptr, s_evJ = nullptr;
    static bool s_tried = false;
    if (!s_tried) {
        s_tried = true;
        if (cudaStreamCreateWithFlags(&s_s2, cudaStreamNonBlocking) != cudaSuccess)
            s_s2 = nullptr;
        if (s_s2) {
            if (cudaEventCreateWithFlags(&s_evF, cudaEventDisableTiming) != cudaSuccess ||
                cudaEventCreateWithFlags(&s_evJ, cudaEventDisableTiming) != cudaSuccess) {
                s_s2 = nullptr;   // fall back to fully serial
            }
        }
    }
    cudaStream_t s2 = s_s2 ? s_s2 : (cudaStream_t)0;

    float* hW1  = hW;   float* hW2  = hW  + (size_t)N_NODES * DFEAT;
    float* agg1 = agg;  float* agg2 = agg + (size_t)N_NODES * DFEAT;
    uint32_t* nfH1 = nfH; uint32_t* nfH2 = nfH + (size_t)NW;
    uint32_t* nfL1 = nfL; uint32_t* nfL2 = nfL + (size_t)NW;
    uint32_t* h1H1 = h1H; uint32_t* h1H2 = h1H + (size_t)NW;
    uint32_t* h1L1 = h1L; uint32_t* h1L2 = h1L + (size_t)NW;
    uint32_t* WH_ = WH;  uint32_t* WL_ = WL;
    const int WSZ = 128 * 256;

    dim3 gemm_grid((N_NODES + 127) / 128, 2, 2);   // 391 x 2 x 2
    int eb2 = (2 * N_EDGES + 255) / 256;

    // ---- fork: CSR chain on s2, conv+GEMM0 on default stream ----
    if (s_s2) {
        cudaEventRecord(s_evF, 0);
        cudaStreamWaitEvent(s_s2, s_evF, 0);
    }
    cudaMemsetAsync(deg, 0, 2 * N_NODES * sizeof(int), s2);
    hist_kernel<<<eb2, 256, 0, s2>>>(dst1, dst2, deg);
    scan1_kernel<<<2 * SCAN_BLKS, 256, 0, s2>>>(deg, rowstart, bsums);
    scan2_kernel<<<2 * SCAN_BLKS, 256, 0, s2>>>(bsums, rowstart, cursor);
    fill_kernel<<<eb2, 256, 0, s2>>>(src1, dst1, src2, dst2, cursor, csr_src);
    if (s_s2) cudaEventRecord(s_evJ, s_s2);

    conv_nf<<<(int)((2 * (size_t)NW + 255) / 256), 256>>>(nf1, nf2, nfH, nfL);
    conv_W<<<(6 * 128 * 256 + 255) / 256, 256>>>(W1, Wr1, Ri1, W2, Wr2, Ri2, WH, WL);

    // hW = h @ W (both branches)
    gemm_mma<0><<<gemm_grid, 256, SMEM_BYTES>>>(
        nfH1, nfL1, nfH2, nfL2,
        WH_ + 0 * WSZ, WL_ + 0 * WSZ, WH_ + 3 * WSZ, WL_ + 3 * WSZ,
        nullptr, nullptr, nullptr, nullptr, nullptr, nullptr,
        hW1, hW2, nullptr, nullptr, nullptr, nullptr, N_NODES);

    // ---- join: gather needs both GEMM0 (stream 0) and fill (s2) ----
    if (s_s2) cudaStreamWaitEvent((cudaStream_t)0, s_evJ, 0);

    // agg = gather-sum of hW rows
    gather_kernel<<<(2 * N_NODES * 32 + 255) / 256, 256>>>(hW, rowstart, csr_src, agg);
    // h1 = relu(agg + b) + relu(h @ Wr + br)  -> split output
    gemm_mma<1><<<gemm_grid, 256, SMEM_BYTES>>>(
        nfH1, nfL1, nfH2, nfL2,
        WH_ + 1 * WSZ, WL_ + 1 * WSZ, WH_ + 4 * WSZ, WL_ + 4 * WSZ,
        br1, br2, agg1, agg2, b1, b2,
        nullptr, nullptr, h1H1, h1L1, h1H2, h1L2, N_NODES);
    // h2 = relu(h1 @ Ri + rbi) -> fp32 (reuse hW buffers)
    gemm_mma<2><<<gemm_grid, 256, SMEM_BYTES>>>(
        h1H1, h1L1, h1H2, h1L2,
        WH_ + 2 * WSZ, WL_ + 2 * WSZ, WH_ + 5 * WSZ, WL_ + 5 * WSZ,
        rbi1, rbi2, nullptr, nullptr, nullptr, nullptr,
        hW1, hW2, nullptr, nullptr, nullptr, nullptr, N_NODES);
    // T[g] = segsum of h2 rows; counts
    segsum_kernel<<<2 * N_GRAPHS, 256>>>(hW, gid1, gid2, T, counts);
    // fused readout + predictor
    readout_final<<<N_GRAPHS, 256>>>(T, counts, Ro1, rbo1, Ro2, rbo2, Wp, bp,
                                     (float*)d_out);
}

// round 9
// speedup vs baseline: 3.2868x; 1.0413x over previous
#include <cuda_runtime.h>
#include <cuda_bf16.h>
#include <cstdint>
#include <cstddef>

// ---------------------------------------------------------------------------
// mulGCN: two-branch GCN forward, split-bf16 mma.sync GEMMs with pre-split
// operands + cp.async double-buffered pipeline. Multi-block CSR scan.
// R9: full two-branch software pipeline across two streams — branch 1 on
// stream 0, branch 2 on s2; gather (L2-bound) of one branch overlaps the
// GEMMs (tensor-bound) of the other.
// Split-bf16: x = hi(trunc bf16, exact) + lo(bf16 rn of remainder);
// A@B ~= AhiBhi + AhiBlo + AloBhi, fp32 accum -> ~2e-5 rel error.
// ---------------------------------------------------------------------------

#define N_NODES   50000
#define N_EDGES   800000
#define DFEAT     256
#define G_FEAT    200
#define N_GRAPHS  512

#define NW   (N_NODES * 128)          // words per branch for split arrays

#define SCAN_BLKS   49                // ceil(50000/1024)
#define SCAN_CHUNK  1024

__device__ float    g_hW  [2][(size_t)N_NODES * DFEAT];   // reused as h2
__device__ float    g_agg [2][(size_t)N_NODES * DFEAT];
__device__ uint32_t g_nfH [2][(size_t)NW];
__device__ uint32_t g_nfL [2][(size_t)NW];
__device__ uint32_t g_h1H [2][(size_t)NW];
__device__ uint32_t g_h1L [2][(size_t)NW];
__device__ uint32_t g_WH  [6][128 * 256];
__device__ uint32_t g_WL  [6][128 * 256];
__device__ float    g_T   [2][N_GRAPHS * DFEAT];
__device__ int      g_counts  [2][N_GRAPHS];
__device__ int      g_deg     [2][N_NODES];
__device__ int      g_rowstart[2][N_NODES + 1];
__device__ int      g_cursor  [2][N_NODES];
__device__ int      g_csr_src [2][N_EDGES];
__device__ int      g_bsums   [2 * SCAN_BLKS];

__device__ __forceinline__ float frelu(float x) { return x > 0.f ? x : 0.f; }

// ------------------------- mma / pack helpers ------------------------------
__device__ __forceinline__ void mma16816(float* c, const uint32_t* a,
                                         uint32_t b0, uint32_t b1) {
    asm volatile(
        "mma.sync.aligned.m16n8k16.row.col.f32.bf16.bf16.f32 "
        "{%0,%1,%2,%3}, {%4,%5,%6,%7}, {%8,%9}, {%0,%1,%2,%3};\n"
        : "+f"(c[0]), "+f"(c[1]), "+f"(c[2]), "+f"(c[3])
        : "r"(a[0]), "r"(a[1]), "r"(a[2]), "r"(a[3]), "r"(b0), "r"(b1));
}

__device__ __forceinline__ uint32_t pack_hi(float x, float y) {
    return __byte_perm(__float_as_uint(x), __float_as_uint(y), 0x7632);
}
__device__ __forceinline__ uint32_t pack_lo(float x, float y) {
    float hx = __uint_as_float(__float_as_uint(x) & 0xFFFF0000u);
    float hy = __uint_as_float(__float_as_uint(y) & 0xFFFF0000u);
    __nv_bfloat162 t;
    t.x = __float2bfloat16(x - hx);
    t.y = __float2bfloat16(y - hy);
    return *reinterpret_cast<uint32_t*>(&t);
}

// ------------------------- cp.async helpers --------------------------------
__device__ __forceinline__ void cp16(uint32_t dst, const void* src) {
    asm volatile("cp.async.cg.shared.global [%0], [%1], 16;"
                 :: "r"(dst), "l"(src));
}
__device__ __forceinline__ void cp16z(uint32_t dst, const void* src, bool ok) {
    int b = ok ? 16 : 0;
    asm volatile("cp.async.cg.shared.global [%0], [%1], 16, %2;"
                 :: "r"(dst), "l"(src), "r"(b));
}
#define CP_COMMIT()  asm volatile("cp.async.commit_group;" ::: "memory")
#define CP_WAIT1()   asm volatile("cp.async.wait_group 1;" ::: "memory")
#define CP_WAIT0()   asm volatile("cp.async.wait_group 0;" ::: "memory")

// SMEM words per buffer: AH[128][20] AL[128][20] BH[16][136] BL[16][136]
static constexpr int W_AH = 0, W_AL = 2560, W_BH = 5120, W_BL = 7296;
static constexpr int WBUF = 9472;
static constexpr int SMEM_BYTES = 2 * WBUF * 4;        // 75776

__device__ __forceinline__ void cpA(uint32_t sb, const uint32_t* __restrict__ AH,
                                    const uint32_t* __restrict__ AL,
                                    int M, int rowBase, int c, int tid)
{
    #pragma unroll
    for (int t = 0; t < 4; t++) {
        int idx = tid + t * 256;          // 0..1023
        int r   = idx >> 3;
        int seg = idx & 7;                // 0..7 (0-3 hi, 4-7 lo)
        int row = rowBase + r;
        bool ok = row < M;
        int rowc = ok ? row : 0;
        int s4 = (seg & 3) * 4;
        const uint32_t* src = (seg < 4 ? AH : AL) + (size_t)rowc * 128 + c * 16 + s4;
        uint32_t dst = sb + ((seg < 4 ? W_AH : W_AL) + r * 20 + s4) * 4;
        cp16z(dst, src, ok);
    }
}

__device__ __forceinline__ void cpB(uint32_t sb, const uint32_t* __restrict__ WH,
                                    const uint32_t* __restrict__ WL,
                                    int colBase, int c, int tid)
{
    #pragma unroll
    for (int t = 0; t < 4; t++) {
        int idx  = tid + t * 256;         // 0..1023
        int kp   = idx >> 6;              // 0..15
        int rest = idx & 63;
        int arr  = rest >> 5;             // 0 hi, 1 lo
        int s4   = (rest & 31) * 4;
        const uint32_t* src = (arr ? WL : WH) + (size_t)(c * 16 + kp) * 256 + colBase + s4;
        uint32_t dst = sb + ((arr ? W_BL : W_BH) + kp * 136 + s4) * 4;
        cp16(dst, src);
    }
}

// ---------------------------------------------------------------------------
// mma GEMM (single branch): 256 threads, 8 warps (4m x 2n), warp tile 32x64.
// Grid (ceil(M/128), 2).
// MODE 0: C fp32 = acc
// MODE 1: CH/CL split = pack(relu(acc+bias)+relu(agg+bagg))
// MODE 2: C fp32 = relu(acc+bias)
// ---------------------------------------------------------------------------
template<int MODE>
__global__ __launch_bounds__(256, 2)
void gemm_mma(const uint32_t* __restrict__ AH, const uint32_t* __restrict__ AL,
              const uint32_t* __restrict__ WH, const uint32_t* __restrict__ WL,
              const float* __restrict__ bias,
              const float* __restrict__ agg,
              const float* __restrict__ bagg,
              float* __restrict__ C,
              uint32_t* __restrict__ CH, uint32_t* __restrict__ CL,
              int M)
{
    extern __shared__ uint32_t sm[];
    const int tid  = threadIdx.x;
    const int lane = tid & 31;
    const int wid  = tid >> 5;
    const int wm   = wid & 3;
    const int wn   = wid >> 2;
    const int gid  = lane >> 2;
    const int tig  = lane & 3;
    const int rowBase = blockIdx.x * 128;
    const int colBase = blockIdx.y * 128;

    uint32_t sbase;
    {
        uint64_t a = __cvta_generic_to_shared(sm);
        sbase = (uint32_t)a;
    }

    float acc[2][8][4];
    #pragma unroll
    for (int mt = 0; mt < 2; mt++)
        #pragma unroll
        for (int nt = 0; nt < 8; nt++)
            #pragma unroll
            for (int q = 0; q < 4; q++) acc[mt][nt][q] = 0.f;

    cpA(sbase, AH, AL, M, rowBase, 0, tid);
    cpB(sbase, WH, WL, colBase, 0, tid);
    CP_COMMIT();

    #pragma unroll
    for (int c = 0; c < 8; c++) {
        if (c < 7) {
            uint32_t nb = sbase + ((c + 1) & 1) * WBUF * 4;
            cpA(nb, AH, AL, M, rowBase, c + 1, tid);
            cpB(nb, WH, WL, colBase, c + 1, tid);
            CP_COMMIT();
            CP_WAIT1();
        } else {
            CP_WAIT0();
        }
        __syncthreads();

        const uint32_t* buf = sm + (c & 1) * WBUF;
        const uint32_t* sAH = buf + W_AH;
        const uint32_t* sAL = buf + W_AL;
        const uint32_t* sBH = buf + W_BH;
        const uint32_t* sBL = buf + W_BL;

        #pragma unroll
        for (int ks = 0; ks < 2; ks++) {
            uint32_t aH[2][4], aL[2][4];
            #pragma unroll
            for (int mt = 0; mt < 2; mt++) {
                int off = (wm * 32 + mt * 16 + gid) * 20 + ks * 8 + tig;
                aH[mt][0] = sAH[off];       aH[mt][1] = sAH[off + 160];
                aH[mt][2] = sAH[off + 4];   aH[mt][3] = sAH[off + 164];
                aL[mt][0] = sAL[off];       aL[mt][1] = sAL[off + 160];
                aL[mt][2] = sAL[off + 4];   aL[mt][3] = sAL[off + 164];
            }
            #pragma unroll
            for (int nt = 0; nt < 8; nt++) {
                int bi = (ks * 8 + tig) * 136 + wn * 64 + nt * 8 + gid;
                uint32_t bh0 = sBH[bi], bh1 = sBH[bi + 544];
                uint32_t bl0 = sBL[bi], bl1 = sBL[bi + 544];
                #pragma unroll
                for (int mt = 0; mt < 2; mt++) {
                    mma16816(acc[mt][nt], aH[mt], bh0, bh1);
                    mma16816(acc[mt][nt], aH[mt], bl0, bl1);
                    mma16816(acc[mt][nt], aL[mt], bh0, bh1);
                }
            }
        }
        __syncthreads();
    }

    // ------------------------------ epilogue -------------------------------
    #pragma unroll
    for (int mt = 0; mt < 2; mt++) {
        #pragma unroll
        for (int nt = 0; nt < 8; nt++) {
            int r0  = rowBase + wm * 32 + mt * 16 + gid;
            int r1  = r0 + 8;
            int col = colBase + wn * 64 + nt * 8 + 2 * tig;
            float* a4 = acc[mt][nt];
            if (MODE == 0) {
                if (r0 < M)
                    *reinterpret_cast<float2*>(C + (size_t)r0 * 256 + col) =
                        make_float2(a4[0], a4[1]);
                if (r1 < M)
                    *reinterpret_cast<float2*>(C + (size_t)r1 * 256 + col) =
                        make_float2(a4[2], a4[3]);
            } else if (MODE == 1) {
                float2 bs = *reinterpret_cast<const float2*>(bias + col);
                float2 ba = *reinterpret_cast<const float2*>(bagg + col);
                if (r0 < M) {
                    float2 ag = *reinterpret_cast<const float2*>(agg + (size_t)r0 * 256 + col);
                    float v0 = frelu(a4[0] + bs.x) + frelu(ag.x + ba.x);
                    float v1 = frelu(a4[1] + bs.y) + frelu(ag.y + ba.y);
                    CH[(size_t)r0 * 128 + (col >> 1)] = pack_hi(v0, v1);
                    CL[(size_t)r0 * 128 + (col >> 1)] = pack_lo(v0, v1);
                }
                if (r1 < M) {
                    float2 ag = *reinterpret_cast<const float2*>(agg + (size_t)r1 * 256 + col);
                    float v0 = frelu(a4[2] + bs.x) + frelu(ag.x + ba.x);
                    float v1 = frelu(a4[3] + bs.y) + frelu(ag.y + ba.y);
                    CH[(size_t)r1 * 128 + (col >> 1)] = pack_hi(v0, v1);
                    CL[(size_t)r1 * 128 + (col >> 1)] = pack_lo(v0, v1);
                }
            } else {
                float2 bs = *reinterpret_cast<const float2*>(bias + col);
                if (r0 < M)
                    *reinterpret_cast<float2*>(C + (size_t)r0 * 256 + col) =
                        make_float2(frelu(a4[0] + bs.x), frelu(a4[1] + bs.y));
                if (r1 < M)
                    *reinterpret_cast<float2*>(C + (size_t)r1 * 256 + col) =
                        make_float2(frelu(a4[2] + bs.x), frelu(a4[3] + bs.y));
            }
        }
    }
}

// ---------------------------------------------------------------------------
// Conversion kernels
// ---------------------------------------------------------------------------
__global__ __launch_bounds__(256)
void conv_nf(const float* __restrict__ n1, const float* __restrict__ n2,
             uint32_t* __restrict__ H, uint32_t* __restrict__ L)
{
    size_t idx = (size_t)blockIdx.x * blockDim.x + threadIdx.x;
    if (idx >= 2 * (size_t)NW) return;
    int br = idx >= (size_t)NW;
    size_t w = idx - (size_t)br * NW;
    const float* nf = br ? n2 : n1;
    float2 v = *reinterpret_cast<const float2*>(nf + w * 2);
    H[idx] = pack_hi(v.x, v.y);
    L[idx] = pack_lo(v.x, v.y);
}

__global__ __launch_bounds__(256)
void conv_W(const float* __restrict__ m0, const float* __restrict__ m1,
            const float* __restrict__ m2, const float* __restrict__ m3,
            const float* __restrict__ m4, const float* __restrict__ m5,
            uint32_t* __restrict__ WH, uint32_t* __restrict__ WL)
{
    int idx = blockIdx.x * blockDim.x + threadIdx.x;
    if (idx >= 6 * 128 * 256) return;
    int m    = idx >> 15;
    int rest = idx & 32767;
    int k2   = rest >> 8;
    int n    = rest & 255;
    const float* Wm = (m == 0) ? m0 : (m == 1) ? m1 : (m == 2) ? m2
                    : (m == 3) ? m3 : (m == 4) ? m4 : m5;
    float a = Wm[(size_t)(2 * k2) * 256 + n];
    float b = Wm[(size_t)(2 * k2 + 1) * 256 + n];
    WH[idx] = pack_hi(a, b);
    WL[idx] = pack_lo(a, b);
}

// ---------------------------------------------------------------------------
// CSR build, both branches (runs on s2, overlapped)
// ---------------------------------------------------------------------------
__global__ void hist_kernel(const int* __restrict__ dst1, const int* __restrict__ dst2,
                            int* __restrict__ deg)
{
    int idx = blockIdx.x * blockDim.x + threadIdx.x;
    if (idx < 2 * N_EDGES) {
        int br = idx >= N_EDGES;
        int e  = idx - br * N_EDGES;
        int d  = br ? dst2[e] : dst1[e];
        atomicAdd(&deg[br * N_NODES + d], 1);
    }
}

__global__ __launch_bounds__(256)
void scan1_kernel(const int* __restrict__ degAll, int* __restrict__ rowstartAll,
                  int* __restrict__ bsums)
{
    __shared__ int wsum[8];
    int br  = blockIdx.x / SCAN_BLKS;
    int blk = blockIdx.x % SCAN_BLKS;
    int t = threadIdx.x, lane = t & 31, w = t >> 5;
    const int* deg = degAll + br * N_NODES;
    int* rowstart  = rowstartAll + br * (N_NODES + 1);

    int base = blk * SCAN_CHUNK + t * 4;
    int v[4];
    #pragma unroll
    for (int i = 0; i < 4; i++)
        v[i] = (base + i < N_NODES) ? deg[base + i] : 0;
    int s = v[0] + v[1] + v[2] + v[3];

    int x = s;
    #pragma unroll
    for (int o = 1; o < 32; o <<= 1) {
        int n = __shfl_up_sync(0xFFFFFFFFu, x, o);
        if (lane >= o) x += n;
    }
    if (lane == 31) wsum[w] = x;
    __syncthreads();
    if (w == 0 && lane < 8) {
        int y = wsum[lane];
        #pragma unroll
        for (int o = 1; o < 8; o <<= 1) {
            int n = __shfl_up_sync(0xFFu, y, o);
            if (lane >= o) y += n;
        }
        wsum[lane] = y;
    }
    __syncthreads();
    int excl = x - s + (w > 0 ? wsum[w - 1] : 0);

    int run = excl;
    #pragma unroll
    for (int i = 0; i < 4; i++) {
        if (base + i < N_NODES) rowstart[base + i] = run;
        run += v[i];
    }
    if (t == 255) bsums[br * SCAN_BLKS + blk] = wsum[7];
}

__global__ __launch_bounds__(256)
void scan2_kernel(const int* __restrict__ bsums, int* __restrict__ rowstartAll,
                  int* __restrict__ cursorAll)
{
    __shared__ int soff;
    int br  = blockIdx.x / SCAN_BLKS;
    int blk = blockIdx.x % SCAN_BLKS;
    int t = threadIdx.x;
    int* rowstart = rowstartAll + br * (N_NODES + 1);
    int* cursor   = cursorAll   + br * N_NODES;

    if (t == 0) {
        int off = 0;
        for (int j = 0; j < blk; j++) off += bsums[br * SCAN_BLKS + j];
        soff = off;
        if (blockIdx.x == 0) {
            rowstartAll[N_NODES] = N_EDGES;
            rowstartAll[(N_NODES + 1) + N_NODES] = N_EDGES;
        }
    }
    __syncthreads();
    int off = soff;
    int base = blk * SCAN_CHUNK + t * 4;
    #pragma unroll
    for (int i = 0; i < 4; i++) {
        int g = base + i;
        if (g < N_NODES) {
            int val = rowstart[g] + off;
            rowstart[g] = val;
            cursor[g]   = val;
        }
    }
}

__global__ void fill_kernel(const int* __restrict__ src1, const int* __restrict__ dst1,
                            const int* __restrict__ src2, const int* __restrict__ dst2,
                            int* __restrict__ cursorAll, int* __restrict__ csrAll)
{
    int idx = blockIdx.x * blockDim.x + threadIdx.x;
    if (idx < 2 * N_EDGES) {
        int br = idx >= N_EDGES;
        int e  = idx - br * N_EDGES;
        int d  = br ? dst2[e] : dst1[e];
        int s  = br ? src2[e] : src1[e];
        int p  = atomicAdd(&cursorAll[br * N_NODES + d], 1);
        csrAll[br * N_EDGES + p] = s;
    }
}

// ---------------------------------------------------------------------------
// Warp-per-node gather (single branch)
// ---------------------------------------------------------------------------
__global__ __launch_bounds__(256)
void gather_kernel(const float* __restrict__ hW,
                   const int* __restrict__ rowstart,
                   const int* __restrict__ csr,
                   float* __restrict__ agg)
{
    int node = (blockIdx.x * blockDim.x + threadIdx.x) >> 5;
    int lane = threadIdx.x & 31;
    if (node >= N_NODES) return;

    int beg = rowstart[node], end = rowstart[node + 1];
    float4 a0 = make_float4(0.f, 0.f, 0.f, 0.f);
    float4 a1 = make_float4(0.f, 0.f, 0.f, 0.f);
    float4 b0 = make_float4(0.f, 0.f, 0.f, 0.f);
    float4 b1 = make_float4(0.f, 0.f, 0.f, 0.f);
    int e = beg;
    for (; e + 1 < end; e += 2) {
        const float4* r0 = reinterpret_cast<const float4*>(hW + (size_t)csr[e]     * DFEAT);
        const float4* r1 = reinterpret_cast<const float4*>(hW + (size_t)csr[e + 1] * DFEAT);
        float4 u0 = r0[lane], u1 = r0[lane + 32];
        float4 v0 = r1[lane], v1 = r1[lane + 32];
        a0.x += u0.x; a0.y += u0.y; a0.z += u0.z; a0.w += u0.w;
        a1.x += u1.x; a1.y += u1.y; a1.z += u1.z; a1.w += u1.w;
        b0.x += v0.x; b0.y += v0.y; b0.z += v0.z; b0.w += v0.w;
        b1.x += v1.x; b1.y += v1.y; b1.z += v1.z; b1.w += v1.w;
    }
    if (e < end) {
        const float4* r0 = reinterpret_cast<const float4*>(hW + (size_t)csr[e] * DFEAT);
        float4 u0 = r0[lane], u1 = r0[lane + 32];
        a0.x += u0.x; a0.y += u0.y; a0.z += u0.z; a0.w += u0.w;
        a1.x += u1.x; a1.y += u1.y; a1.z += u1.z; a1.w += u1.w;
    }
    a0.x += b0.x; a0.y += b0.y; a0.z += b0.z; a0.w += b0.w;
    a1.x += b1.x; a1.y += b1.y; a1.z += b1.z; a1.w += b1.w;
    float4* out = reinterpret_cast<float4*>(agg + (size_t)node * DFEAT);
    out[lane]      = a0;
    out[lane + 32] = a1;
}

// ---------------------------------------------------------------------------
// Segment sum (sorted gid), single branch
// ---------------------------------------------------------------------------
__global__ __launch_bounds__(256)
void segsum_kernel(const float* __restrict__ h2, const int* __restrict__ gid,
                   float* __restrict__ T, int* __restrict__ counts)
{
    __shared__ int sb, se;
    int g = blockIdx.x;
    if (threadIdx.x == 0) {
        int lo = 0, hi = N_NODES;
        while (lo < hi) { int m = (lo + hi) >> 1; if (gid[m] < g) lo = m + 1; else hi = m; }
        sb = lo;
        lo = sb; hi = N_NODES;
        while (lo < hi) { int m = (lo + hi) >> 1; if (gid[m] < g + 1) lo = m + 1; else hi = m; }
        se = lo;
        counts[g] = se - sb;
    }
    __syncthreads();
    int beg = sb, end = se, c = threadIdx.x;
    float s = 0.f;
    for (int r = beg; r < end; r++)
        s += h2[(size_t)r * DFEAT + c];
    T[(size_t)g * DFEAT + c] = s;
}

// ---------------------------------------------------------------------------
// Fused readout + predictor
// ---------------------------------------------------------------------------
__global__ __launch_bounds__(256)
void readout_final(const float* __restrict__ TAll, const int* __restrict__ countsAll,
                   const float* __restrict__ Ro1, const float* __restrict__ rbo1,
                   const float* __restrict__ Ro2, const float* __restrict__ rbo2,
                   const float* __restrict__ Wp, const float* __restrict__ bp,
                   float* __restrict__ out)
{
    __shared__ float ts1[DFEAT], ts2[DFEAT];
    __shared__ float red[256];
    int g = blockIdx.x;
    int t = threadIdx.x;
    ts1[t] = TAll[(size_t)g * DFEAT + t];
    ts2[t] = TAll[((size_t)N_GRAPHS + g) * DFEAT + t];
    __syncthreads();
    float c1 = (float)countsAll[g];
    float c2 = (float)countsAll[N_GRAPHS + g];
    float partial = 0.f;
    if (t < G_FEAT) {
        float s = c1 * rbo1[t] + c2 * rbo2[t];
        #pragma unroll 8
        for (int k = 0; k < DFEAT; k++)
            s += ts1[k] * Ro1[(size_t)k * G_FEAT + t]
               + ts2[k] * Ro2[(size_t)k * G_FEAT + t];
        partial = s * Wp[t];
    }
    red[t] = partial;
    __syncthreads();
    #pragma unroll
    for (int st = 128; st > 0; st >>= 1) {
        if (t < st) red[t] += red[t + st];
        __syncthreads();
    }
    if (t == 0) out[g] = red[0] + bp[0];
}

// ---------------------------------------------------------------------------
extern "C" void kernel_launch(void* const* d_in, const int* in_sizes, int n_in,
                              void* d_out, int out_size)
{
    const float* nf1 = (const float*)d_in[0];
    const float* nf2 = (const float*)d_in[2];
    const int* src1 = (const int*)d_in[4];
    const int* dst1 = (const int*)d_in[5];
    const int* gid1 = (const int*)d_in[6];
    const int* src2 = (const int*)d_in[7];
    const int* dst2 = (const int*)d_in[8];
    const int* gid2 = (const int*)d_in[9];
    const float* W1  = (const float*)d_in[10]; const float* b1  = (const float*)d_in[11];
    const float* Wr1 = (const float*)d_in[12]; const float* br1 = (const float*)d_in[13];
    const float* W2  = (const float*)d_in[14]; const float* b2  = (const float*)d_in[15];
    const float* Wr2 = (const float*)d_in[16]; const float* br2 = (const float*)d_in[17];
    const float* Ri1 = (const float*)d_in[18]; const float* rbi1 = (const float*)d_in[19];
    const float* Ro1 = (const float*)d_in[20]; const float* rbo1 = (const float*)d_in[21];
    const float* Ri2 = (const float*)d_in[22]; const float* rbi2 = (const float*)d_in[23];
    const float* Ro2 = (const float*)d_in[24]; const float* rbo2 = (const float*)d_in[25];
    const float* Wp  = (const float*)d_in[26]; const float* bp   = (const float*)d_in[27];

    float *hW, *agg, *T;
    uint32_t *nfH, *nfL, *h1H, *h1L, *WH, *WL;
    int *counts, *deg, *rowstart, *cursor, *csr_src, *bsums;
    cudaGetSymbolAddress((void**)&hW,       g_hW);
    cudaGetSymbolAddress((void**)&agg,      g_agg);
    cudaGetSymbolAddress((void**)&nfH,      g_nfH);
    cudaGetSymbolAddress((void**)&nfL,      g_nfL);
    cudaGetSymbolAddress((void**)&h1H,      g_h1H);
    cudaGetSymbolAddress((void**)&h1L,      g_h1L);
    cudaGetSymbolAddress((void**)&WH,       g_WH);
    cudaGetSymbolAddress((void**)&WL,       g_WL);
    cudaGetSymbolAddress((void**)&T,        g_T);
    cudaGetSymbolAddress((void**)&counts,   g_counts);
    cudaGetSymbolAddress((void**)&deg,      g_deg);
    cudaGetSymbolAddress((void**)&rowstart, g_rowstart);
    cudaGetSymbolAddress((void**)&cursor,   g_cursor);
    cudaGetSymbolAddress((void**)&csr_src,  g_csr_src);
    cudaGetSymbolAddress((void**)&bsums,    g_bsums);

    cudaFuncSetAttribute(gemm_mma<0>, cudaFuncAttributeMaxDynamicSharedMemorySize, SMEM_BYTES);
    cudaFuncSetAttribute(gemm_mma<1>, cudaFuncAttributeMaxDynamicSharedMemorySize, SMEM_BYTES);
    cudaFuncSetAttribute(gemm_mma<2>, cudaFuncAttributeMaxDynamicSharedMemorySize, SMEM_BYTES);

    // Lazy second stream + events (created on the first, uncaptured, call).
    static cudaStream_t s_s2 = nullptr;
    static cudaEvent_t  s_evF = nullptr, s_evCSR = nullptr, s_evConv = nullptr,
                        s_evJ = nullptr;
    static bool s_tried = false;
    if (!s_tried) {
        s_tried = true;
        if (cudaStreamCreateWithFlags(&s_s2, cudaStreamNonBlocking) != cudaSuccess)
            s_s2 = nullptr;
        if (s_s2) {
            if (cudaEventCreateWithFlags(&s_evF,   cudaEventDisableTiming) != cudaSuccess ||
                cudaEventCreateWithFlags(&s_evCSR, cudaEventDisableTiming) != cudaSuccess ||
                cudaEventCreateWithFlags(&s_evConv,cudaEventDisableTiming) != cudaSuccess ||
                cudaEventCreateWithFlags(&s_evJ,   cudaEventDisableTiming) != cudaSuccess) {
                s_s2 = nullptr;   // fall back to fully serial on stream 0
            }
        }
    }
    cudaStream_t s0 = (cudaStream_t)0;
    cudaStream_t s2 = s_s2 ? s_s2 : s0;

    float* hW1  = hW;   float* hW2  = hW  + (size_t)N_NODES * DFEAT;
    float* agg1 = agg;  float* agg2 = agg + (size_t)N_NODES * DFEAT;
    float* T1   = T;    float* T2   = T   + (size_t)N_GRAPHS * DFEAT;
    int* counts1 = counts;  int* counts2 = counts + N_GRAPHS;
    uint32_t* nfH1 = nfH; uint32_t* nfH2 = nfH + (size_t)NW;
    uint32_t* nfL1 = nfL; uint32_t* nfL2 = nfL + (size_t)NW;
    uint32_t* h1H1 = h1H; uint32_t* h1H2 = h1H + (size_t)NW;
    uint32_t* h1L1 = h1L; uint32_t* h1L2 = h1L + (size_t)NW;
    const int* rs1 = rowstart;              const int* rs2 = rowstart + (N_NODES + 1);
    const int* cs1 = csr_src;               const int* cs2 = csr_src + N_EDGES;
    uint32_t* WH_ = WH;  uint32_t* WL_ = WL;
    const int WSZ = 128 * 256;   // slots: 0=W1 1=Wr1 2=Ri1 3=W2 4=Wr2 5=Ri2

    dim3 gemm_grid((N_NODES + 127) / 128, 2);       // per-branch: 391 x 2
    int eb2 = (2 * N_EDGES + 255) / 256;
    int gat_blocks = (N_NODES * 32 + 255) / 256;

    // ---- fork ----
    if (s_s2) {
        cudaEventRecord(s_evF, s0);
        cudaStreamWaitEvent(s_s2, s_evF, 0);
    }

    // s2: CSR chain (both branches)
    cudaMemsetAsync(deg, 0, 2 * N_NODES * sizeof(int), s2);
    hist_kernel<<<eb2, 256, 0, s2>>>(dst1, dst2, deg);
    scan1_kernel<<<2 * SCAN_BLKS, 256, 0, s2>>>(deg, rowstart, bsums);
    scan2_kernel<<<2 * SCAN_BLKS, 256, 0, s2>>>(bsums, rowstart, cursor);
    fill_kernel<<<eb2, 256, 0, s2>>>(src1, dst1, src2, dst2, cursor, csr_src);
    if (s_s2) cudaEventRecord(s_evCSR, s_s2);

    // s0: conversions (both branches + all weights)
    conv_nf<<<(int)((2 * (size_t)NW + 255) / 256), 256, 0, s0>>>(nf1, nf2, nfH, nfL);
    conv_W<<<(6 * 128 * 256 + 255) / 256, 256, 0, s0>>>(W1, Wr1, Ri1, W2, Wr2, Ri2,
                                                        WH, WL);
    if (s_s2) cudaEventRecord(s_evConv, s0);

    // s0: branch-1 chain
    gemm_mma<0><<<gemm_grid, 256, SMEM_BYTES, s0>>>(
        nfH1, nfL1, WH_ + 0 * WSZ, WL_ + 0 * WSZ,
        nullptr, nullptr, nullptr, hW1, nullptr, nullptr, N_NODES);
    if (s_s2) cudaStreamWaitEvent(s0, s_evCSR, 0);
    gather_kernel<<<gat_blocks, 256, 0, s0>>>(hW1, rs1, cs1, agg1);
    gemm_mma<1><<<gemm_grid, 256, SMEM_BYTES, s0>>>(
        nfH1, nfL1, WH_ + 1 * WSZ, WL_ + 1 * WSZ,
        br1, agg1, b1, nullptr, h1H1, h1L1, N_NODES);
    gemm_mma<2><<<gemm_grid, 256, SMEM_BYTES, s0>>>(
        h1H1, h1L1, WH_ + 2 * WSZ, WL_ + 2 * WSZ,
        rbi1, nullptr, nullptr, hW1, nullptr, nullptr, N_NODES);
    segsum_kernel<<<N_GRAPHS, 256, 0, s0>>>(hW1, gid1, T1, counts1);

    // s2: branch-2 chain (needs conv for weights/features)
    if (s_s2) cudaStreamWaitEvent(s_s2, s_evConv, 0);
    gemm_mma<0><<<gemm_grid, 256, SMEM_BYTES, s2>>>(
        nfH2, nfL2, WH_ + 3 * WSZ, WL_ + 3 * WSZ,
        nullptr, nullptr, nullptr, hW2, nullptr, nullptr, N_NODES);
    gather_kernel<<<gat_blocks, 256, 0, s2>>>(hW2, rs2, cs2, agg2);
    gemm_mma<1><<<gemm_grid, 256, SMEM_BYTES, s2>>>(
        nfH2, nfL2, WH_ + 4 * WSZ, WL_ + 4 * WSZ,
        br2, agg2, b2, nullptr, h1H2, h1L2, N_NODES);
    gemm_mma<2><<<gemm_grid, 256, SMEM_BYTES, s2>>>(
        h1H2, h1L2, WH_ + 5 * WSZ, WL_ + 5 * WSZ,
        rbi2, nullptr, nullptr, hW2, nullptr, nullptr, N_NODES);
    segsum_kernel<<<N_GRAPHS, 256, 0, s2>>>(hW2, gid2, T2, counts2);
    if (s_s2) cudaEventRecord(s_evJ, s_s2);

    // join + fused readout/predictor
    if (s_s2) cudaStreamWaitEvent(s0, s_evJ, 0);
    readout_final<<<N_GRAPHS, 256, 0, s0>>>(T, counts, Ro1, rbo1, Ro2, rbo2, Wp, bp,
                                            (float*)d_out);
}